// round 5
// baseline (speedup 1.0000x reference)
#include <cuda_runtime.h>
#include <cstdint>
#include <cstddef>

// Problem constants
#define Bb 4
#define Ss 2048
#define Dd 1024
#define DI 2048          // D_INNER
#define NT (Bb*Ss)       // 8192 tokens
#define NE 8
#define RHID 128

// GEMM tile config
#define BM 128
#define BN 128
#define BKK 16
#define STR 20           // padded smem row stride (floats)
#define STAGES 3
#define SMEM_BYTES (STAGES * (BM + BN) * STR * 4)

// Scratch (device globals: allocation-free rule)
__device__ float g_zx[(size_t)16 * NT * DI];    // job j (=2e:z, 2e+1:x) output
__device__ float g_xact[(size_t)NE * NT * DI];  // gated act * comb (tf32-rounded)
__device__ float g_outbuf[(size_t)NE * NT * Dd];// per-expert out_proj (list order)
__device__ float g_hr[(size_t)NT * Dd];         // tf32-rounded h
__device__ float g_inwr[(size_t)NE * 2 * DI * Dd]; // tf32-rounded in_proj_w
__device__ float g_owr[(size_t)NE * Dd * DI];   // tf32-rounded out_proj_w
__device__ float g_rh[(size_t)NT * RHID];       // silu(router hidden), fp32
__device__ float g_comb[(size_t)NT * NE];
__device__ int   g_selflag[(size_t)NT * NE];
__device__ int   g_lists[16 * NT];              // job j token list at j*NT
__device__ int   g_posx[NE * NT];               // token -> pos in x list
__device__ int4  g_tokmap[NT];                  // (e1,q1,e2,q2)
__device__ int   g_cnts2[16];                   // count per job

__device__ __forceinline__ float silu_(float x) { return x / (1.0f + expf(-x)); }

__device__ __forceinline__ float round_tf32f(float f) {
    uint32_t u;
    asm("cvt.rna.tf32.f32 %0, %1;" : "=r"(u) : "f"(f));
    return __uint_as_float(u);
}

// ---------------------------------------------------------------------------
// Elementwise tf32 rounding pass (vectorized, grid-stride).
// ---------------------------------------------------------------------------
__global__ void round_pass(const float4* __restrict__ src, float4* __restrict__ dst,
                           int n4)
{
    for (int i = blockIdx.x * blockDim.x + threadIdx.x; i < n4;
         i += gridDim.x * blockDim.x) {
        float4 v = src[i];
        v.x = round_tf32f(v.x); v.y = round_tf32f(v.y);
        v.z = round_tf32f(v.z); v.w = round_tf32f(v.w);
        dst[i] = v;
    }
}

// ---------------------------------------------------------------------------
// Router layer 1, FULL FP32: rh = silu(h @ W1^T).
// 32 tokens x 128 hidden per block -> grid 256 (fills the chip).
// ---------------------------------------------------------------------------
__global__ __launch_bounds__(256) void router_l1(const float* __restrict__ h,
                                                 const float* __restrict__ w1,
                                                 float* __restrict__ rh)
{
    __shared__ float As[32][33];
    __shared__ float Ws[128][33];

    const int tid = threadIdx.x;
    const int t0 = blockIdx.x * 32;
    const int ty = tid >> 4;        // 0..15 -> token pair
    const int tx = tid & 15;        // 0..15 -> 8 hidden units

    float acc[2][8];
#pragma unroll
    for (int i = 0; i < 2; ++i)
#pragma unroll
        for (int j = 0; j < 8; ++j) acc[i][j] = 0.f;

    const int arow = tid >> 3, acol = (tid & 7) * 4;    // A: 32x32, 4 floats/thr
    const int wrow = tid >> 1, wcol = (tid & 1) * 16;   // W: 128x32, 16 floats/thr

    for (int k0 = 0; k0 < Dd; k0 += 32) {
        float4 a0 = *(const float4*)&h[(size_t)(t0 + arow) * Dd + k0 + acol];
        As[arow][acol + 0] = a0.x; As[arow][acol + 1] = a0.y;
        As[arow][acol + 2] = a0.z; As[arow][acol + 3] = a0.w;
#pragma unroll
        for (int q = 0; q < 4; ++q) {
            float4 w = *(const float4*)&w1[(size_t)wrow * Dd + k0 + wcol + q * 4];
            Ws[wrow][wcol + q * 4 + 0] = w.x; Ws[wrow][wcol + q * 4 + 1] = w.y;
            Ws[wrow][wcol + q * 4 + 2] = w.z; Ws[wrow][wcol + q * 4 + 3] = w.w;
        }
        __syncthreads();

#pragma unroll 8
        for (int k = 0; k < 32; ++k) {
            float a[2], b[8];
#pragma unroll
            for (int i = 0; i < 2; ++i) a[i] = As[ty * 2 + i][k];
#pragma unroll
            for (int j = 0; j < 8; ++j) b[j] = Ws[tx * 8 + j][k];
#pragma unroll
            for (int i = 0; i < 2; ++i)
#pragma unroll
                for (int j = 0; j < 8; ++j) acc[i][j] += a[i] * b[j];
        }
        __syncthreads();
    }

#pragma unroll
    for (int i = 0; i < 2; ++i) {
        int t = t0 + ty * 2 + i;
#pragma unroll
        for (int j = 0; j < 8; ++j)
            rh[(size_t)t * RHID + tx * 8 + j] = silu_(acc[i][j]);
    }
}

// ---------------------------------------------------------------------------
// Router finish (fp32): logits, top-2 softmax, comb/selflag/lists/tokmap.
// ---------------------------------------------------------------------------
__global__ void router_finish(const float* __restrict__ rh,
                              const float* __restrict__ w2)
{
    int t = (blockIdx.x * blockDim.x + threadIdx.x) >> 5;
    int lane = threadIdx.x & 31;
    if (t >= NT) return;

    const float* r = rh + (size_t)t * RHID;
    float v0 = r[lane], v1 = r[lane + 32], v2 = r[lane + 64], v3 = r[lane + 96];

    float lg[NE];
#pragma unroll
    for (int e = 0; e < NE; ++e) {
        const float* w = w2 + e * RHID;
        float p = v0 * w[lane] + v1 * w[lane + 32] + v2 * w[lane + 64] + v3 * w[lane + 96];
#pragma unroll
        for (int o = 16; o; o >>= 1) p += __shfl_xor_sync(0xffffffffu, p, o);
        lg[e] = p;
    }

    if (lane == 0) {
        int i1 = 0; float l1 = lg[0];
#pragma unroll
        for (int e = 1; e < NE; ++e) if (lg[e] > l1) { l1 = lg[e]; i1 = e; }
        int i2 = -1; float l2 = -1e30f;
#pragma unroll
        for (int e = 0; e < NE; ++e) { if (e == i1) continue; if (lg[e] > l2) { l2 = lg[e]; i2 = e; } }
        float wtop = 1.f / (1.f + expf(l2 - l1));
        float* cb = &g_comb[(size_t)t * NE];
        int* sf = &g_selflag[(size_t)t * NE];
#pragma unroll
        for (int e = 0; e < NE; ++e) { cb[e] = 0.f; sf[e] = 0; }
        cb[i1] = wtop;       sf[i1] = 1;
        cb[i2] = 1.f - wtop; sf[i2] = 1;
        int q1 = atomicAdd(&g_cnts2[2 * i1], 1); g_lists[(2 * i1) * NT + q1] = t;
        int q2 = atomicAdd(&g_cnts2[2 * i2], 1); g_lists[(2 * i2) * NT + q2] = t;
        g_tokmap[t] = make_int4(i1, q1, i2, q2);
    }
}

// ---------------------------------------------------------------------------
// Conv-input (dilated) token lists.
// ---------------------------------------------------------------------------
__global__ void build_xlists()
{
    int t = blockIdx.x * blockDim.x + threadIdx.x;
    int e = blockIdx.y;
    if (t >= NT) return;
    int b = t >> 11, s = t & (Ss - 1);
    bool need = false;
#pragma unroll
    for (int j = 0; j < 4; ++j) {
        int sj = s + j;
        if (sj < Ss) need |= (g_selflag[(size_t)(b * Ss + sj) * NE + e] != 0);
    }
    if (need) {
        int p = atomicAdd(&g_cnts2[2 * e + 1], 1);
        g_lists[(2 * e + 1) * NT + p] = t;
        g_posx[e * NT + t] = p;
    }
}

// ---------------------------------------------------------------------------
// TF32 GEMM (TN), batched over blockIdx.z: C[M,N] = A[M,K] * W[N,K]^T.
// Inputs pre-rounded to tf32. 3-stage cp.async pipeline, ONE barrier/iter.
// M = cnts[mBase + z*mStride] (early-exit). Optional A-row gather per z.
// ---------------------------------------------------------------------------
__global__ __launch_bounds__(256, 2) void gemm_tn_v3(
    const float* __restrict__ A, const float* __restrict__ W, float* __restrict__ C,
    const int* __restrict__ cnts, int mBase, int mStride,
    int N, int K,
    size_t aStrideZ, size_t wStrideZ, size_t cStrideZ,
    const int* __restrict__ idx, size_t idxStrideZ)
{
    const int z = blockIdx.z;
    const int M = cnts[mBase + z * mStride];
    if ((int)blockIdx.y * BM >= M) return;

    A += (size_t)z * aStrideZ;
    W += (size_t)z * wStrideZ;
    C += (size_t)z * cStrideZ;
    const int* aidx = idx ? idx + (size_t)z * idxStrideZ : nullptr;

    extern __shared__ float smem[];
    float* Asm = smem;                         // [STAGES][BM*STR]
    float* Bsm = smem + STAGES * BM * STR;     // [STAGES][BN*STR]

    const int tid  = threadIdx.x;
    const int lane = tid & 31;
    const int warp = tid >> 5;
    const int g  = lane >> 2;
    const int tg = lane & 3;
    const int wm = (warp & 1) * 64;
    const int wn = (warp >> 1) * 32;

    const int r0   = tid >> 2;
    const int roff = (tid & 3) * 4;
    const int i0 = blockIdx.y * BM + r0;
    const int i1 = i0 + 64;
    const int ic0 = min(i0, M - 1);
    const int ic1 = min(i1, M - 1);
    const float* arow0 = A + (size_t)(aidx ? aidx[ic0] : ic0) * K + roff;
    const float* arow1 = A + (size_t)(aidx ? aidx[ic1] : ic1) * K + roff;
    const float* Bg = W + (size_t)(blockIdx.x * BN) * K;
    const float* brow0 = Bg + (size_t)r0 * K + roff;
    const float* brow1 = Bg + (size_t)(r0 + 64) * K + roff;

    const uint32_t sa0 = (uint32_t)__cvta_generic_to_shared(&Asm[r0 * STR + roff]);
    const uint32_t sa1 = (uint32_t)__cvta_generic_to_shared(&Asm[(r0 + 64) * STR + roff]);
    const uint32_t sb0 = (uint32_t)__cvta_generic_to_shared(&Bsm[r0 * STR + roff]);
    const uint32_t sb1 = (uint32_t)__cvta_generic_to_shared(&Bsm[(r0 + 64) * STR + roff]);
    const uint32_t bufstep = (uint32_t)(BM * STR * sizeof(float));

    float c[4][4][4];
#pragma unroll
    for (int i = 0; i < 4; ++i)
#pragma unroll
        for (int j = 0; j < 4; ++j)
#pragma unroll
            for (int r = 0; r < 4; ++r) c[i][j][r] = 0.f;

    const int nk = K / BKK;

    auto load_tile = [&](int buf, int kc) {
        const int k0 = kc * BKK;
        const uint32_t bo = buf * bufstep;
        asm volatile("cp.async.cg.shared.global [%0], [%1], 16;\n" :: "r"(sa0 + bo), "l"(arow0 + k0) : "memory");
        asm volatile("cp.async.cg.shared.global [%0], [%1], 16;\n" :: "r"(sa1 + bo), "l"(arow1 + k0) : "memory");
        asm volatile("cp.async.cg.shared.global [%0], [%1], 16;\n" :: "r"(sb0 + bo), "l"(brow0 + k0) : "memory");
        asm volatile("cp.async.cg.shared.global [%0], [%1], 16;\n" :: "r"(sb1 + bo), "l"(brow1 + k0) : "memory");
        asm volatile("cp.async.commit_group;\n" ::: "memory");
    };

    // prologue: 2 tiles in flight (nk >= 64 always here)
    load_tile(0, 0);
    load_tile(1, 1);

    int buf = 0;
    for (int kc = 0; kc < nk; ++kc) {
        asm volatile("cp.async.wait_group 1;\n" ::: "memory");
        __syncthreads();
        if (kc + 2 < nk) {
            int nb = buf + 2; if (nb >= STAGES) nb -= STAGES;
            load_tile(nb, kc + 2);
        } else {
            asm volatile("cp.async.commit_group;\n" ::: "memory");
        }

        const float* Ab = Asm + buf * (BM * STR);
        const float* Bb2 = Bsm + buf * (BN * STR);

#pragma unroll
        for (int kk = 0; kk < BKK; kk += 8) {
            uint32_t a[4][4], b[4][2];
#pragma unroll
            for (int mi = 0; mi < 4; ++mi) {
                int r = wm + mi * 16 + g;
                a[mi][0] = __float_as_uint(Ab[(r    ) * STR + kk + tg    ]);
                a[mi][1] = __float_as_uint(Ab[(r + 8) * STR + kk + tg    ]);
                a[mi][2] = __float_as_uint(Ab[(r    ) * STR + kk + tg + 4]);
                a[mi][3] = __float_as_uint(Ab[(r + 8) * STR + kk + tg + 4]);
            }
#pragma unroll
            for (int ni = 0; ni < 4; ++ni) {
                int r = wn + ni * 8 + g;
                b[ni][0] = __float_as_uint(Bb2[r * STR + kk + tg    ]);
                b[ni][1] = __float_as_uint(Bb2[r * STR + kk + tg + 4]);
            }
#pragma unroll
            for (int mi = 0; mi < 4; ++mi)
#pragma unroll
                for (int ni = 0; ni < 4; ++ni)
                    asm volatile(
                        "mma.sync.aligned.m16n8k8.row.col.f32.tf32.tf32.f32 "
                        "{%0,%1,%2,%3}, {%4,%5,%6,%7}, {%8,%9}, {%0,%1,%2,%3};"
                        : "+f"(c[mi][ni][0]), "+f"(c[mi][ni][1]),
                          "+f"(c[mi][ni][2]), "+f"(c[mi][ni][3])
                        : "r"(a[mi][0]), "r"(a[mi][1]), "r"(a[mi][2]), "r"(a[mi][3]),
                          "r"(b[ni][0]), "r"(b[ni][1]));
        }
        if (++buf == STAGES) buf = 0;
    }

#pragma unroll
    for (int mi = 0; mi < 4; ++mi) {
        int m0 = blockIdx.y * BM + wm + mi * 16 + g;
        int m1 = m0 + 8;
#pragma unroll
        for (int ni = 0; ni < 4; ++ni) {
            int n0 = blockIdx.x * BN + wn + ni * 8 + 2 * tg;
            if (m0 < M) {
                float* p = C + (size_t)m0 * N + n0;
                p[0] = c[mi][ni][0]; p[1] = c[mi][ni][1];
            }
            if (m1 < M) {
                float* p = C + (size_t)m1 * N + n0;
                p[0] = c[mi][ni][2]; p[1] = c[mi][ni][3];
            }
        }
    }
}

// ---------------------------------------------------------------------------
// Sparse fused conv + bias + silu(x)*silu(z)*comb, tf32-round the output.
// Batched over experts via blockIdx.y.
// ---------------------------------------------------------------------------
__global__ void conv_act_sparse(const float* __restrict__ cw_all,   // [E][DI][4]
                                const float* __restrict__ cb_all)   // [E][DI]
{
    const int e = blockIdx.y;
    const int cnt = g_cnts2[2 * e];
    const int total = cnt * (DI / 4);
    const int* sel = g_lists + (2 * e) * NT;
    const int* posx = g_posx + e * NT;
    const float* zb = g_zx + (size_t)(2 * e) * NT * DI;
    const float* xb = g_zx + (size_t)(2 * e + 1) * NT * DI;
    float* xact = g_xact + (size_t)e * NT * DI;
    const float4* cwf = reinterpret_cast<const float4*>(cw_all + (size_t)e * DI * 4);
    const float4* cbf = reinterpret_cast<const float4*>(cb_all + (size_t)e * DI);

    for (int idx = blockIdx.x * blockDim.x + threadIdx.x; idx < total;
         idx += gridDim.x * blockDim.x) {
        const int i  = idx >> 9;           // DI/4 = 512
        const int c4 = idx & 511;
        const int c  = c4 * 4;
        const int t  = sel[i];
        const float wgt = g_comb[(size_t)t * NE + e];
        const int b = t >> 11, s = t & (Ss - 1);

        float4 w0 = cwf[c4 * 4 + 0];
        float4 w1 = cwf[c4 * 4 + 1];
        float4 w2 = cwf[c4 * 4 + 2];
        float4 w3 = cwf[c4 * 4 + 3];
        float4 acc = cbf[c4];

#pragma unroll
        for (int j = 0; j < 4; ++j) {
            int sj = s - 3 + j;
            if (sj < 0) continue;
            int r = posx[b * Ss + sj];
            const float4 xv = *reinterpret_cast<const float4*>(xb + (size_t)r * DI + c);
            float t0 = (j == 0) ? w0.x : (j == 1) ? w0.y : (j == 2) ? w0.z : w0.w;
            float t1 = (j == 0) ? w1.x : (j == 1) ? w1.y : (j == 2) ? w1.z : w1.w;
            float t2 = (j == 0) ? w2.x : (j == 1) ? w2.y : (j == 2) ? w2.z : w2.w;
            float t3 = (j == 0) ? w3.x : (j == 1) ? w3.y : (j == 2) ? w3.z : w3.w;
            acc.x += t0 * xv.x; acc.y += t1 * xv.y;
            acc.z += t2 * xv.z; acc.w += t3 * xv.w;
        }

        const float4 z = *reinterpret_cast<const float4*>(zb + (size_t)i * DI + c);
        float4 o;
        o.x = round_tf32f(silu_(acc.x) * silu_(z.x) * wgt);
        o.y = round_tf32f(silu_(acc.y) * silu_(z.y) * wgt);
        o.z = round_tf32f(silu_(acc.z) * silu_(z.z) * wgt);
        o.w = round_tf32f(silu_(acc.w) * silu_(z.w) * wgt);
        *reinterpret_cast<float4*>(xact + (size_t)i * DI + c) = o;
    }
}

// ---------------------------------------------------------------------------
// Combine: out[t] = outbuf[e1][q1] + outbuf[e2][q2].
// ---------------------------------------------------------------------------
__global__ void combine_kernel(float* __restrict__ out)
{
    const int t = blockIdx.x;
    const int4 m = g_tokmap[t];
    const float4* a = reinterpret_cast<const float4*>(
        g_outbuf + ((size_t)m.x * NT + m.y) * Dd);
    const float4* b = reinterpret_cast<const float4*>(
        g_outbuf + ((size_t)m.z * NT + m.w) * Dd);
    float4* o = reinterpret_cast<float4*>(out + (size_t)t * Dd);
    const int i = threadIdx.x;  // 256 threads x float4 = 1024 floats
    float4 va = a[i], vb = b[i];
    o[i] = make_float4(va.x + vb.x, va.y + vb.y, va.z + vb.z, va.w + vb.w);
}

// ---------------------------------------------------------------------------
extern "C" void kernel_launch(void* const* d_in, const int* in_sizes, int n_in,
                              void* d_out, int out_size)
{
    const float* h   = (const float*)d_in[0];   // [B,S,D]
    const float* inw = (const float*)d_in[1];   // [E, 2*DI, D]
    const float* cw  = (const float*)d_in[2];   // [E, DI, 1, 4]
    const float* cb  = (const float*)d_in[3];   // [E, DI]
    const float* ow  = (const float*)d_in[4];   // [E, D, DI]
    const float* rw1 = (const float*)d_in[5];   // [128, D]
    const float* rw2 = (const float*)d_in[6];   // [E, 128]
    float* out = (float*)d_out;                 // [B,S,D]

    void *zxp, *xap, *obp, *hrp, *iwp, *owp, *rhp, *cntp, *lstp;
    cudaGetSymbolAddress(&zxp, g_zx);
    cudaGetSymbolAddress(&xap, g_xact);
    cudaGetSymbolAddress(&obp, g_outbuf);
    cudaGetSymbolAddress(&hrp, g_hr);
    cudaGetSymbolAddress(&iwp, g_inwr);
    cudaGetSymbolAddress(&owp, g_owr);
    cudaGetSymbolAddress(&rhp, g_rh);
    cudaGetSymbolAddress(&cntp, g_cnts2);
    cudaGetSymbolAddress(&lstp, g_lists);
    float* zx   = (float*)zxp;
    float* xact = (float*)xap;
    float* obuf = (float*)obp;
    float* hr   = (float*)hrp;
    float* inwr = (float*)iwp;
    float* owr  = (float*)owp;
    float* rh   = (float*)rhp;
    int* cnts   = (int*)cntp;
    int* lists  = (int*)lstp;

    static_assert(SMEM_BYTES <= 64 * 1024, "smem");
    cudaFuncSetAttribute(gemm_tn_v3, cudaFuncAttributeMaxDynamicSharedMemorySize,
                         SMEM_BYTES);

    cudaMemsetAsync(cnts, 0, 16 * sizeof(int));

    // tf32-round all MMA inputs once (bit-identical to per-element cvt)
    round_pass<<<1024, 256>>>((const float4*)h,   (float4*)hr,   NT * Dd / 4);
    round_pass<<<2048, 256>>>((const float4*)inw, (float4*)inwr, NE * 2 * DI * Dd / 4);
    round_pass<<<2048, 256>>>((const float4*)ow,  (float4*)owr,  NE * Dd * DI / 4);

    // router, all fp32
    router_l1<<<NT / 32, 256>>>(h, rw1, rh);
    router_finish<<<(NT * 32) / 256, 256>>>(rh, rw2);
    build_xlists<<<dim3(NT / 256, NE), 256>>>();

    // in_proj: 16 jobs (expert e: job 2e = z rows, job 2e+1 = x rows)
    gemm_tn_v3<<<dim3(DI / BN, NT / BM, 16), 256, SMEM_BYTES>>>(
        hr, inwr, zx, cnts, 0, 1, DI, Dd,
        (size_t)0, (size_t)DI * Dd, (size_t)NT * DI, lists, (size_t)NT);

    // conv + gate, batched over experts
    conv_act_sparse<<<dim3(1024, NE), 256>>>(cw, cb);

    // out_proj per expert -> list-ordered outbuf
    gemm_tn_v3<<<dim3(Dd / BN, NT / BM, NE), 256, SMEM_BYTES>>>(
        xact, owr, obuf, cnts, 0, 2, Dd, DI,
        (size_t)NT * DI, (size_t)Dd * DI, (size_t)NT * Dd, nullptr, (size_t)0);

    // final combine (2 experts per token, deterministic)
    combine_kernel<<<NT, 256>>>(out);
}

// round 8
// speedup vs baseline: 1.0662x; 1.0662x over previous
#include <cuda_runtime.h>
#include <cstdint>
#include <cstddef>

// Problem constants
#define BATCH 4
#define Ss 2048
#define Dd 1024
#define DI 2048          // D_INNER
#define NT (BATCH*Ss)    // 8192 tokens
#define NE 8
#define RHID 128

// GEMM tile config: 256x128x32, 512 threads, 3-stage cp.async
#define BM 256
#define BN 128
#define BKK 32
#define STR 36                         // padded smem row stride (floats)
#define STAGES 3
#define A_STAGE_FLOATS (BM * STR)
#define STAGE_FLOATS ((BM + BN) * STR)
#define SMEM_BYTES (STAGES * STAGE_FLOATS * 4)   // 165,888 B

// Scratch (device globals: allocation-free rule)
__device__ float g_zx[(size_t)16 * NT * DI];
__device__ float g_xact[(size_t)NE * NT * DI];
__device__ float g_outbuf[(size_t)NE * NT * Dd];
__device__ float g_hr[(size_t)NT * Dd];
__device__ float g_inwr[(size_t)NE * 2 * DI * Dd];
__device__ float g_owr[(size_t)NE * Dd * DI];
__device__ float g_rh[(size_t)NT * RHID];
__device__ float g_comb[(size_t)NT * NE];
__device__ int   g_selflag[(size_t)NT * NE];
__device__ int   g_lists[16 * NT];
__device__ int   g_posx[NE * NT];
__device__ int4  g_tokmap[NT];
__device__ int   g_cnts2[16];

__device__ __forceinline__ float silu_(float x) { return x / (1.0f + expf(-x)); }

__device__ __forceinline__ float round_tf32f(float f) {
    uint32_t u;
    asm("cvt.rna.tf32.f32 %0, %1;" : "=r"(u) : "f"(f));
    return __uint_as_float(u);
}

// ---------------------------------------------------------------------------
// Elementwise tf32 rounding pass.
// ---------------------------------------------------------------------------
__global__ void round_pass(const float4* __restrict__ src, float4* __restrict__ dst,
                           int n4)
{
    for (int i = blockIdx.x * blockDim.x + threadIdx.x; i < n4;
         i += gridDim.x * blockDim.x) {
        float4 v = src[i];
        v.x = round_tf32f(v.x); v.y = round_tf32f(v.y);
        v.z = round_tf32f(v.z); v.w = round_tf32f(v.w);
        dst[i] = v;
    }
}

// ---------------------------------------------------------------------------
// Router layer 1, FULL FP32 (64 tokens/block, grid 128).
// ---------------------------------------------------------------------------
__global__ __launch_bounds__(256) void router_l1(const float* __restrict__ h,
                                                 const float* __restrict__ w1,
                                                 float* __restrict__ rh)
{
    __shared__ float As[64][33];
    __shared__ float Ws[128][33];

    const int tid = threadIdx.x;
    const int t0 = blockIdx.x * 64;
    const int ty = tid >> 4;
    const int tx = tid & 15;

    float acc[4][8];
#pragma unroll
    for (int i = 0; i < 4; ++i)
#pragma unroll
        for (int j = 0; j < 8; ++j) acc[i][j] = 0.f;

    const int arow = tid >> 2, acol = (tid & 3) * 8;
    const int wrow = tid >> 1, wcol = (tid & 1) * 16;

    for (int k0 = 0; k0 < Dd; k0 += 32) {
        float4 a0 = *(const float4*)&h[(size_t)(t0 + arow) * Dd + k0 + acol];
        float4 a1 = *(const float4*)&h[(size_t)(t0 + arow) * Dd + k0 + acol + 4];
        As[arow][acol + 0] = a0.x; As[arow][acol + 1] = a0.y;
        As[arow][acol + 2] = a0.z; As[arow][acol + 3] = a0.w;
        As[arow][acol + 4] = a1.x; As[arow][acol + 5] = a1.y;
        As[arow][acol + 6] = a1.z; As[arow][acol + 7] = a1.w;
#pragma unroll
        for (int q = 0; q < 4; ++q) {
            float4 w = *(const float4*)&w1[(size_t)wrow * Dd + k0 + wcol + q * 4];
            Ws[wrow][wcol + q * 4 + 0] = w.x; Ws[wrow][wcol + q * 4 + 1] = w.y;
            Ws[wrow][wcol + q * 4 + 2] = w.z; Ws[wrow][wcol + q * 4 + 3] = w.w;
        }
        __syncthreads();

#pragma unroll 8
        for (int k = 0; k < 32; ++k) {
            float a[4], b[8];
#pragma unroll
            for (int i = 0; i < 4; ++i) a[i] = As[ty * 4 + i][k];
#pragma unroll
            for (int j = 0; j < 8; ++j) b[j] = Ws[tx * 8 + j][k];
#pragma unroll
            for (int i = 0; i < 4; ++i)
#pragma unroll
                for (int j = 0; j < 8; ++j) acc[i][j] += a[i] * b[j];
        }
        __syncthreads();
    }

#pragma unroll
    for (int i = 0; i < 4; ++i) {
        int t = t0 + ty * 4 + i;
#pragma unroll
        for (int j = 0; j < 8; ++j)
            rh[(size_t)t * RHID + tx * 8 + j] = silu_(acc[i][j]);
    }
}

// ---------------------------------------------------------------------------
// Router finish (fp32): logits, top-2 softmax, comb/selflag/lists/tokmap.
// ---------------------------------------------------------------------------
__global__ void router_finish(const float* __restrict__ rh,
                              const float* __restrict__ w2)
{
    int t = (blockIdx.x * blockDim.x + threadIdx.x) >> 5;
    int lane = threadIdx.x & 31;
    if (t >= NT) return;

    const float* r = rh + (size_t)t * RHID;
    float v0 = r[lane], v1 = r[lane + 32], v2 = r[lane + 64], v3 = r[lane + 96];

    float lg[NE];
#pragma unroll
    for (int e = 0; e < NE; ++e) {
        const float* w = w2 + e * RHID;
        float p = v0 * w[lane] + v1 * w[lane + 32] + v2 * w[lane + 64] + v3 * w[lane + 96];
#pragma unroll
        for (int o = 16; o; o >>= 1) p += __shfl_xor_sync(0xffffffffu, p, o);
        lg[e] = p;
    }

    if (lane == 0) {
        int i1 = 0; float l1 = lg[0];
#pragma unroll
        for (int e = 1; e < NE; ++e) if (lg[e] > l1) { l1 = lg[e]; i1 = e; }
        int i2 = -1; float l2 = -1e30f;
#pragma unroll
        for (int e = 0; e < NE; ++e) { if (e == i1) continue; if (lg[e] > l2) { l2 = lg[e]; i2 = e; } }
        float wtop = 1.f / (1.f + expf(l2 - l1));
        float* cb = &g_comb[(size_t)t * NE];
        int* sf = &g_selflag[(size_t)t * NE];
#pragma unroll
        for (int e = 0; e < NE; ++e) { cb[e] = 0.f; sf[e] = 0; }
        cb[i1] = wtop;       sf[i1] = 1;
        cb[i2] = 1.f - wtop; sf[i2] = 1;
        int q1 = atomicAdd(&g_cnts2[2 * i1], 1); g_lists[(2 * i1) * NT + q1] = t;
        int q2 = atomicAdd(&g_cnts2[2 * i2], 1); g_lists[(2 * i2) * NT + q2] = t;
        g_tokmap[t] = make_int4(i1, q1, i2, q2);
    }
}

// ---------------------------------------------------------------------------
// Conv-input (dilated) token lists.
// ---------------------------------------------------------------------------
__global__ void build_xlists()
{
    int t = blockIdx.x * blockDim.x + threadIdx.x;
    int e = blockIdx.y;
    if (t >= NT) return;
    int b = t >> 11, s = t & (Ss - 1);
    bool need = false;
#pragma unroll
    for (int j = 0; j < 4; ++j) {
        int sj = s + j;
        if (sj < Ss) need |= (g_selflag[(size_t)(b * Ss + sj) * NE + e] != 0);
    }
    if (need) {
        int p = atomicAdd(&g_cnts2[2 * e + 1], 1);
        g_lists[(2 * e + 1) * NT + p] = t;
        g_posx[e * NT + t] = p;
    }
}

// ---------------------------------------------------------------------------
// TF32 GEMM (TN), batched over blockIdx.z: C[M,N] = A[M,K] * W[N,K]^T.
// 256x128x32 tiles, 512 threads (16 warps, 4m x 4n of 64x32), 3-stage
// cp.async ring, pre-rounded tf32 inputs (no CVT in loop). Runtime M with
// early-exit, optional per-z A-row gather.
// ---------------------------------------------------------------------------
__global__ __launch_bounds__(512, 1) void gemm_tn_v4(
    const float* __restrict__ A, const float* __restrict__ W, float* __restrict__ C,
    const int* __restrict__ cnts, int mBase, int mStride,
    int N, int K,
    size_t aStrideZ, size_t wStrideZ, size_t cStrideZ,
    const int* __restrict__ idx, size_t idxStrideZ)
{
    const int z = blockIdx.z;
    const int M = cnts[mBase + z * mStride];
    if ((int)blockIdx.y * BM >= M) return;

    A += (size_t)z * aStrideZ;
    W += (size_t)z * wStrideZ;
    C += (size_t)z * cStrideZ;
    const int* aidx = idx ? idx + (size_t)z * idxStrideZ : nullptr;

    extern __shared__ float smem[];

    const int tid  = threadIdx.x;
    const int lane = tid & 31;
    const int warp = tid >> 5;
    const int g  = lane >> 2;
    const int tg = lane & 3;
    const int wm = (warp & 3) * 64;      // 0,64,128,192
    const int wn = (warp >> 2) * 32;     // 0,32,64,96

    // Loader coordinates: 16B chunks. Row = BKK=32 floats = 8 chunks.
    const int r0   = tid >> 3;           // 0..63
    const int roff = (tid & 7) * 4;

    const float* arow[4];
#pragma unroll
    for (int k = 0; k < 4; ++k) {
        int gr = blockIdx.y * BM + r0 + 64 * k;
        int cr = min(gr, M - 1);
        arow[k] = A + (size_t)(aidx ? aidx[cr] : cr) * K + roff;
    }
    const float* Bg = W + (size_t)(blockIdx.x * BN) * K;
    const float* brow[2];
#pragma unroll
    for (int k = 0; k < 2; ++k)
        brow[k] = Bg + (size_t)(r0 + 64 * k) * K + roff;

    uint32_t sa[4], sb[2];
#pragma unroll
    for (int k = 0; k < 4; ++k)
        sa[k] = (uint32_t)__cvta_generic_to_shared(
            &smem[(r0 + 64 * k) * STR + roff]);
#pragma unroll
    for (int k = 0; k < 2; ++k)
        sb[k] = (uint32_t)__cvta_generic_to_shared(
            &smem[A_STAGE_FLOATS + (r0 + 64 * k) * STR + roff]);
    const uint32_t stagestep = (uint32_t)(STAGE_FLOATS * sizeof(float));

    float c[4][4][4];
#pragma unroll
    for (int i = 0; i < 4; ++i)
#pragma unroll
        for (int j = 0; j < 4; ++j)
#pragma unroll
            for (int r = 0; r < 4; ++r) c[i][j][r] = 0.f;

    const int nk = K / BKK;

    auto load_stage = [&](int s, int kc) {
        const int k0 = kc * BKK;
        const uint32_t so = s * stagestep;
#pragma unroll
        for (int k = 0; k < 4; ++k)
            asm volatile("cp.async.cg.shared.global [%0], [%1], 16;\n"
                         :: "r"(sa[k] + so), "l"(arow[k] + k0) : "memory");
#pragma unroll
        for (int k = 0; k < 2; ++k)
            asm volatile("cp.async.cg.shared.global [%0], [%1], 16;\n"
                         :: "r"(sb[k] + so), "l"(brow[k] + k0) : "memory");
        asm volatile("cp.async.commit_group;\n" ::: "memory");
    };

    load_stage(0, 0);
    load_stage(1, 1);

    int buf = 0;
    for (int kc = 0; kc < nk; ++kc) {
        asm volatile("cp.async.wait_group 1;\n" ::: "memory");
        __syncthreads();
        if (kc + 2 < nk) {
            int nb = buf + 2; if (nb >= STAGES) nb -= STAGES;
            load_stage(nb, kc + 2);
        } else {
            asm volatile("cp.async.commit_group;\n" ::: "memory");
        }

        const float* Ash = smem + buf * STAGE_FLOATS;
        const float* Bsh = Ash + A_STAGE_FLOATS;

#pragma unroll
        for (int kk = 0; kk < BKK; kk += 8) {
            uint32_t a[4][4], b[4][2];
#pragma unroll
            for (int mi = 0; mi < 4; ++mi) {
                int r = wm + mi * 16 + g;
                a[mi][0] = __float_as_uint(Ash[(r    ) * STR + kk + tg    ]);
                a[mi][1] = __float_as_uint(Ash[(r + 8) * STR + kk + tg    ]);
                a[mi][2] = __float_as_uint(Ash[(r    ) * STR + kk + tg + 4]);
                a[mi][3] = __float_as_uint(Ash[(r + 8) * STR + kk + tg + 4]);
            }
#pragma unroll
            for (int ni = 0; ni < 4; ++ni) {
                int r = wn + ni * 8 + g;
                b[ni][0] = __float_as_uint(Bsh[r * STR + kk + tg    ]);
                b[ni][1] = __float_as_uint(Bsh[r * STR + kk + tg + 4]);
            }
#pragma unroll
            for (int mi = 0; mi < 4; ++mi)
#pragma unroll
                for (int ni = 0; ni < 4; ++ni)
                    asm volatile(
                        "mma.sync.aligned.m16n8k8.row.col.f32.tf32.tf32.f32 "
                        "{%0,%1,%2,%3}, {%4,%5,%6,%7}, {%8,%9}, {%0,%1,%2,%3};"
                        : "+f"(c[mi][ni][0]), "+f"(c[mi][ni][1]),
                          "+f"(c[mi][ni][2]), "+f"(c[mi][ni][3])
                        : "r"(a[mi][0]), "r"(a[mi][1]), "r"(a[mi][2]), "r"(a[mi][3]),
                          "r"(b[ni][0]), "r"(b[ni][1]));
        }
        if (++buf == STAGES) buf = 0;
    }

#pragma unroll
    for (int mi = 0; mi < 4; ++mi) {
        int m0 = blockIdx.y * BM + wm + mi * 16 + g;
        int m1 = m0 + 8;
#pragma unroll
        for (int ni = 0; ni < 4; ++ni) {
            int n0 = blockIdx.x * BN + wn + ni * 8 + 2 * tg;
            if (m0 < M) {
                float* p = C + (size_t)m0 * N + n0;
                p[0] = c[mi][ni][0]; p[1] = c[mi][ni][1];
            }
            if (m1 < M) {
                float* p = C + (size_t)m1 * N + n0;
                p[0] = c[mi][ni][2]; p[1] = c[mi][ni][3];
            }
        }
    }
}

// ---------------------------------------------------------------------------
// Sparse fused conv + bias + silu(x)*silu(z)*comb, tf32-round the output.
// ---------------------------------------------------------------------------
__global__ void conv_act_sparse(const float* __restrict__ cw_all,
                                const float* __restrict__ cb_all)
{
    const int e = blockIdx.y;
    const int cnt = g_cnts2[2 * e];
    const int total = cnt * (DI / 4);
    const int* sel = g_lists + (2 * e) * NT;
    const int* posx = g_posx + e * NT;
    const float* zb = g_zx + (size_t)(2 * e) * NT * DI;
    const float* xb = g_zx + (size_t)(2 * e + 1) * NT * DI;
    float* xact = g_xact + (size_t)e * NT * DI;
    const float4* cwf = reinterpret_cast<const float4*>(cw_all + (size_t)e * DI * 4);
    const float4* cbf = reinterpret_cast<const float4*>(cb_all + (size_t)e * DI);

    for (int idx = blockIdx.x * blockDim.x + threadIdx.x; idx < total;
         idx += gridDim.x * blockDim.x) {
        const int i  = idx >> 9;
        const int c4 = idx & 511;
        const int c  = c4 * 4;
        const int t  = sel[i];
        const float wgt = g_comb[(size_t)t * NE + e];
        const int b = t >> 11, s = t & (Ss - 1);

        float4 w0 = cwf[c4 * 4 + 0];
        float4 w1 = cwf[c4 * 4 + 1];
        float4 w2 = cwf[c4 * 4 + 2];
        float4 w3 = cwf[c4 * 4 + 3];
        float4 acc = cbf[c4];

#pragma unroll
        for (int j = 0; j < 4; ++j) {
            int sj = s - 3 + j;
            if (sj < 0) continue;
            int r = posx[b * Ss + sj];
            const float4 xv = *reinterpret_cast<const float4*>(xb + (size_t)r * DI + c);
            float t0 = (j == 0) ? w0.x : (j == 1) ? w0.y : (j == 2) ? w0.z : w0.w;
            float t1 = (j == 0) ? w1.x : (j == 1) ? w1.y : (j == 2) ? w1.z : w1.w;
            float t2 = (j == 0) ? w2.x : (j == 1) ? w2.y : (j == 2) ? w2.z : w2.w;
            float t3 = (j == 0) ? w3.x : (j == 1) ? w3.y : (j == 2) ? w3.z : w3.w;
            acc.x += t0 * xv.x; acc.y += t1 * xv.y;
            acc.z += t2 * xv.z; acc.w += t3 * xv.w;
        }

        const float4 z = *reinterpret_cast<const float4*>(zb + (size_t)i * DI + c);
        float4 o;
        o.x = round_tf32f(silu_(acc.x) * silu_(z.x) * wgt);
        o.y = round_tf32f(silu_(acc.y) * silu_(z.y) * wgt);
        o.z = round_tf32f(silu_(acc.z) * silu_(z.z) * wgt);
        o.w = round_tf32f(silu_(acc.w) * silu_(z.w) * wgt);
        *reinterpret_cast<float4*>(xact + (size_t)i * DI + c) = o;
    }
}

// ---------------------------------------------------------------------------
// Combine: out[t] = outbuf[e1][q1] + outbuf[e2][q2].
// ---------------------------------------------------------------------------
__global__ void combine_kernel(float* __restrict__ out)
{
    const int t = blockIdx.x;
    const int4 m = g_tokmap[t];
    const float4* a = reinterpret_cast<const float4*>(
        g_outbuf + ((size_t)m.x * NT + m.y) * Dd);
    const float4* b = reinterpret_cast<const float4*>(
        g_outbuf + ((size_t)m.z * NT + m.w) * Dd);
    float4* o = reinterpret_cast<float4*>(out + (size_t)t * Dd);
    const int i = threadIdx.x;
    float4 va = a[i], vb = b[i];
    o[i] = make_float4(va.x + vb.x, va.y + vb.y, va.z + vb.z, va.w + vb.w);
}

// ---------------------------------------------------------------------------
extern "C" void kernel_launch(void* const* d_in, const int* in_sizes, int n_in,
                              void* d_out, int out_size)
{
    const float* h   = (const float*)d_in[0];
    const float* inw = (const float*)d_in[1];
    const float* cw  = (const float*)d_in[2];
    const float* cb  = (const float*)d_in[3];
    const float* ow  = (const float*)d_in[4];
    const float* rw1 = (const float*)d_in[5];
    const float* rw2 = (const float*)d_in[6];
    float* out = (float*)d_out;

    void *zxp, *xap, *obp, *hrp, *iwp, *owp, *rhp, *cntp, *lstp;
    cudaGetSymbolAddress(&zxp, g_zx);
    cudaGetSymbolAddress(&xap, g_xact);
    cudaGetSymbolAddress(&obp, g_outbuf);
    cudaGetSymbolAddress(&hrp, g_hr);
    cudaGetSymbolAddress(&iwp, g_inwr);
    cudaGetSymbolAddress(&owp, g_owr);
    cudaGetSymbolAddress(&rhp, g_rh);
    cudaGetSymbolAddress(&cntp, g_cnts2);
    cudaGetSymbolAddress(&lstp, g_lists);
    float* zx   = (float*)zxp;
    float* xact = (float*)xap;
    float* obuf = (float*)obp;
    float* hr   = (float*)hrp;
    float* inwr = (float*)iwp;
    float* owr  = (float*)owp;
    float* rh   = (float*)rhp;
    int* cnts   = (int*)cntp;
    int* lists  = (int*)lstp;

    cudaFuncSetAttribute(gemm_tn_v4, cudaFuncAttributeMaxDynamicSharedMemorySize,
                         SMEM_BYTES);

    cudaMemsetAsync(cnts, 0, 16 * sizeof(int));

    // tf32-round all MMA inputs once (bit-identical to per-element cvt)
    round_pass<<<1024, 256>>>((const float4*)h,   (float4*)hr,   NT * Dd / 4);
    round_pass<<<2048, 256>>>((const float4*)inw, (float4*)inwr, NE * 2 * DI * Dd / 4);
    round_pass<<<2048, 256>>>((const float4*)ow,  (float4*)owr,  NE * Dd * DI / 4);

    // router, all fp32
    router_l1<<<NT / 64, 256>>>(h, rw1, rh);
    router_finish<<<(NT * 32) / 256, 256>>>(rh, rw2);
    build_xlists<<<dim3(NT / 256, NE), 256>>>();

    // in_proj: 16 jobs (expert e: job 2e = z rows, job 2e+1 = x rows)
    gemm_tn_v4<<<dim3(DI / BN, NT / BM, 16), 512, SMEM_BYTES>>>(
        hr, inwr, zx, cnts, 0, 1, DI, Dd,
        (size_t)0, (size_t)DI * Dd, (size_t)NT * DI, lists, (size_t)NT);

    // conv + gate, batched over experts
    conv_act_sparse<<<dim3(1024, NE), 256>>>(cw, cb);

    // out_proj per expert -> list-ordered outbuf
    gemm_tn_v4<<<dim3(Dd / BN, NT / BM, NE), 512, SMEM_BYTES>>>(
        xact, owr, obuf, cnts, 0, 2, Dd, DI,
        (size_t)NT * DI, (size_t)Dd * DI, (size_t)NT * Dd, nullptr, (size_t)0);

    // final combine
    combine_kernel<<<NT, 256>>>(out);
}

// round 9
// speedup vs baseline: 1.1535x; 1.0819x over previous
#include <cuda_runtime.h>
#include <cstdint>
#include <cstddef>

// Problem constants
#define BATCH 4
#define Ss 2048
#define Dd 1024
#define DI 2048          // D_INNER
#define NT (BATCH*Ss)    // 8192 tokens
#define NE 8
#define RHID 128

// GEMM tile config: 128x256x32 CTA tile, 256 threads (8 warps of 64x64)
#define BM 128
#define BN 256
#define BKK 32
#define STR 36                         // padded smem row stride (floats)
#define STAGES 3
#define A_STAGE_FLOATS (BM * STR)
#define STAGE_FLOATS ((BM + BN) * STR)
#define SMEM_BYTES (STAGES * STAGE_FLOATS * 4)   // 165,888 B

// Scratch (device globals: allocation-free rule)
__device__ float g_zx[(size_t)16 * NT * DI];
__device__ float g_xact[(size_t)NE * NT * DI];
__device__ float g_outbuf[(size_t)NE * NT * Dd];
__device__ float g_hr[(size_t)NT * Dd];
__device__ float g_rh[(size_t)NT * RHID];
__device__ float g_comb[(size_t)NT * NE];
__device__ int   g_selflag[(size_t)NT * NE];
__device__ int   g_lists[16 * NT];
__device__ int   g_posx[NE * NT];
__device__ int4  g_tokmap[NT];
__device__ int   g_cnts2[16];

__device__ __forceinline__ float silu_(float x) { return x / (1.0f + expf(-x)); }

__device__ __forceinline__ float round_tf32f(float f) {
    uint32_t u;
    asm("cvt.rna.tf32.f32 %0, %1;" : "=r"(u) : "f"(f));
    return __uint_as_float(u);
}

__device__ __forceinline__ uint32_t cvt_tf32u(float f) {
    uint32_t u;
    asm("cvt.rna.tf32.f32 %0, %1;" : "=r"(u) : "f"(f));
    return u;
}

// ---------------------------------------------------------------------------
// Elementwise tf32 rounding pass (activations only now).
// ---------------------------------------------------------------------------
__global__ void round_pass(const float4* __restrict__ src, float4* __restrict__ dst,
                           int n4)
{
    for (int i = blockIdx.x * blockDim.x + threadIdx.x; i < n4;
         i += gridDim.x * blockDim.x) {
        float4 v = src[i];
        v.x = round_tf32f(v.x); v.y = round_tf32f(v.y);
        v.z = round_tf32f(v.z); v.w = round_tf32f(v.w);
        dst[i] = v;
    }
}

// ---------------------------------------------------------------------------
// Router layer 1, FULL FP32 (64 tokens/block, grid 128).
// ---------------------------------------------------------------------------
__global__ __launch_bounds__(256) void router_l1(const float* __restrict__ h,
                                                 const float* __restrict__ w1,
                                                 float* __restrict__ rh)
{
    __shared__ float As[64][33];
    __shared__ float Ws[128][33];

    const int tid = threadIdx.x;
    const int t0 = blockIdx.x * 64;
    const int ty = tid >> 4;
    const int tx = tid & 15;

    float acc[4][8];
#pragma unroll
    for (int i = 0; i < 4; ++i)
#pragma unroll
        for (int j = 0; j < 8; ++j) acc[i][j] = 0.f;

    const int arow = tid >> 2, acol = (tid & 3) * 8;
    const int wrow = tid >> 1, wcol = (tid & 1) * 16;

    for (int k0 = 0; k0 < Dd; k0 += 32) {
        float4 a0 = *(const float4*)&h[(size_t)(t0 + arow) * Dd + k0 + acol];
        float4 a1 = *(const float4*)&h[(size_t)(t0 + arow) * Dd + k0 + acol + 4];
        As[arow][acol + 0] = a0.x; As[arow][acol + 1] = a0.y;
        As[arow][acol + 2] = a0.z; As[arow][acol + 3] = a0.w;
        As[arow][acol + 4] = a1.x; As[arow][acol + 5] = a1.y;
        As[arow][acol + 6] = a1.z; As[arow][acol + 7] = a1.w;
#pragma unroll
        for (int q = 0; q < 4; ++q) {
            float4 w = *(const float4*)&w1[(size_t)wrow * Dd + k0 + wcol + q * 4];
            Ws[wrow][wcol + q * 4 + 0] = w.x; Ws[wrow][wcol + q * 4 + 1] = w.y;
            Ws[wrow][wcol + q * 4 + 2] = w.z; Ws[wrow][wcol + q * 4 + 3] = w.w;
        }
        __syncthreads();

#pragma unroll 8
        for (int k = 0; k < 32; ++k) {
            float a[4], b[8];
#pragma unroll
            for (int i = 0; i < 4; ++i) a[i] = As[ty * 4 + i][k];
#pragma unroll
            for (int j = 0; j < 8; ++j) b[j] = Ws[tx * 8 + j][k];
#pragma unroll
            for (int i = 0; i < 4; ++i)
#pragma unroll
                for (int j = 0; j < 8; ++j) acc[i][j] += a[i] * b[j];
        }
        __syncthreads();
    }

#pragma unroll
    for (int i = 0; i < 4; ++i) {
        int t = t0 + ty * 4 + i;
#pragma unroll
        for (int j = 0; j < 8; ++j)
            rh[(size_t)t * RHID + tx * 8 + j] = silu_(acc[i][j]);
    }
}

// ---------------------------------------------------------------------------
// Router finish (fp32): logits, top-2 softmax, comb/selflag/lists/tokmap.
// ---------------------------------------------------------------------------
__global__ void router_finish(const float* __restrict__ rh,
                              const float* __restrict__ w2)
{
    int t = (blockIdx.x * blockDim.x + threadIdx.x) >> 5;
    int lane = threadIdx.x & 31;
    if (t >= NT) return;

    const float* r = rh + (size_t)t * RHID;
    float v0 = r[lane], v1 = r[lane + 32], v2 = r[lane + 64], v3 = r[lane + 96];

    float lg[NE];
#pragma unroll
    for (int e = 0; e < NE; ++e) {
        const float* w = w2 + e * RHID;
        float p = v0 * w[lane] + v1 * w[lane + 32] + v2 * w[lane + 64] + v3 * w[lane + 96];
#pragma unroll
        for (int o = 16; o; o >>= 1) p += __shfl_xor_sync(0xffffffffu, p, o);
        lg[e] = p;
    }

    if (lane == 0) {
        int i1 = 0; float l1 = lg[0];
#pragma unroll
        for (int e = 1; e < NE; ++e) if (lg[e] > l1) { l1 = lg[e]; i1 = e; }
        int i2 = -1; float l2 = -1e30f;
#pragma unroll
        for (int e = 0; e < NE; ++e) { if (e == i1) continue; if (lg[e] > l2) { l2 = lg[e]; i2 = e; } }
        float wtop = 1.f / (1.f + expf(l2 - l1));
        float* cb = &g_comb[(size_t)t * NE];
        int* sf = &g_selflag[(size_t)t * NE];
#pragma unroll
        for (int e = 0; e < NE; ++e) { cb[e] = 0.f; sf[e] = 0; }
        cb[i1] = wtop;       sf[i1] = 1;
        cb[i2] = 1.f - wtop; sf[i2] = 1;
        int q1 = atomicAdd(&g_cnts2[2 * i1], 1); g_lists[(2 * i1) * NT + q1] = t;
        int q2 = atomicAdd(&g_cnts2[2 * i2], 1); g_lists[(2 * i2) * NT + q2] = t;
        g_tokmap[t] = make_int4(i1, q1, i2, q2);
    }
}

// ---------------------------------------------------------------------------
// Conv-input (dilated) token lists.
// ---------------------------------------------------------------------------
__global__ void build_xlists()
{
    int t = blockIdx.x * blockDim.x + threadIdx.x;
    int e = blockIdx.y;
    if (t >= NT) return;
    int b = t >> 11, s = t & (Ss - 1);
    bool need = false;
#pragma unroll
    for (int j = 0; j < 4; ++j) {
        int sj = s + j;
        if (sj < Ss) need |= (g_selflag[(size_t)(b * Ss + sj) * NE + e] != 0);
    }
    if (need) {
        int p = atomicAdd(&g_cnts2[2 * e + 1], 1);
        g_lists[(2 * e + 1) * NT + p] = t;
        g_posx[e * NT + t] = p;
    }
}

// ---------------------------------------------------------------------------
// TF32 GEMM (TN), batched over blockIdx.z: C[M,N] = A[M,K] * W[N,K]^T.
// 128x256x32 CTA tiles, 256 threads = 8 warps of 64x64 (2m x 4n).
// A pre-rounded tf32; W raw fp32, cvt'd in-loop (bit-identical, we are
// smem-bytes bound so cvt rides free). 3-stage cp.async ring.
// Runtime M with early-exit, optional per-z A-row gather.
// ---------------------------------------------------------------------------
__global__ __launch_bounds__(256, 1) void gemm_tn_v5(
    const float* __restrict__ A, const float* __restrict__ W, float* __restrict__ C,
    const int* __restrict__ cnts, int mBase, int mStride,
    int N, int K,
    size_t aStrideZ, size_t wStrideZ, size_t cStrideZ,
    const int* __restrict__ idx, size_t idxStrideZ)
{
    const int z = blockIdx.z;
    const int M = cnts[mBase + z * mStride];
    if ((int)blockIdx.y * BM >= M) return;

    A += (size_t)z * aStrideZ;
    W += (size_t)z * wStrideZ;
    C += (size_t)z * cStrideZ;
    const int* aidx = idx ? idx + (size_t)z * idxStrideZ : nullptr;

    extern __shared__ float smem[];

    const int tid  = threadIdx.x;
    const int lane = tid & 31;
    const int warp = tid >> 5;
    const int g  = lane >> 2;
    const int tg = lane & 3;
    const int wm = (warp & 1) * 64;      // 0,64
    const int wn = (warp >> 1) * 64;     // 0,64,128,192

    // Loader: 16B chunks, row = 32 floats = 8 chunks.
    // A: 128 rows -> 4 chunks/thread (rows r0+32k). B: 256 rows -> 8/thread.
    const int r0   = tid >> 3;           // 0..31
    const int roff = (tid & 7) * 4;

    const float* arow[4];
#pragma unroll
    for (int k = 0; k < 4; ++k) {
        int gr = blockIdx.y * BM + r0 + 32 * k;
        int cr = min(gr, M - 1);
        arow[k] = A + (size_t)(aidx ? aidx[cr] : cr) * K + roff;
    }
    const float* bbase = W + (size_t)(blockIdx.x * BN + r0) * K + roff;

    const uint32_t saB = (uint32_t)__cvta_generic_to_shared(&smem[r0 * STR + roff]);
    const uint32_t sbB = (uint32_t)__cvta_generic_to_shared(
        &smem[A_STAGE_FLOATS + r0 * STR + roff]);
    const uint32_t stagestep = (uint32_t)(STAGE_FLOATS * sizeof(float));
    const uint32_t rowskip = (uint32_t)(32 * STR * sizeof(float));

    float c[2][8][4];   // wait: mi covers 4 steps of 16 within 64 -> [4][8][4]
    // (use full 4x8 accumulator grid)
    float cc[4][8][4];
#pragma unroll
    for (int i = 0; i < 4; ++i)
#pragma unroll
        for (int j = 0; j < 8; ++j)
#pragma unroll
            for (int r = 0; r < 4; ++r) cc[i][j][r] = 0.f;
    (void)c;

    const int nk = K / BKK;

    auto load_stage = [&](int s, int kc) {
        const int k0 = kc * BKK;
        const uint32_t so = s * stagestep;
#pragma unroll
        for (int k = 0; k < 4; ++k)
            asm volatile("cp.async.cg.shared.global [%0], [%1], 16;\n"
                         :: "r"(saB + so + k * rowskip), "l"(arow[k] + k0) : "memory");
#pragma unroll
        for (int k = 0; k < 8; ++k)
            asm volatile("cp.async.cg.shared.global [%0], [%1], 16;\n"
                         :: "r"(sbB + so + k * rowskip),
                            "l"(bbase + (size_t)32 * k * K + k0) : "memory");
        asm volatile("cp.async.commit_group;\n" ::: "memory");
    };

    load_stage(0, 0);
    load_stage(1, 1);

    int buf = 0;
    for (int kc = 0; kc < nk; ++kc) {
        asm volatile("cp.async.wait_group 1;\n" ::: "memory");
        __syncthreads();
        if (kc + 2 < nk) {
            int nb = buf + 2; if (nb >= STAGES) nb -= STAGES;
            load_stage(nb, kc + 2);
        } else {
            asm volatile("cp.async.commit_group;\n" ::: "memory");
        }

        const float* Ash = smem + buf * STAGE_FLOATS;
        const float* Bsh = Ash + A_STAGE_FLOATS;

#pragma unroll
        for (int kk = 0; kk < BKK; kk += 8) {
            uint32_t a[4][4], b[8][2];
#pragma unroll
            for (int mi = 0; mi < 4; ++mi) {
                int r = wm + mi * 16 + g;
                a[mi][0] = __float_as_uint(Ash[(r    ) * STR + kk + tg    ]);
                a[mi][1] = __float_as_uint(Ash[(r + 8) * STR + kk + tg    ]);
                a[mi][2] = __float_as_uint(Ash[(r    ) * STR + kk + tg + 4]);
                a[mi][3] = __float_as_uint(Ash[(r + 8) * STR + kk + tg + 4]);
            }
#pragma unroll
            for (int ni = 0; ni < 8; ++ni) {
                int r = wn + ni * 8 + g;
                b[ni][0] = cvt_tf32u(Bsh[r * STR + kk + tg    ]);
                b[ni][1] = cvt_tf32u(Bsh[r * STR + kk + tg + 4]);
            }
#pragma unroll
            for (int mi = 0; mi < 4; ++mi)
#pragma unroll
                for (int ni = 0; ni < 8; ++ni)
                    asm volatile(
                        "mma.sync.aligned.m16n8k8.row.col.f32.tf32.tf32.f32 "
                        "{%0,%1,%2,%3}, {%4,%5,%6,%7}, {%8,%9}, {%0,%1,%2,%3};"
                        : "+f"(cc[mi][ni][0]), "+f"(cc[mi][ni][1]),
                          "+f"(cc[mi][ni][2]), "+f"(cc[mi][ni][3])
                        : "r"(a[mi][0]), "r"(a[mi][1]), "r"(a[mi][2]), "r"(a[mi][3]),
                          "r"(b[ni][0]), "r"(b[ni][1]));
        }
        if (++buf == STAGES) buf = 0;
    }

#pragma unroll
    for (int mi = 0; mi < 4; ++mi) {
        int m0 = blockIdx.y * BM + wm + mi * 16 + g;
        int m1 = m0 + 8;
#pragma unroll
        for (int ni = 0; ni < 8; ++ni) {
            int n0 = blockIdx.x * BN + wn + ni * 8 + 2 * tg;
            if (m0 < M) {
                float* p = C + (size_t)m0 * N + n0;
                p[0] = cc[mi][ni][0]; p[1] = cc[mi][ni][1];
            }
            if (m1 < M) {
                float* p = C + (size_t)m1 * N + n0;
                p[0] = cc[mi][ni][2]; p[1] = cc[mi][ni][3];
            }
        }
    }
}

// ---------------------------------------------------------------------------
// Sparse fused conv + bias + silu(x)*silu(z)*comb, tf32-round the output.
// ---------------------------------------------------------------------------
__global__ void conv_act_sparse(const float* __restrict__ cw_all,
                                const float* __restrict__ cb_all)
{
    const int e = blockIdx.y;
    const int cnt = g_cnts2[2 * e];
    const int total = cnt * (DI / 4);
    const int* sel = g_lists + (2 * e) * NT;
    const int* posx = g_posx + e * NT;
    const float* zb = g_zx + (size_t)(2 * e) * NT * DI;
    const float* xb = g_zx + (size_t)(2 * e + 1) * NT * DI;
    float* xact = g_xact + (size_t)e * NT * DI;
    const float4* cwf = reinterpret_cast<const float4*>(cw_all + (size_t)e * DI * 4);
    const float4* cbf = reinterpret_cast<const float4*>(cb_all + (size_t)e * DI);

    for (int idx = blockIdx.x * blockDim.x + threadIdx.x; idx < total;
         idx += gridDim.x * blockDim.x) {
        const int i  = idx >> 9;
        const int c4 = idx & 511;
        const int c  = c4 * 4;
        const int t  = sel[i];
        const float wgt = g_comb[(size_t)t * NE + e];
        const int b = t >> 11, s = t & (Ss - 1);

        float4 w0 = cwf[c4 * 4 + 0];
        float4 w1 = cwf[c4 * 4 + 1];
        float4 w2 = cwf[c4 * 4 + 2];
        float4 w3 = cwf[c4 * 4 + 3];
        float4 acc = cbf[c4];

#pragma unroll
        for (int j = 0; j < 4; ++j) {
            int sj = s - 3 + j;
            if (sj < 0) continue;
            int r = posx[b * Ss + sj];
            const float4 xv = *reinterpret_cast<const float4*>(xb + (size_t)r * DI + c);
            float t0 = (j == 0) ? w0.x : (j == 1) ? w0.y : (j == 2) ? w0.z : w0.w;
            float t1 = (j == 0) ? w1.x : (j == 1) ? w1.y : (j == 2) ? w1.z : w1.w;
            float t2 = (j == 0) ? w2.x : (j == 1) ? w2.y : (j == 2) ? w2.z : w2.w;
            float t3 = (j == 0) ? w3.x : (j == 1) ? w3.y : (j == 2) ? w3.z : w3.w;
            acc.x += t0 * xv.x; acc.y += t1 * xv.y;
            acc.z += t2 * xv.z; acc.w += t3 * xv.w;
        }

        const float4 z = *reinterpret_cast<const float4*>(zb + (size_t)i * DI + c);
        float4 o;
        o.x = round_tf32f(silu_(acc.x) * silu_(z.x) * wgt);
        o.y = round_tf32f(silu_(acc.y) * silu_(z.y) * wgt);
        o.z = round_tf32f(silu_(acc.z) * silu_(z.z) * wgt);
        o.w = round_tf32f(silu_(acc.w) * silu_(z.w) * wgt);
        *reinterpret_cast<float4*>(xact + (size_t)i * DI + c) = o;
    }
}

// ---------------------------------------------------------------------------
// Combine: out[t] = outbuf[e1][q1] + outbuf[e2][q2].
// ---------------------------------------------------------------------------
__global__ void combine_kernel(float* __restrict__ out)
{
    const int t = blockIdx.x;
    const int4 m = g_tokmap[t];
    const float4* a = reinterpret_cast<const float4*>(
        g_outbuf + ((size_t)m.x * NT + m.y) * Dd);
    const float4* b = reinterpret_cast<const float4*>(
        g_outbuf + ((size_t)m.z * NT + m.w) * Dd);
    float4* o = reinterpret_cast<float4*>(out + (size_t)t * Dd);
    const int i = threadIdx.x;
    float4 va = a[i], vb = b[i];
    o[i] = make_float4(va.x + vb.x, va.y + vb.y, va.z + vb.z, va.w + vb.w);
}

// ---------------------------------------------------------------------------
extern "C" void kernel_launch(void* const* d_in, const int* in_sizes, int n_in,
                              void* d_out, int out_size)
{
    const float* h   = (const float*)d_in[0];
    const float* inw = (const float*)d_in[1];
    const float* cw  = (const float*)d_in[2];
    const float* cb  = (const float*)d_in[3];
    const float* ow  = (const float*)d_in[4];
    const float* rw1 = (const float*)d_in[5];
    const float* rw2 = (const float*)d_in[6];
    float* out = (float*)d_out;

    void *zxp, *xap, *obp, *hrp, *rhp, *cntp, *lstp;
    cudaGetSymbolAddress(&zxp, g_zx);
    cudaGetSymbolAddress(&xap, g_xact);
    cudaGetSymbolAddress(&obp, g_outbuf);
    cudaGetSymbolAddress(&hrp, g_hr);
    cudaGetSymbolAddress(&rhp, g_rh);
    cudaGetSymbolAddress(&cntp, g_cnts2);
    cudaGetSymbolAddress(&lstp, g_lists);
    float* zx   = (float*)zxp;
    float* xact = (float*)xap;
    float* obuf = (float*)obp;
    float* hr   = (float*)hrp;
    float* rh   = (float*)rhp;
    int* cnts   = (int*)cntp;
    int* lists  = (int*)lstp;

    cudaFuncSetAttribute(gemm_tn_v5, cudaFuncAttributeMaxDynamicSharedMemorySize,
                         SMEM_BYTES);

    cudaMemsetAsync(cnts, 0, 16 * sizeof(int));

    // tf32-round the shared activation once (weights are cvt'd in-loop)
    round_pass<<<1024, 256>>>((const float4*)h, (float4*)hr, NT * Dd / 4);

    // router, all fp32
    router_l1<<<NT / 64, 256>>>(h, rw1, rh);
    router_finish<<<(NT * 32) / 256, 256>>>(rh, rw2);
    build_xlists<<<dim3(NT / 256, NE), 256>>>();

    // in_proj: 16 jobs (expert e: job 2e = z rows, job 2e+1 = x rows)
    gemm_tn_v5<<<dim3(DI / BN, NT / BM, 16), 256, SMEM_BYTES>>>(
        hr, inw, zx, cnts, 0, 1, DI, Dd,
        (size_t)0, (size_t)DI * Dd, (size_t)NT * DI, lists, (size_t)NT);

    // conv + gate, batched over experts
    conv_act_sparse<<<dim3(1024, NE), 256>>>(cw, cb);

    // out_proj per expert -> list-ordered outbuf
    gemm_tn_v5<<<dim3(Dd / BN, NT / BM, NE), 256, SMEM_BYTES>>>(
        xact, ow, obuf, cnts, 0, 2, Dd, DI,
        (size_t)NT * DI, (size_t)Dd * DI, (size_t)NT * Dd, nullptr, (size_t)0);

    // final combine
    combine_kernel<<<NT, 256>>>(out);
}

// round 10
// speedup vs baseline: 1.1995x; 1.0398x over previous
#include <cuda_runtime.h>
#include <cstdint>
#include <cstddef>

// Problem constants
#define BATCH 4
#define Ss 2048
#define Dd 1024
#define DI 2048          // D_INNER
#define NT (BATCH*Ss)    // 8192 tokens
#define NE 8
#define RHID 128

// GEMM tile config: 128x128x32 CTA tile, 128 threads (4 warps of 64x64)
#define BM 128
#define BN 128
#define BKK 32
#define STR 36                         // padded smem row stride (floats)
#define STAGES 3
#define A_STAGE_FLOATS (BM * STR)
#define STAGE_FLOATS ((BM + BN) * STR)
#define SMEM_BYTES (STAGES * STAGE_FLOATS * 4)   // 110,592 B -> 2 CTAs/SM

// Scratch (device globals: allocation-free rule)
__device__ float g_zx[(size_t)16 * NT * DI];
__device__ float g_xact[(size_t)NE * NT * DI];
__device__ float g_hr[(size_t)NT * Dd];
__device__ float g_rh[(size_t)NT * RHID];
__device__ float g_comb[(size_t)NT * NE];
__device__ int   g_selflag[(size_t)NT * NE];
__device__ int   g_lists[16 * NT];
__device__ int   g_posx[NE * NT];
__device__ int   g_cnts2[16];

__device__ __forceinline__ float silu_(float x) { return x / (1.0f + expf(-x)); }

__device__ __forceinline__ float round_tf32f(float f) {
    uint32_t u;
    asm("cvt.rna.tf32.f32 %0, %1;" : "=r"(u) : "f"(f));
    return __uint_as_float(u);
}

__device__ __forceinline__ uint32_t cvt_tf32u(float f) {
    uint32_t u;
    asm("cvt.rna.tf32.f32 %0, %1;" : "=r"(u) : "f"(f));
    return u;
}

// ---------------------------------------------------------------------------
// Elementwise tf32 rounding pass (activations only).
// ---------------------------------------------------------------------------
__global__ void round_pass(const float4* __restrict__ src, float4* __restrict__ dst,
                           int n4)
{
    for (int i = blockIdx.x * blockDim.x + threadIdx.x; i < n4;
         i += gridDim.x * blockDim.x) {
        float4 v = src[i];
        v.x = round_tf32f(v.x); v.y = round_tf32f(v.y);
        v.z = round_tf32f(v.z); v.w = round_tf32f(v.w);
        dst[i] = v;
    }
}

// ---------------------------------------------------------------------------
// Router layer 1, FULL FP32 (64 tokens/block, grid 128).
// ---------------------------------------------------------------------------
__global__ __launch_bounds__(256) void router_l1(const float* __restrict__ h,
                                                 const float* __restrict__ w1,
                                                 float* __restrict__ rh)
{
    __shared__ float As[64][33];
    __shared__ float Ws[128][33];

    const int tid = threadIdx.x;
    const int t0 = blockIdx.x * 64;
    const int ty = tid >> 4;
    const int tx = tid & 15;

    float acc[4][8];
#pragma unroll
    for (int i = 0; i < 4; ++i)
#pragma unroll
        for (int j = 0; j < 8; ++j) acc[i][j] = 0.f;

    const int arow = tid >> 2, acol = (tid & 3) * 8;
    const int wrow = tid >> 1, wcol = (tid & 1) * 16;

    for (int k0 = 0; k0 < Dd; k0 += 32) {
        float4 a0 = *(const float4*)&h[(size_t)(t0 + arow) * Dd + k0 + acol];
        float4 a1 = *(const float4*)&h[(size_t)(t0 + arow) * Dd + k0 + acol + 4];
        As[arow][acol + 0] = a0.x; As[arow][acol + 1] = a0.y;
        As[arow][acol + 2] = a0.z; As[arow][acol + 3] = a0.w;
        As[arow][acol + 4] = a1.x; As[arow][acol + 5] = a1.y;
        As[arow][acol + 6] = a1.z; As[arow][acol + 7] = a1.w;
#pragma unroll
        for (int q = 0; q < 4; ++q) {
            float4 w = *(const float4*)&w1[(size_t)wrow * Dd + k0 + wcol + q * 4];
            Ws[wrow][wcol + q * 4 + 0] = w.x; Ws[wrow][wcol + q * 4 + 1] = w.y;
            Ws[wrow][wcol + q * 4 + 2] = w.z; Ws[wrow][wcol + q * 4 + 3] = w.w;
        }
        __syncthreads();

#pragma unroll 8
        for (int k = 0; k < 32; ++k) {
            float a[4], b[8];
#pragma unroll
            for (int i = 0; i < 4; ++i) a[i] = As[ty * 4 + i][k];
#pragma unroll
            for (int j = 0; j < 8; ++j) b[j] = Ws[tx * 8 + j][k];
#pragma unroll
            for (int i = 0; i < 4; ++i)
#pragma unroll
                for (int j = 0; j < 8; ++j) acc[i][j] += a[i] * b[j];
        }
        __syncthreads();
    }

#pragma unroll
    for (int i = 0; i < 4; ++i) {
        int t = t0 + ty * 4 + i;
#pragma unroll
        for (int j = 0; j < 8; ++j)
            rh[(size_t)t * RHID + tx * 8 + j] = silu_(acc[i][j]);
    }
}

// ---------------------------------------------------------------------------
// Router finish (fp32): logits, top-2 softmax, comb/selflag/lists.
// ---------------------------------------------------------------------------
__global__ void router_finish(const float* __restrict__ rh,
                              const float* __restrict__ w2)
{
    int t = (blockIdx.x * blockDim.x + threadIdx.x) >> 5;
    int lane = threadIdx.x & 31;
    if (t >= NT) return;

    const float* r = rh + (size_t)t * RHID;
    float v0 = r[lane], v1 = r[lane + 32], v2 = r[lane + 64], v3 = r[lane + 96];

    float lg[NE];
#pragma unroll
    for (int e = 0; e < NE; ++e) {
        const float* w = w2 + e * RHID;
        float p = v0 * w[lane] + v1 * w[lane + 32] + v2 * w[lane + 64] + v3 * w[lane + 96];
#pragma unroll
        for (int o = 16; o; o >>= 1) p += __shfl_xor_sync(0xffffffffu, p, o);
        lg[e] = p;
    }

    if (lane == 0) {
        int i1 = 0; float l1 = lg[0];
#pragma unroll
        for (int e = 1; e < NE; ++e) if (lg[e] > l1) { l1 = lg[e]; i1 = e; }
        int i2 = -1; float l2 = -1e30f;
#pragma unroll
        for (int e = 0; e < NE; ++e) { if (e == i1) continue; if (lg[e] > l2) { l2 = lg[e]; i2 = e; } }
        float wtop = 1.f / (1.f + expf(l2 - l1));
        float* cb = &g_comb[(size_t)t * NE];
        int* sf = &g_selflag[(size_t)t * NE];
#pragma unroll
        for (int e = 0; e < NE; ++e) { cb[e] = 0.f; sf[e] = 0; }
        cb[i1] = wtop;       sf[i1] = 1;
        cb[i2] = 1.f - wtop; sf[i2] = 1;
        int q1 = atomicAdd(&g_cnts2[2 * i1], 1); g_lists[(2 * i1) * NT + q1] = t;
        int q2 = atomicAdd(&g_cnts2[2 * i2], 1); g_lists[(2 * i2) * NT + q2] = t;
    }
}

// ---------------------------------------------------------------------------
// Conv-input (dilated) token lists.
// ---------------------------------------------------------------------------
__global__ void build_xlists()
{
    int t = blockIdx.x * blockDim.x + threadIdx.x;
    int e = blockIdx.y;
    if (t >= NT) return;
    int b = t >> 11, s = t & (Ss - 1);
    bool need = false;
#pragma unroll
    for (int j = 0; j < 4; ++j) {
        int sj = s + j;
        if (sj < Ss) need |= (g_selflag[(size_t)(b * Ss + sj) * NE + e] != 0);
    }
    if (need) {
        int p = atomicAdd(&g_cnts2[2 * e + 1], 1);
        g_lists[(2 * e + 1) * NT + p] = t;
        g_posx[e * NT + t] = p;
    }
}

// ---------------------------------------------------------------------------
// TF32 GEMM (TN), batched over blockIdx.z: C[M,N] op= A[M,K] * W[N,K]^T.
// 128x128x32 CTA tile, 128 threads = 4 warps of 64x64 (2m x 2n).
// 3-stage cp.async ring, 110.6KB smem -> 2 CTAs/SM for latency overlap.
// A pre-rounded tf32; W raw fp32 cvt'd in-loop (bit-identical).
// mode 0: store to C row m. mode 1: atomicAdd into C row c_idx[m].
// ---------------------------------------------------------------------------
__global__ __launch_bounds__(128, 2) void gemm_tn_v6(
    const float* __restrict__ A, const float* __restrict__ W, float* __restrict__ C,
    const int* __restrict__ cnts, int mBase, int mStride,
    int N, int K,
    size_t aStrideZ, size_t wStrideZ, size_t cStrideZ,
    const int* __restrict__ a_idx, size_t aIdxStrideZ,
    const int* __restrict__ c_idx, size_t cIdxStrideZ,
    int mode)
{
    const int z = blockIdx.z;
    const int M = cnts[mBase + z * mStride];
    if ((int)blockIdx.y * BM >= M) return;

    A += (size_t)z * aStrideZ;
    W += (size_t)z * wStrideZ;
    C += (size_t)z * cStrideZ;
    const int* aidx = a_idx ? a_idx + (size_t)z * aIdxStrideZ : nullptr;
    const int* cidx = c_idx ? c_idx + (size_t)z * cIdxStrideZ : nullptr;

    extern __shared__ float smem[];

    const int tid  = threadIdx.x;
    const int lane = tid & 31;
    const int warp = tid >> 5;
    const int g  = lane >> 2;
    const int tg = lane & 3;
    const int wm = (warp & 1) * 64;      // 0,64
    const int wn = (warp >> 1) * 64;     // 0,64

    // Loader: 16B chunks; row = 32 floats = 8 chunks; atom = tid&7 constant.
    // A: rows r0+16j (j=0..7); B: rows r0+16j.
    const int r0   = tid >> 3;           // 0..15
    const int roff = (tid & 7) * 4;

    int arowidx[8];
#pragma unroll
    for (int j = 0; j < 8; ++j) {
        int gr = blockIdx.y * BM + r0 + 16 * j;
        int cr = min(gr, M - 1);
        arowidx[j] = aidx ? aidx[cr] : cr;
    }
    const float* bbase = W + (size_t)(blockIdx.x * BN + r0) * K + roff;

    const uint32_t saB = (uint32_t)__cvta_generic_to_shared(&smem[r0 * STR + roff]);
    const uint32_t sbB = (uint32_t)__cvta_generic_to_shared(
        &smem[A_STAGE_FLOATS + r0 * STR + roff]);
    const uint32_t stagestep = (uint32_t)(STAGE_FLOATS * sizeof(float));
    const uint32_t rowskip = (uint32_t)(16 * STR * sizeof(float));

    float cc[4][8][4];
#pragma unroll
    for (int i = 0; i < 4; ++i)
#pragma unroll
        for (int j = 0; j < 8; ++j)
#pragma unroll
            for (int r = 0; r < 4; ++r) cc[i][j][r] = 0.f;

    const int nk = K / BKK;

    auto load_stage = [&](int s, int kc) {
        const int k0 = kc * BKK;
        const uint32_t so = s * stagestep;
#pragma unroll
        for (int j = 0; j < 8; ++j) {
            const float* src = A + (size_t)arowidx[j] * K + roff + k0;
            asm volatile("cp.async.cg.shared.global [%0], [%1], 16;\n"
                         :: "r"(saB + so + j * rowskip), "l"(src) : "memory");
        }
#pragma unroll
        for (int j = 0; j < 8; ++j)
            asm volatile("cp.async.cg.shared.global [%0], [%1], 16;\n"
                         :: "r"(sbB + so + j * rowskip),
                            "l"(bbase + (size_t)16 * j * K + k0) : "memory");
        asm volatile("cp.async.commit_group;\n" ::: "memory");
    };

    load_stage(0, 0);
    load_stage(1, 1);

    int buf = 0;
    for (int kc = 0; kc < nk; ++kc) {
        asm volatile("cp.async.wait_group 1;\n" ::: "memory");
        __syncthreads();
        if (kc + 2 < nk) {
            int nb = buf + 2; if (nb >= STAGES) nb -= STAGES;
            load_stage(nb, kc + 2);
        } else {
            asm volatile("cp.async.commit_group;\n" ::: "memory");
        }

        const float* Ash = smem + buf * STAGE_FLOATS;
        const float* Bsh = Ash + A_STAGE_FLOATS;

#pragma unroll
        for (int kk = 0; kk < BKK; kk += 8) {
            uint32_t a[4][4], b[8][2];
#pragma unroll
            for (int mi = 0; mi < 4; ++mi) {
                int r = wm + mi * 16 + g;
                a[mi][0] = __float_as_uint(Ash[(r    ) * STR + kk + tg    ]);
                a[mi][1] = __float_as_uint(Ash[(r + 8) * STR + kk + tg    ]);
                a[mi][2] = __float_as_uint(Ash[(r    ) * STR + kk + tg + 4]);
                a[mi][3] = __float_as_uint(Ash[(r + 8) * STR + kk + tg + 4]);
            }
#pragma unroll
            for (int ni = 0; ni < 8; ++ni) {
                int r = wn + ni * 8 + g;
                b[ni][0] = cvt_tf32u(Bsh[r * STR + kk + tg    ]);
                b[ni][1] = cvt_tf32u(Bsh[r * STR + kk + tg + 4]);
            }
#pragma unroll
            for (int mi = 0; mi < 4; ++mi)
#pragma unroll
                for (int ni = 0; ni < 8; ++ni)
                    asm volatile(
                        "mma.sync.aligned.m16n8k8.row.col.f32.tf32.tf32.f32 "
                        "{%0,%1,%2,%3}, {%4,%5,%6,%7}, {%8,%9}, {%0,%1,%2,%3};"
                        : "+f"(cc[mi][ni][0]), "+f"(cc[mi][ni][1]),
                          "+f"(cc[mi][ni][2]), "+f"(cc[mi][ni][3])
                        : "r"(a[mi][0]), "r"(a[mi][1]), "r"(a[mi][2]), "r"(a[mi][3]),
                          "r"(b[ni][0]), "r"(b[ni][1]));
        }
        if (++buf == STAGES) buf = 0;
    }

#pragma unroll
    for (int mi = 0; mi < 4; ++mi) {
        int m0 = blockIdx.y * BM + wm + mi * 16 + g;
        int m1 = m0 + 8;
#pragma unroll
        for (int ni = 0; ni < 8; ++ni) {
            int n0 = blockIdx.x * BN + wn + ni * 8 + 2 * tg;
            if (mode == 0) {
                if (m0 < M) {
                    float* p = C + (size_t)m0 * N + n0;
                    p[0] = cc[mi][ni][0]; p[1] = cc[mi][ni][1];
                }
                if (m1 < M) {
                    float* p = C + (size_t)m1 * N + n0;
                    p[0] = cc[mi][ni][2]; p[1] = cc[mi][ni][3];
                }
            } else {
                if (m0 < M) {
                    float* p = C + (size_t)cidx[m0] * N + n0;
                    atomicAdd(&p[0], cc[mi][ni][0]);
                    atomicAdd(&p[1], cc[mi][ni][1]);
                }
                if (m1 < M) {
                    float* p = C + (size_t)cidx[m1] * N + n0;
                    atomicAdd(&p[0], cc[mi][ni][2]);
                    atomicAdd(&p[1], cc[mi][ni][3]);
                }
            }
        }
    }
}

// ---------------------------------------------------------------------------
// Sparse fused conv + bias + silu(x)*silu(z)*comb, tf32-round the output.
// ---------------------------------------------------------------------------
__global__ void conv_act_sparse(const float* __restrict__ cw_all,
                                const float* __restrict__ cb_all)
{
    const int e = blockIdx.y;
    const int cnt = g_cnts2[2 * e];
    const int total = cnt * (DI / 4);
    const int* sel = g_lists + (2 * e) * NT;
    const int* posx = g_posx + e * NT;
    const float* zb = g_zx + (size_t)(2 * e) * NT * DI;
    const float* xb = g_zx + (size_t)(2 * e + 1) * NT * DI;
    float* xact = g_xact + (size_t)e * NT * DI;
    const float4* cwf = reinterpret_cast<const float4*>(cw_all + (size_t)e * DI * 4);
    const float4* cbf = reinterpret_cast<const float4*>(cb_all + (size_t)e * DI);

    for (int idx = blockIdx.x * blockDim.x + threadIdx.x; idx < total;
         idx += gridDim.x * blockDim.x) {
        const int i  = idx >> 9;
        const int c4 = idx & 511;
        const int c  = c4 * 4;
        const int t  = sel[i];
        const float wgt = g_comb[(size_t)t * NE + e];
        const int b = t >> 11, s = t & (Ss - 1);

        float4 w0 = cwf[c4 * 4 + 0];
        float4 w1 = cwf[c4 * 4 + 1];
        float4 w2 = cwf[c4 * 4 + 2];
        float4 w3 = cwf[c4 * 4 + 3];
        float4 acc = cbf[c4];

#pragma unroll
        for (int j = 0; j < 4; ++j) {
            int sj = s - 3 + j;
            if (sj < 0) continue;
            int r = posx[b * Ss + sj];
            const float4 xv = *reinterpret_cast<const float4*>(xb + (size_t)r * DI + c);
            float t0 = (j == 0) ? w0.x : (j == 1) ? w0.y : (j == 2) ? w0.z : w0.w;
            float t1 = (j == 0) ? w1.x : (j == 1) ? w1.y : (j == 2) ? w1.z : w1.w;
            float t2 = (j == 0) ? w2.x : (j == 1) ? w2.y : (j == 2) ? w2.z : w2.w;
            float t3 = (j == 0) ? w3.x : (j == 1) ? w3.y : (j == 2) ? w3.z : w3.w;
            acc.x += t0 * xv.x; acc.y += t1 * xv.y;
            acc.z += t2 * xv.z; acc.w += t3 * xv.w;
        }

        const float4 z = *reinterpret_cast<const float4*>(zb + (size_t)i * DI + c);
        float4 o;
        o.x = round_tf32f(silu_(acc.x) * silu_(z.x) * wgt);
        o.y = round_tf32f(silu_(acc.y) * silu_(z.y) * wgt);
        o.z = round_tf32f(silu_(acc.z) * silu_(z.z) * wgt);
        o.w = round_tf32f(silu_(acc.w) * silu_(z.w) * wgt);
        *reinterpret_cast<float4*>(xact + (size_t)i * DI + c) = o;
    }
}

// ---------------------------------------------------------------------------
extern "C" void kernel_launch(void* const* d_in, const int* in_sizes, int n_in,
                              void* d_out, int out_size)
{
    const float* h   = (const float*)d_in[0];
    const float* inw = (const float*)d_in[1];
    const float* cw  = (const float*)d_in[2];
    const float* cb  = (const float*)d_in[3];
    const float* ow  = (const float*)d_in[4];
    const float* rw1 = (const float*)d_in[5];
    const float* rw2 = (const float*)d_in[6];
    float* out = (float*)d_out;

    void *zxp, *xap, *hrp, *rhp, *cntp, *lstp;
    cudaGetSymbolAddress(&zxp, g_zx);
    cudaGetSymbolAddress(&xap, g_xact);
    cudaGetSymbolAddress(&hrp, g_hr);
    cudaGetSymbolAddress(&rhp, g_rh);
    cudaGetSymbolAddress(&cntp, g_cnts2);
    cudaGetSymbolAddress(&lstp, g_lists);
    float* zx   = (float*)zxp;
    float* xact = (float*)xap;
    float* hr   = (float*)hrp;
    float* rh   = (float*)rhp;
    int* cnts   = (int*)cntp;
    int* lists  = (int*)lstp;

    cudaFuncSetAttribute(gemm_tn_v6, cudaFuncAttributeMaxDynamicSharedMemorySize,
                         SMEM_BYTES);

    cudaMemsetAsync(cnts, 0, 16 * sizeof(int));
    cudaMemsetAsync(out, 0, (size_t)NT * Dd * sizeof(float));

    // tf32-round the shared activation once (weights cvt'd in-loop)
    round_pass<<<1024, 256>>>((const float4*)h, (float4*)hr, NT * Dd / 4);

    // router, all fp32
    router_l1<<<NT / 64, 256>>>(h, rw1, rh);
    router_finish<<<(NT * 32) / 256, 256>>>(rh, rw2);
    build_xlists<<<dim3(NT / 256, NE), 256>>>();

    // in_proj: 16 jobs (expert e: job 2e = z rows, job 2e+1 = x rows)
    gemm_tn_v6<<<dim3(DI / BN, NT / BM, 16), 128, SMEM_BYTES>>>(
        hr, inw, zx, cnts, 0, 1, DI, Dd,
        (size_t)0, (size_t)DI * Dd, (size_t)NT * DI,
        lists, (size_t)NT, nullptr, (size_t)0, 0);

    // conv + gate, batched over experts
    conv_act_sparse<<<dim3(1024, NE), 256>>>(cw, cb);

    // out_proj per expert: atomic scatter-accumulate into out (2 adds/elem,
    // commutative -> deterministic, value-identical to separate combine)
    gemm_tn_v6<<<dim3(Dd / BN, NT / BM, NE), 128, SMEM_BYTES>>>(
        xact, ow, out, cnts, 0, 2, Dd, DI,
        (size_t)NT * DI, (size_t)Dd * DI, (size_t)0,
        nullptr, (size_t)0, lists, (size_t)(2 * NT), 1);
}

// round 11
// speedup vs baseline: 1.9826x; 1.6529x over previous
#include <cuda_runtime.h>
#include <cuda_fp16.h>
#include <cstdint>
#include <cstddef>

// Problem constants
#define BATCH 4
#define Ss 2048
#define Dd 1024
#define DI 2048          // D_INNER
#define NT (BATCH*Ss)    // 8192 tokens
#define NE 8
#define RHID 128

// FP16 GEMM tile config: 128x128x64 CTA tile, 128 threads (4 warps of 64x64)
#define BM 128
#define BN 128
#define BKH 64                          // K elements per stage (halfs)
#define STRH 72                         // padded smem row stride (halfs) = 144B
#define STAGES 3
#define A_STAGE_HALFS (BM * STRH)
#define STAGE_HALFS ((BM + BN) * STRH)
#define SMEM_BYTES (STAGES * STAGE_HALFS * 2)   // 110,592 B -> 2 CTAs/SM

// Scratch (device globals: allocation-free rule)
__device__ float  g_zx[(size_t)16 * NT * DI];     // in_proj outputs (fp32)
__device__ __half g_xact[(size_t)NE * NT * DI];   // gated act (fp16)
__device__ __half g_hh[(size_t)NT * Dd];          // h in fp16
__device__ __half g_inwh[(size_t)NE * 2 * DI * Dd];
__device__ __half g_owh[(size_t)NE * Dd * DI];
__device__ float  g_rh[(size_t)NT * RHID];
__device__ float  g_comb[(size_t)NT * NE];
__device__ int    g_selflag[(size_t)NT * NE];
__device__ int    g_lists[16 * NT];
__device__ int    g_posx[NE * NT];
__device__ int    g_cnts2[16];

__device__ __forceinline__ float silu_(float x) { return x / (1.0f + expf(-x)); }

// ---------------------------------------------------------------------------
// fp32 -> fp16 convert pass (vectorized).
// ---------------------------------------------------------------------------
__global__ void to_half_pass(const float4* __restrict__ src,
                             uint2* __restrict__ dst, int n4)
{
    for (int i = blockIdx.x * blockDim.x + threadIdx.x; i < n4;
         i += gridDim.x * blockDim.x) {
        float4 v = src[i];
        __half2 lo = __floats2half2_rn(v.x, v.y);
        __half2 hi = __floats2half2_rn(v.z, v.w);
        uint2 o;
        o.x = *reinterpret_cast<uint32_t*>(&lo);
        o.y = *reinterpret_cast<uint32_t*>(&hi);
        dst[i] = o;
    }
}

// ---------------------------------------------------------------------------
// Router layer 1, FULL FP32 (64 tokens/block, grid 128).
// ---------------------------------------------------------------------------
__global__ __launch_bounds__(256) void router_l1(const float* __restrict__ h,
                                                 const float* __restrict__ w1,
                                                 float* __restrict__ rh)
{
    __shared__ float As[64][33];
    __shared__ float Ws[128][33];

    const int tid = threadIdx.x;
    const int t0 = blockIdx.x * 64;
    const int ty = tid >> 4;
    const int tx = tid & 15;

    float acc[4][8];
#pragma unroll
    for (int i = 0; i < 4; ++i)
#pragma unroll
        for (int j = 0; j < 8; ++j) acc[i][j] = 0.f;

    const int arow = tid >> 2, acol = (tid & 3) * 8;
    const int wrow = tid >> 1, wcol = (tid & 1) * 16;

    for (int k0 = 0; k0 < Dd; k0 += 32) {
        float4 a0 = *(const float4*)&h[(size_t)(t0 + arow) * Dd + k0 + acol];
        float4 a1 = *(const float4*)&h[(size_t)(t0 + arow) * Dd + k0 + acol + 4];
        As[arow][acol + 0] = a0.x; As[arow][acol + 1] = a0.y;
        As[arow][acol + 2] = a0.z; As[arow][acol + 3] = a0.w;
        As[arow][acol + 4] = a1.x; As[arow][acol + 5] = a1.y;
        As[arow][acol + 6] = a1.z; As[arow][acol + 7] = a1.w;
#pragma unroll
        for (int q = 0; q < 4; ++q) {
            float4 w = *(const float4*)&w1[(size_t)wrow * Dd + k0 + wcol + q * 4];
            Ws[wrow][wcol + q * 4 + 0] = w.x; Ws[wrow][wcol + q * 4 + 1] = w.y;
            Ws[wrow][wcol + q * 4 + 2] = w.z; Ws[wrow][wcol + q * 4 + 3] = w.w;
        }
        __syncthreads();

#pragma unroll 8
        for (int k = 0; k < 32; ++k) {
            float a[4], b[8];
#pragma unroll
            for (int i = 0; i < 4; ++i) a[i] = As[ty * 4 + i][k];
#pragma unroll
            for (int j = 0; j < 8; ++j) b[j] = Ws[tx * 8 + j][k];
#pragma unroll
            for (int i = 0; i < 4; ++i)
#pragma unroll
                for (int j = 0; j < 8; ++j) acc[i][j] += a[i] * b[j];
        }
        __syncthreads();
    }

#pragma unroll
    for (int i = 0; i < 4; ++i) {
        int t = t0 + ty * 4 + i;
#pragma unroll
        for (int j = 0; j < 8; ++j)
            rh[(size_t)t * RHID + tx * 8 + j] = silu_(acc[i][j]);
    }
}

// ---------------------------------------------------------------------------
// Router finish (fp32): logits, top-2 softmax, comb/selflag/lists.
// ---------------------------------------------------------------------------
__global__ void router_finish(const float* __restrict__ rh,
                              const float* __restrict__ w2)
{
    int t = (blockIdx.x * blockDim.x + threadIdx.x) >> 5;
    int lane = threadIdx.x & 31;
    if (t >= NT) return;

    const float* r = rh + (size_t)t * RHID;
    float v0 = r[lane], v1 = r[lane + 32], v2 = r[lane + 64], v3 = r[lane + 96];

    float lg[NE];
#pragma unroll
    for (int e = 0; e < NE; ++e) {
        const float* w = w2 + e * RHID;
        float p = v0 * w[lane] + v1 * w[lane + 32] + v2 * w[lane + 64] + v3 * w[lane + 96];
#pragma unroll
        for (int o = 16; o; o >>= 1) p += __shfl_xor_sync(0xffffffffu, p, o);
        lg[e] = p;
    }

    if (lane == 0) {
        int i1 = 0; float l1 = lg[0];
#pragma unroll
        for (int e = 1; e < NE; ++e) if (lg[e] > l1) { l1 = lg[e]; i1 = e; }
        int i2 = -1; float l2 = -1e30f;
#pragma unroll
        for (int e = 0; e < NE; ++e) { if (e == i1) continue; if (lg[e] > l2) { l2 = lg[e]; i2 = e; } }
        float wtop = 1.f / (1.f + expf(l2 - l1));
        float* cb = &g_comb[(size_t)t * NE];
        int* sf = &g_selflag[(size_t)t * NE];
#pragma unroll
        for (int e = 0; e < NE; ++e) { cb[e] = 0.f; sf[e] = 0; }
        cb[i1] = wtop;       sf[i1] = 1;
        cb[i2] = 1.f - wtop; sf[i2] = 1;
        int q1 = atomicAdd(&g_cnts2[2 * i1], 1); g_lists[(2 * i1) * NT + q1] = t;
        int q2 = atomicAdd(&g_cnts2[2 * i2], 1); g_lists[(2 * i2) * NT + q2] = t;
    }
}

// ---------------------------------------------------------------------------
// Conv-input (dilated) token lists.
// ---------------------------------------------------------------------------
__global__ void build_xlists()
{
    int t = blockIdx.x * blockDim.x + threadIdx.x;
    int e = blockIdx.y;
    if (t >= NT) return;
    int b = t >> 11, s = t & (Ss - 1);
    bool need = false;
#pragma unroll
    for (int j = 0; j < 4; ++j) {
        int sj = s + j;
        if (sj < Ss) need |= (g_selflag[(size_t)(b * Ss + sj) * NE + e] != 0);
    }
    if (need) {
        int p = atomicAdd(&g_cnts2[2 * e + 1], 1);
        g_lists[(2 * e + 1) * NT + p] = t;
        g_posx[e * NT + t] = p;
    }
}

// ---------------------------------------------------------------------------
// FP16 GEMM (TN), batched over blockIdx.z: C[M,N] op= A[M,K] * W[N,K]^T.
// 128x128x64 CTA tile, 128 threads = 4 warps of 64x64 (2m x 2n).
// mma.m16n8k16.f32.f16.f16.f32, fp32 accumulate. 3-stage cp.async ring,
// 110.6KB smem -> 2 CTAs/SM. mode 0: store; mode 1: atomicAdd to c_idx rows.
// ---------------------------------------------------------------------------
__global__ __launch_bounds__(128, 2) void gemm_fp16(
    const __half* __restrict__ A, const __half* __restrict__ W,
    float* __restrict__ C,
    const int* __restrict__ cnts, int mBase, int mStride,
    int N, int K,
    size_t aStrideZ, size_t wStrideZ, size_t cStrideZ,
    const int* __restrict__ a_idx, size_t aIdxStrideZ,
    const int* __restrict__ c_idx, size_t cIdxStrideZ,
    int mode)
{
    const int z = blockIdx.z;
    const int M = cnts[mBase + z * mStride];
    if ((int)blockIdx.y * BM >= M) return;

    A += (size_t)z * aStrideZ;
    W += (size_t)z * wStrideZ;
    C += (size_t)z * cStrideZ;
    const int* aidx = a_idx ? a_idx + (size_t)z * aIdxStrideZ : nullptr;
    const int* cidx = c_idx ? c_idx + (size_t)z * cIdxStrideZ : nullptr;

    extern __shared__ __half smem[];

    const int tid  = threadIdx.x;
    const int lane = tid & 31;
    const int warp = tid >> 5;
    const int g  = lane >> 2;
    const int tg = lane & 3;
    const int wm = (warp & 1) * 64;      // 0,64
    const int wn = (warp >> 1) * 64;     // 0,64

    // Loader: 16B chunks (8 halfs); row = 64 halfs = 8 chunks.
    const int r0    = tid >> 3;          // 0..15
    const int roffH = (tid & 7) * 8;     // half offset in row

    int arowidx[8];
#pragma unroll
    for (int j = 0; j < 8; ++j) {
        int gr = blockIdx.y * BM + r0 + 16 * j;
        int cr = min(gr, M - 1);
        arowidx[j] = aidx ? aidx[cr] : cr;
    }
    const __half* bbase = W + (size_t)(blockIdx.x * BN + r0) * K + roffH;

    const uint32_t saB = (uint32_t)__cvta_generic_to_shared(&smem[r0 * STRH + roffH]);
    const uint32_t sbB = (uint32_t)__cvta_generic_to_shared(
        &smem[A_STAGE_HALFS + r0 * STRH + roffH]);
    const uint32_t stagestep = (uint32_t)(STAGE_HALFS * sizeof(__half));
    const uint32_t rowskip = (uint32_t)(16 * STRH * sizeof(__half));

    float cc[4][8][4];
#pragma unroll
    for (int i = 0; i < 4; ++i)
#pragma unroll
        for (int j = 0; j < 8; ++j)
#pragma unroll
            for (int r = 0; r < 4; ++r) cc[i][j][r] = 0.f;

    const int nk = K / BKH;

    auto load_stage = [&](int s, int kc) {
        const int k0 = kc * BKH;
        const uint32_t so = s * stagestep;
#pragma unroll
        for (int j = 0; j < 8; ++j) {
            const __half* src = A + (size_t)arowidx[j] * K + roffH + k0;
            asm volatile("cp.async.cg.shared.global [%0], [%1], 16;\n"
                         :: "r"(saB + so + j * rowskip), "l"(src) : "memory");
        }
#pragma unroll
        for (int j = 0; j < 8; ++j)
            asm volatile("cp.async.cg.shared.global [%0], [%1], 16;\n"
                         :: "r"(sbB + so + j * rowskip),
                            "l"(bbase + (size_t)16 * j * K + k0) : "memory");
        asm volatile("cp.async.commit_group;\n" ::: "memory");
    };

    load_stage(0, 0);
    load_stage(1, 1);

    int buf = 0;
    for (int kc = 0; kc < nk; ++kc) {
        asm volatile("cp.async.wait_group 1;\n" ::: "memory");
        __syncthreads();
        if (kc + 2 < nk) {
            int nb = buf + 2; if (nb >= STAGES) nb -= STAGES;
            load_stage(nb, kc + 2);
        } else {
            asm volatile("cp.async.commit_group;\n" ::: "memory");
        }

        const __half* Ash = smem + buf * STAGE_HALFS;
        const __half* Bsh = Ash + A_STAGE_HALFS;

#pragma unroll
        for (int kk = 0; kk < BKH; kk += 16) {
            uint32_t a[4][4], b[8][2];
#pragma unroll
            for (int mi = 0; mi < 4; ++mi) {
                int r = wm + mi * 16 + g;
                a[mi][0] = *(const uint32_t*)&Ash[(r    ) * STRH + kk + 2 * tg    ];
                a[mi][1] = *(const uint32_t*)&Ash[(r + 8) * STRH + kk + 2 * tg    ];
                a[mi][2] = *(const uint32_t*)&Ash[(r    ) * STRH + kk + 2 * tg + 8];
                a[mi][3] = *(const uint32_t*)&Ash[(r + 8) * STRH + kk + 2 * tg + 8];
            }
#pragma unroll
            for (int ni = 0; ni < 8; ++ni) {
                int r = wn + ni * 8 + g;
                b[ni][0] = *(const uint32_t*)&Bsh[r * STRH + kk + 2 * tg    ];
                b[ni][1] = *(const uint32_t*)&Bsh[r * STRH + kk + 2 * tg + 8];
            }
#pragma unroll
            for (int mi = 0; mi < 4; ++mi)
#pragma unroll
                for (int ni = 0; ni < 8; ++ni)
                    asm volatile(
                        "mma.sync.aligned.m16n8k16.row.col.f32.f16.f16.f32 "
                        "{%0,%1,%2,%3}, {%4,%5,%6,%7}, {%8,%9}, {%0,%1,%2,%3};"
                        : "+f"(cc[mi][ni][0]), "+f"(cc[mi][ni][1]),
                          "+f"(cc[mi][ni][2]), "+f"(cc[mi][ni][3])
                        : "r"(a[mi][0]), "r"(a[mi][1]), "r"(a[mi][2]), "r"(a[mi][3]),
                          "r"(b[ni][0]), "r"(b[ni][1]));
        }
        if (++buf == STAGES) buf = 0;
    }

#pragma unroll
    for (int mi = 0; mi < 4; ++mi) {
        int m0 = blockIdx.y * BM + wm + mi * 16 + g;
        int m1 = m0 + 8;
#pragma unroll
        for (int ni = 0; ni < 8; ++ni) {
            int n0 = blockIdx.x * BN + wn + ni * 8 + 2 * tg;
            if (mode == 0) {
                if (m0 < M) {
                    float* p = C + (size_t)m0 * N + n0;
                    p[0] = cc[mi][ni][0]; p[1] = cc[mi][ni][1];
                }
                if (m1 < M) {
                    float* p = C + (size_t)m1 * N + n0;
                    p[0] = cc[mi][ni][2]; p[1] = cc[mi][ni][3];
                }
            } else {
                if (m0 < M) {
                    float* p = C + (size_t)cidx[m0] * N + n0;
                    atomicAdd(&p[0], cc[mi][ni][0]);
                    atomicAdd(&p[1], cc[mi][ni][1]);
                }
                if (m1 < M) {
                    float* p = C + (size_t)cidx[m1] * N + n0;
                    atomicAdd(&p[0], cc[mi][ni][2]);
                    atomicAdd(&p[1], cc[mi][ni][3]);
                }
            }
        }
    }
}

// ---------------------------------------------------------------------------
// Sparse fused conv + bias + silu(x)*silu(z)*comb -> fp16 xact.
// ---------------------------------------------------------------------------
__global__ void conv_act_sparse(const float* __restrict__ cw_all,
                                const float* __restrict__ cb_all)
{
    const int e = blockIdx.y;
    const int cnt = g_cnts2[2 * e];
    const int total = cnt * (DI / 4);
    const int* sel = g_lists + (2 * e) * NT;
    const int* posx = g_posx + e * NT;
    const float* zb = g_zx + (size_t)(2 * e) * NT * DI;
    const float* xb = g_zx + (size_t)(2 * e + 1) * NT * DI;
    __half* xact = g_xact + (size_t)e * NT * DI;
    const float4* cwf = reinterpret_cast<const float4*>(cw_all + (size_t)e * DI * 4);
    const float4* cbf = reinterpret_cast<const float4*>(cb_all + (size_t)e * DI);

    for (int idx = blockIdx.x * blockDim.x + threadIdx.x; idx < total;
         idx += gridDim.x * blockDim.x) {
        const int i  = idx >> 9;
        const int c4 = idx & 511;
        const int c  = c4 * 4;
        const int t  = sel[i];
        const float wgt = g_comb[(size_t)t * NE + e];
        const int b = t >> 11, s = t & (Ss - 1);

        float4 w0 = cwf[c4 * 4 + 0];
        float4 w1 = cwf[c4 * 4 + 1];
        float4 w2 = cwf[c4 * 4 + 2];
        float4 w3 = cwf[c4 * 4 + 3];
        float4 acc = cbf[c4];

#pragma unroll
        for (int j = 0; j < 4; ++j) {
            int sj = s - 3 + j;
            if (sj < 0) continue;
            int r = posx[b * Ss + sj];
            const float4 xv = *reinterpret_cast<const float4*>(xb + (size_t)r * DI + c);
            float t0 = (j == 0) ? w0.x : (j == 1) ? w0.y : (j == 2) ? w0.z : w0.w;
            float t1 = (j == 0) ? w1.x : (j == 1) ? w1.y : (j == 2) ? w1.z : w1.w;
            float t2 = (j == 0) ? w2.x : (j == 1) ? w2.y : (j == 2) ? w2.z : w2.w;
            float t3 = (j == 0) ? w3.x : (j == 1) ? w3.y : (j == 2) ? w3.z : w3.w;
            acc.x += t0 * xv.x; acc.y += t1 * xv.y;
            acc.z += t2 * xv.z; acc.w += t3 * xv.w;
        }

        const float4 z = *reinterpret_cast<const float4*>(zb + (size_t)i * DI + c);
        __half2 lo = __floats2half2_rn(silu_(acc.x) * silu_(z.x) * wgt,
                                       silu_(acc.y) * silu_(z.y) * wgt);
        __half2 hi = __floats2half2_rn(silu_(acc.z) * silu_(z.z) * wgt,
                                       silu_(acc.w) * silu_(z.w) * wgt);
        uint2 o;
        o.x = *reinterpret_cast<uint32_t*>(&lo);
        o.y = *reinterpret_cast<uint32_t*>(&hi);
        *reinterpret_cast<uint2*>(xact + (size_t)i * DI + c) = o;
    }
}

// ---------------------------------------------------------------------------
extern "C" void kernel_launch(void* const* d_in, const int* in_sizes, int n_in,
                              void* d_out, int out_size)
{
    const float* h   = (const float*)d_in[0];
    const float* inw = (const float*)d_in[1];
    const float* cw  = (const float*)d_in[2];
    const float* cb  = (const float*)d_in[3];
    const float* ow  = (const float*)d_in[4];
    const float* rw1 = (const float*)d_in[5];
    const float* rw2 = (const float*)d_in[6];
    float* out = (float*)d_out;

    void *zxp, *xap, *hhp, *iwp, *owp, *rhp, *cntp, *lstp;
    cudaGetSymbolAddress(&zxp, g_zx);
    cudaGetSymbolAddress(&xap, g_xact);
    cudaGetSymbolAddress(&hhp, g_hh);
    cudaGetSymbolAddress(&iwp, g_inwh);
    cudaGetSymbolAddress(&owp, g_owh);
    cudaGetSymbolAddress(&rhp, g_rh);
    cudaGetSymbolAddress(&cntp, g_cnts2);
    cudaGetSymbolAddress(&lstp, g_lists);
    float*  zx    = (float*)zxp;
    __half* xact  = (__half*)xap;
    __half* hh    = (__half*)hhp;
    __half* inwh  = (__half*)iwp;
    __half* owh   = (__half*)owp;
    float*  rh    = (float*)rhp;
    int*    cnts  = (int*)cntp;
    int*    lists = (int*)lstp;

    cudaFuncSetAttribute(gemm_fp16, cudaFuncAttributeMaxDynamicSharedMemorySize,
                         SMEM_BYTES);

    cudaMemsetAsync(cnts, 0, 16 * sizeof(int));
    cudaMemsetAsync(out, 0, (size_t)NT * Dd * sizeof(float));

    // fp32 -> fp16 converts (MMA operands)
    to_half_pass<<<1024, 256>>>((const float4*)h,   (uint2*)hh,   NT * Dd / 4);
    to_half_pass<<<2048, 256>>>((const float4*)inw, (uint2*)inwh, NE * 2 * DI * Dd / 4);
    to_half_pass<<<2048, 256>>>((const float4*)ow,  (uint2*)owh,  NE * Dd * DI / 4);

    // router, all fp32
    router_l1<<<NT / 64, 256>>>(h, rw1, rh);
    router_finish<<<(NT * 32) / 256, 256>>>(rh, rw2);
    build_xlists<<<dim3(NT / 256, NE), 256>>>();

    // in_proj: 16 jobs (expert e: job 2e = z rows, job 2e+1 = x rows)
    gemm_fp16<<<dim3(DI / BN, NT / BM, 16), 128, SMEM_BYTES>>>(
        hh, inwh, zx, cnts, 0, 1, DI, Dd,
        (size_t)0, (size_t)DI * Dd, (size_t)NT * DI,
        lists, (size_t)NT, nullptr, (size_t)0, 0);

    // conv + gate, batched over experts -> fp16 xact
    conv_act_sparse<<<dim3(1024, NE), 256>>>(cw, cb);

    // out_proj per expert: atomic scatter-accumulate into out
    gemm_fp16<<<dim3(Dd / BN, NT / BM, NE), 128, SMEM_BYTES>>>(
        xact, owh, out, cnts, 0, 2, Dd, DI,
        (size_t)NT * DI, (size_t)Dd * DI, (size_t)0,
        nullptr, (size_t)0, lists, (size_t)(2 * NT), 1);
}

// round 12
// speedup vs baseline: 2.0963x; 1.0573x over previous
#include <cuda_runtime.h>
#include <cuda_fp16.h>
#include <cstdint>
#include <cstddef>

// Problem constants
#define BATCH 4
#define Ss 2048
#define Dd 1024
#define DI 2048          // D_INNER
#define NT (BATCH*Ss)    // 8192 tokens
#define NE 8
#define RHID 128

// FP16 GEMM tile config: 128x128x64 CTA tile, 128 threads (4 warps of 64x64)
#define BM 128
#define BN 128
#define BKH 64                          // K elements per stage (halfs)
#define STRH 72                         // padded smem row stride (halfs) = 144B
#define STAGES 3
#define A_STAGE_HALFS (BM * STRH)
#define STAGE_HALFS ((BM + BN) * STRH)
#define SMEM_BYTES (STAGES * STAGE_HALFS * 2)   // 110,592 B -> 2 CTAs/SM

// Scratch (device globals: allocation-free rule)
__device__ __half g_zx[(size_t)16 * NT * DI];     // in_proj outputs (fp16)
__device__ __half g_xact[(size_t)NE * NT * DI];   // gated act (fp16)
__device__ __half g_hh[(size_t)NT * Dd];          // h in fp16
__device__ __half g_inwh[(size_t)NE * 2 * DI * Dd];
__device__ __half g_owh[(size_t)NE * Dd * DI];
__device__ float  g_rhp[(size_t)2 * NT * RHID];   // router hidden partials (fp32)
__device__ float  g_comb[(size_t)NT * NE];
__device__ int    g_selflag[(size_t)NT * NE];
__device__ int    g_lists[16 * NT];
__device__ int    g_posx[NE * NT];
__device__ int    g_cnts2[16];

__device__ __forceinline__ float silu_(float x) { return x / (1.0f + expf(-x)); }

// ---------------------------------------------------------------------------
// fp32 -> fp16 convert pass (vectorized).
// ---------------------------------------------------------------------------
__global__ void to_half_pass(const float4* __restrict__ src,
                             uint2* __restrict__ dst, int n4)
{
    for (int i = blockIdx.x * blockDim.x + threadIdx.x; i < n4;
         i += gridDim.x * blockDim.x) {
        float4 v = src[i];
        __half2 lo = __floats2half2_rn(v.x, v.y);
        __half2 hi = __floats2half2_rn(v.z, v.w);
        uint2 o;
        o.x = *reinterpret_cast<uint32_t*>(&lo);
        o.y = *reinterpret_cast<uint32_t*>(&hi);
        dst[i] = o;
    }
}

// ---------------------------------------------------------------------------
// Router layer 1, FULL FP32, split-K x2: raw partial sums (no silu here).
// grid (NT/64, 2); blockIdx.y selects K half. Partials added (fixed order)
// in router_finish before silu -> bit-deterministic.
// ---------------------------------------------------------------------------
__global__ __launch_bounds__(256) void router_l1(const float* __restrict__ h,
                                                 const float* __restrict__ w1,
                                                 float* __restrict__ rhp)
{
    __shared__ float As[64][33];
    __shared__ float Ws[128][33];

    const int tid = threadIdx.x;
    const int t0 = blockIdx.x * 64;
    const int kbase = blockIdx.y * (Dd / 2);
    float* rh = rhp + (size_t)blockIdx.y * NT * RHID;
    const int ty = tid >> 4;
    const int tx = tid & 15;

    float acc[4][8];
#pragma unroll
    for (int i = 0; i < 4; ++i)
#pragma unroll
        for (int j = 0; j < 8; ++j) acc[i][j] = 0.f;

    const int arow = tid >> 2, acol = (tid & 3) * 8;
    const int wrow = tid >> 1, wcol = (tid & 1) * 16;

    for (int k0 = kbase; k0 < kbase + Dd / 2; k0 += 32) {
        float4 a0 = *(const float4*)&h[(size_t)(t0 + arow) * Dd + k0 + acol];
        float4 a1 = *(const float4*)&h[(size_t)(t0 + arow) * Dd + k0 + acol + 4];
        As[arow][acol + 0] = a0.x; As[arow][acol + 1] = a0.y;
        As[arow][acol + 2] = a0.z; As[arow][acol + 3] = a0.w;
        As[arow][acol + 4] = a1.x; As[arow][acol + 5] = a1.y;
        As[arow][acol + 6] = a1.z; As[arow][acol + 7] = a1.w;
#pragma unroll
        for (int q = 0; q < 4; ++q) {
            float4 w = *(const float4*)&w1[(size_t)wrow * Dd + k0 + wcol + q * 4];
            Ws[wrow][wcol + q * 4 + 0] = w.x; Ws[wrow][wcol + q * 4 + 1] = w.y;
            Ws[wrow][wcol + q * 4 + 2] = w.z; Ws[wrow][wcol + q * 4 + 3] = w.w;
        }
        __syncthreads();

#pragma unroll 8
        for (int k = 0; k < 32; ++k) {
            float a[4], b[8];
#pragma unroll
            for (int i = 0; i < 4; ++i) a[i] = As[ty * 4 + i][k];
#pragma unroll
            for (int j = 0; j < 8; ++j) b[j] = Ws[tx * 8 + j][k];
#pragma unroll
            for (int i = 0; i < 4; ++i)
#pragma unroll
                for (int j = 0; j < 8; ++j) acc[i][j] += a[i] * b[j];
        }
        __syncthreads();
    }

#pragma unroll
    for (int i = 0; i < 4; ++i) {
        int t = t0 + ty * 4 + i;
#pragma unroll
        for (int j = 0; j < 8; ++j)
            rh[(size_t)t * RHID + tx * 8 + j] = acc[i][j];
    }
}

// ---------------------------------------------------------------------------
// Router finish (fp32): rh = silu(p0 + p1), logits, top-2 softmax, lists.
// ---------------------------------------------------------------------------
__global__ void router_finish(const float* __restrict__ rhp,
                              const float* __restrict__ w2)
{
    int t = (blockIdx.x * blockDim.x + threadIdx.x) >> 5;
    int lane = threadIdx.x & 31;
    if (t >= NT) return;

    const float* r0 = rhp + (size_t)t * RHID;
    const float* r1 = rhp + (size_t)NT * RHID + (size_t)t * RHID;
    float v0 = silu_(r0[lane]       + r1[lane]);
    float v1 = silu_(r0[lane + 32]  + r1[lane + 32]);
    float v2 = silu_(r0[lane + 64]  + r1[lane + 64]);
    float v3 = silu_(r0[lane + 96]  + r1[lane + 96]);

    float lg[NE];
#pragma unroll
    for (int e = 0; e < NE; ++e) {
        const float* w = w2 + e * RHID;
        float p = v0 * w[lane] + v1 * w[lane + 32] + v2 * w[lane + 64] + v3 * w[lane + 96];
#pragma unroll
        for (int o = 16; o; o >>= 1) p += __shfl_xor_sync(0xffffffffu, p, o);
        lg[e] = p;
    }

    if (lane == 0) {
        int i1 = 0; float l1 = lg[0];
#pragma unroll
        for (int e = 1; e < NE; ++e) if (lg[e] > l1) { l1 = lg[e]; i1 = e; }
        int i2 = -1; float l2 = -1e30f;
#pragma unroll
        for (int e = 0; e < NE; ++e) { if (e == i1) continue; if (lg[e] > l2) { l2 = lg[e]; i2 = e; } }
        float wtop = 1.f / (1.f + expf(l2 - l1));
        float* cb = &g_comb[(size_t)t * NE];
        int* sf = &g_selflag[(size_t)t * NE];
#pragma unroll
        for (int e = 0; e < NE; ++e) { cb[e] = 0.f; sf[e] = 0; }
        cb[i1] = wtop;       sf[i1] = 1;
        cb[i2] = 1.f - wtop; sf[i2] = 1;
        int q1 = atomicAdd(&g_cnts2[2 * i1], 1); g_lists[(2 * i1) * NT + q1] = t;
        int q2 = atomicAdd(&g_cnts2[2 * i2], 1); g_lists[(2 * i2) * NT + q2] = t;
    }
}

// ---------------------------------------------------------------------------
// Conv-input (dilated) token lists.
// ---------------------------------------------------------------------------
__global__ void build_xlists()
{
    int t = blockIdx.x * blockDim.x + threadIdx.x;
    int e = blockIdx.y;
    if (t >= NT) return;
    int b = t >> 11, s = t & (Ss - 1);
    bool need = false;
#pragma unroll
    for (int j = 0; j < 4; ++j) {
        int sj = s + j;
        if (sj < Ss) need |= (g_selflag[(size_t)(b * Ss + sj) * NE + e] != 0);
    }
    if (need) {
        int p = atomicAdd(&g_cnts2[2 * e + 1], 1);
        g_lists[(2 * e + 1) * NT + p] = t;
        g_posx[e * NT + t] = p;
    }
}

// ---------------------------------------------------------------------------
// FP16 GEMM (TN), batched over blockIdx.z: C[M,N] op= A[M,K] * W[N,K]^T.
// 128x128x64 CTA tile, 128 threads = 4 warps of 64x64 (2m x 2n).
// mma.m16n8k16.f32.f16.f16.f32, fp32 accumulate. 3-stage cp.async ring,
// 110.6KB smem -> 2 CTAs/SM.
// mode 0: store fp16 to C rows (C is __half*).
// mode 1: atomicAdd fp32 into C row c_idx[m] (C is float*).
// ---------------------------------------------------------------------------
__global__ __launch_bounds__(128, 2) void gemm_fp16(
    const __half* __restrict__ A, const __half* __restrict__ W,
    void* __restrict__ Cv,
    const int* __restrict__ cnts, int mBase, int mStride,
    int N, int K,
    size_t aStrideZ, size_t wStrideZ, size_t cStrideZ,
    const int* __restrict__ a_idx, size_t aIdxStrideZ,
    const int* __restrict__ c_idx, size_t cIdxStrideZ,
    int mode)
{
    const int z = blockIdx.z;
    const int M = cnts[mBase + z * mStride];
    if ((int)blockIdx.y * BM >= M) return;

    A += (size_t)z * aStrideZ;
    W += (size_t)z * wStrideZ;
    const int* aidx = a_idx ? a_idx + (size_t)z * aIdxStrideZ : nullptr;
    const int* cidx = c_idx ? c_idx + (size_t)z * cIdxStrideZ : nullptr;

    extern __shared__ __half smem[];

    const int tid  = threadIdx.x;
    const int lane = tid & 31;
    const int warp = tid >> 5;
    const int g  = lane >> 2;
    const int tg = lane & 3;
    const int wm = (warp & 1) * 64;      // 0,64
    const int wn = (warp >> 1) * 64;     // 0,64

    // Loader: 16B chunks (8 halfs); row = 64 halfs = 8 chunks.
    const int r0    = tid >> 3;          // 0..15
    const int roffH = (tid & 7) * 8;     // half offset in row

    int arowidx[8];
#pragma unroll
    for (int j = 0; j < 8; ++j) {
        int gr = blockIdx.y * BM + r0 + 16 * j;
        int cr = min(gr, M - 1);
        arowidx[j] = aidx ? aidx[cr] : cr;
    }
    const __half* bbase = W + (size_t)(blockIdx.x * BN + r0) * K + roffH;

    const uint32_t saB = (uint32_t)__cvta_generic_to_shared(&smem[r0 * STRH + roffH]);
    const uint32_t sbB = (uint32_t)__cvta_generic_to_shared(
        &smem[A_STAGE_HALFS + r0 * STRH + roffH]);
    const uint32_t stagestep = (uint32_t)(STAGE_HALFS * sizeof(__half));
    const uint32_t rowskip = (uint32_t)(16 * STRH * sizeof(__half));

    float cc[4][8][4];
#pragma unroll
    for (int i = 0; i < 4; ++i)
#pragma unroll
        for (int j = 0; j < 8; ++j)
#pragma unroll
            for (int r = 0; r < 4; ++r) cc[i][j][r] = 0.f;

    const int nk = K / BKH;

    auto load_stage = [&](int s, int kc) {
        const int k0 = kc * BKH;
        const uint32_t so = s * stagestep;
#pragma unroll
        for (int j = 0; j < 8; ++j) {
            const __half* src = A + (size_t)arowidx[j] * K + roffH + k0;
            asm volatile("cp.async.cg.shared.global [%0], [%1], 16;\n"
                         :: "r"(saB + so + j * rowskip), "l"(src) : "memory");
        }
#pragma unroll
        for (int j = 0; j < 8; ++j)
            asm volatile("cp.async.cg.shared.global [%0], [%1], 16;\n"
                         :: "r"(sbB + so + j * rowskip),
                            "l"(bbase + (size_t)16 * j * K + k0) : "memory");
        asm volatile("cp.async.commit_group;\n" ::: "memory");
    };

    load_stage(0, 0);
    load_stage(1, 1);

    int buf = 0;
    for (int kc = 0; kc < nk; ++kc) {
        asm volatile("cp.async.wait_group 1;\n" ::: "memory");
        __syncthreads();
        if (kc + 2 < nk) {
            int nb = buf + 2; if (nb >= STAGES) nb -= STAGES;
            load_stage(nb, kc + 2);
        } else {
            asm volatile("cp.async.commit_group;\n" ::: "memory");
        }

        const __half* Ash = smem + buf * STAGE_HALFS;
        const __half* Bsh = Ash + A_STAGE_HALFS;

#pragma unroll
        for (int kk = 0; kk < BKH; kk += 16) {
            uint32_t a[4][4], b[8][2];
#pragma unroll
            for (int mi = 0; mi < 4; ++mi) {
                int r = wm + mi * 16 + g;
                a[mi][0] = *(const uint32_t*)&Ash[(r    ) * STRH + kk + 2 * tg    ];
                a[mi][1] = *(const uint32_t*)&Ash[(r + 8) * STRH + kk + 2 * tg    ];
                a[mi][2] = *(const uint32_t*)&Ash[(r    ) * STRH + kk + 2 * tg + 8];
                a[mi][3] = *(const uint32_t*)&Ash[(r + 8) * STRH + kk + 2 * tg + 8];
            }
#pragma unroll
            for (int ni = 0; ni < 8; ++ni) {
                int r = wn + ni * 8 + g;
                b[ni][0] = *(const uint32_t*)&Bsh[r * STRH + kk + 2 * tg    ];
                b[ni][1] = *(const uint32_t*)&Bsh[r * STRH + kk + 2 * tg + 8];
            }
#pragma unroll
            for (int mi = 0; mi < 4; ++mi)
#pragma unroll
                for (int ni = 0; ni < 8; ++ni)
                    asm volatile(
                        "mma.sync.aligned.m16n8k16.row.col.f32.f16.f16.f32 "
                        "{%0,%1,%2,%3}, {%4,%5,%6,%7}, {%8,%9}, {%0,%1,%2,%3};"
                        : "+f"(cc[mi][ni][0]), "+f"(cc[mi][ni][1]),
                          "+f"(cc[mi][ni][2]), "+f"(cc[mi][ni][3])
                        : "r"(a[mi][0]), "r"(a[mi][1]), "r"(a[mi][2]), "r"(a[mi][3]),
                          "r"(b[ni][0]), "r"(b[ni][1]));
        }
        if (++buf == STAGES) buf = 0;
    }

    if (mode == 0) {
        __half* C = (__half*)Cv + (size_t)z * cStrideZ;
#pragma unroll
        for (int mi = 0; mi < 4; ++mi) {
            int m0 = blockIdx.y * BM + wm + mi * 16 + g;
            int m1 = m0 + 8;
#pragma unroll
            for (int ni = 0; ni < 8; ++ni) {
                int n0 = blockIdx.x * BN + wn + ni * 8 + 2 * tg;
                if (m0 < M) {
                    __half2 v = __floats2half2_rn(cc[mi][ni][0], cc[mi][ni][1]);
                    *reinterpret_cast<__half2*>(C + (size_t)m0 * N + n0) = v;
                }
                if (m1 < M) {
                    __half2 v = __floats2half2_rn(cc[mi][ni][2], cc[mi][ni][3]);
                    *reinterpret_cast<__half2*>(C + (size_t)m1 * N + n0) = v;
                }
            }
        }
    } else {
        float* C = (float*)Cv + (size_t)z * cStrideZ;
#pragma unroll
        for (int mi = 0; mi < 4; ++mi) {
            int m0 = blockIdx.y * BM + wm + mi * 16 + g;
            int m1 = m0 + 8;
#pragma unroll
            for (int ni = 0; ni < 8; ++ni) {
                int n0 = blockIdx.x * BN + wn + ni * 8 + 2 * tg;
                if (m0 < M) {
                    float* p = C + (size_t)cidx[m0] * N + n0;
                    atomicAdd(&p[0], cc[mi][ni][0]);
                    atomicAdd(&p[1], cc[mi][ni][1]);
                }
                if (m1 < M) {
                    float* p = C + (size_t)cidx[m1] * N + n0;
                    atomicAdd(&p[0], cc[mi][ni][2]);
                    atomicAdd(&p[1], cc[mi][ni][3]);
                }
            }
        }
    }
}

// ---------------------------------------------------------------------------
// Sparse fused conv + bias + silu(x)*silu(z)*comb (fp16 in -> fp16 out).
// Compute in fp32.
// ---------------------------------------------------------------------------
__global__ void conv_act_sparse(const float* __restrict__ cw_all,
                                const float* __restrict__ cb_all)
{
    const int e = blockIdx.y;
    const int cnt = g_cnts2[2 * e];
    const int total = cnt * (DI / 4);
    const int* sel = g_lists + (2 * e) * NT;
    const int* posx = g_posx + e * NT;
    const __half* zb = g_zx + (size_t)(2 * e) * NT * DI;
    const __half* xb = g_zx + (size_t)(2 * e + 1) * NT * DI;
    __half* xact = g_xact + (size_t)e * NT * DI;
    const float4* cwf = reinterpret_cast<const float4*>(cw_all + (size_t)e * DI * 4);
    const float4* cbf = reinterpret_cast<const float4*>(cb_all + (size_t)e * DI);

    for (int idx = blockIdx.x * blockDim.x + threadIdx.x; idx < total;
         idx += gridDim.x * blockDim.x) {
        const int i  = idx >> 9;
        const int c4 = idx & 511;
        const int c  = c4 * 4;
        const int t  = sel[i];
        const float wgt = g_comb[(size_t)t * NE + e];
        const int b = t >> 11, s = t & (Ss - 1);

        float4 w0 = cwf[c4 * 4 + 0];
        float4 w1 = cwf[c4 * 4 + 1];
        float4 w2 = cwf[c4 * 4 + 2];
        float4 w3 = cwf[c4 * 4 + 3];
        float4 acc = cbf[c4];

#pragma unroll
        for (int j = 0; j < 4; ++j) {
            int sj = s - 3 + j;
            if (sj < 0) continue;
            int r = posx[b * Ss + sj];
            const uint2 xr = *reinterpret_cast<const uint2*>(xb + (size_t)r * DI + c);
            float2 xlo = __half22float2(*reinterpret_cast<const __half2*>(&xr.x));
            float2 xhi = __half22float2(*reinterpret_cast<const __half2*>(&xr.y));
            float t0 = (j == 0) ? w0.x : (j == 1) ? w0.y : (j == 2) ? w0.z : w0.w;
            float t1 = (j == 0) ? w1.x : (j == 1) ? w1.y : (j == 2) ? w1.z : w1.w;
            float t2 = (j == 0) ? w2.x : (j == 1) ? w2.y : (j == 2) ? w2.z : w2.w;
            float t3 = (j == 0) ? w3.x : (j == 1) ? w3.y : (j == 2) ? w3.z : w3.w;
            acc.x += t0 * xlo.x; acc.y += t1 * xlo.y;
            acc.z += t2 * xhi.x; acc.w += t3 * xhi.y;
        }

        const uint2 zr = *reinterpret_cast<const uint2*>(zb + (size_t)i * DI + c);
        float2 zlo = __half22float2(*reinterpret_cast<const __half2*>(&zr.x));
        float2 zhi = __half22float2(*reinterpret_cast<const __half2*>(&zr.y));
        __half2 lo = __floats2half2_rn(silu_(acc.x) * silu_(zlo.x) * wgt,
                                       silu_(acc.y) * silu_(zlo.y) * wgt);
        __half2 hi = __floats2half2_rn(silu_(acc.z) * silu_(zhi.x) * wgt,
                                       silu_(acc.w) * silu_(zhi.y) * wgt);
        uint2 o;
        o.x = *reinterpret_cast<uint32_t*>(&lo);
        o.y = *reinterpret_cast<uint32_t*>(&hi);
        *reinterpret_cast<uint2*>(xact + (size_t)i * DI + c) = o;
    }
}

// ---------------------------------------------------------------------------
extern "C" void kernel_launch(void* const* d_in, const int* in_sizes, int n_in,
                              void* d_out, int out_size)
{
    const float* h   = (const float*)d_in[0];
    const float* inw = (const float*)d_in[1];
    const float* cw  = (const float*)d_in[2];
    const float* cb  = (const float*)d_in[3];
    const float* ow  = (const float*)d_in[4];
    const float* rw1 = (const float*)d_in[5];
    const float* rw2 = (const float*)d_in[6];
    float* out = (float*)d_out;

    void *zxp, *xap, *hhp, *iwp, *owp, *rhp, *cntp, *lstp;
    cudaGetSymbolAddress(&zxp, g_zx);
    cudaGetSymbolAddress(&xap, g_xact);
    cudaGetSymbolAddress(&hhp, g_hh);
    cudaGetSymbolAddress(&iwp, g_inwh);
    cudaGetSymbolAddress(&owp, g_owh);
    cudaGetSymbolAddress(&rhp, g_rhp);
    cudaGetSymbolAddress(&cntp, g_cnts2);
    cudaGetSymbolAddress(&lstp, g_lists);
    __half* zx    = (__half*)zxp;
    __half* xact  = (__half*)xap;
    __half* hh    = (__half*)hhp;
    __half* inwh  = (__half*)iwp;
    __half* owh   = (__half*)owp;
    float*  rhpf  = (float*)rhp;
    int*    cnts  = (int*)cntp;
    int*    lists = (int*)lstp;

    cudaFuncSetAttribute(gemm_fp16, cudaFuncAttributeMaxDynamicSharedMemorySize,
                         SMEM_BYTES);

    cudaMemsetAsync(cnts, 0, 16 * sizeof(int));
    cudaMemsetAsync(out, 0, (size_t)NT * Dd * sizeof(float));

    // fp32 -> fp16 converts (MMA operands)
    to_half_pass<<<1024, 256>>>((const float4*)h,   (uint2*)hh,   NT * Dd / 4);
    to_half_pass<<<2048, 256>>>((const float4*)inw, (uint2*)inwh, NE * 2 * DI * Dd / 4);
    to_half_pass<<<2048, 256>>>((const float4*)ow,  (uint2*)owh,  NE * Dd * DI / 4);

    // router, all fp32 (split-K x2 for occupancy; deterministic reduce)
    router_l1<<<dim3(NT / 64, 2), 256>>>(h, rw1, rhpf);
    router_finish<<<(NT * 32) / 256, 256>>>(rhpf, rw2);
    build_xlists<<<dim3(NT / 256, NE), 256>>>();

    // in_proj: 16 jobs (expert e: job 2e = z rows, job 2e+1 = x rows), fp16 out
    gemm_fp16<<<dim3(DI / BN, NT / BM, 16), 128, SMEM_BYTES>>>(
        hh, inwh, zx, cnts, 0, 1, DI, Dd,
        (size_t)0, (size_t)DI * Dd, (size_t)NT * DI,
        lists, (size_t)NT, nullptr, (size_t)0, 0);

    // conv + gate, batched over experts (fp16 in/out, fp32 math)
    conv_act_sparse<<<dim3(1024, NE), 256>>>(cw, cb);

    // out_proj per expert: atomic fp32 scatter-accumulate into out
    gemm_fp16<<<dim3(Dd / BN, NT / BM, NE), 128, SMEM_BYTES>>>(
        xact, owh, out, cnts, 0, 2, Dd, DI,
        (size_t)NT * DI, (size_t)Dd * DI, (size_t)0,
        nullptr, (size_t)0, lists, (size_t)(2 * NT), 1);
}

// round 13
// speedup vs baseline: 2.0964x; 1.0000x over previous
#include <cuda_runtime.h>
#include <cuda_fp16.h>
#include <cstdint>
#include <cstddef>

// Problem constants
#define BATCH 4
#define Ss 2048
#define Dd 1024
#define DI 2048          // D_INNER
#define NT (BATCH*Ss)    // 8192 tokens
#define NE 8
#define RHID 128

// FP16 GEMM tile config: 128x128x64 CTA tile, 128 threads (4 warps of 64x64)
#define BM 128
#define BN 128
#define BKH 64                          // K elements per stage (halfs)
#define STRH 72                         // padded smem row stride (halfs) = 144B
#define STAGES 3
#define A_STAGE_HALFS (BM * STRH)
#define STAGE_HALFS ((BM + BN) * STRH)
#define SMEM_BYTES (STAGES * STAGE_HALFS * 2)   // 110,592 B -> 2 CTAs/SM

// Scratch (device globals: allocation-free rule)
__device__ __half g_zx[(size_t)16 * NT * DI];     // in_proj outputs (fp16)
__device__ __half g_xact[(size_t)NE * NT * DI];   // gated act (fp16)
__device__ __half g_hh[(size_t)NT * Dd];          // h in fp16
__device__ __half g_inwh[(size_t)NE * 2 * DI * Dd];
__device__ __half g_owh[(size_t)NE * Dd * DI];
__device__ float  g_rhp[(size_t)2 * NT * RHID];   // router hidden partials (fp32)
__device__ float  g_comb[(size_t)NT * NE];
__device__ int    g_selflag[(size_t)NT * NE];
__device__ int    g_lists[16 * NT];
__device__ int    g_posx[NE * NT];
__device__ int    g_cnts2[16];

__device__ __forceinline__ float silu_(float x) { return x / (1.0f + expf(-x)); }

// ---------------------------------------------------------------------------
// Fused fp32 -> fp16 convert for h, in_proj_w, out_proj_w; zeros cnts.
// ---------------------------------------------------------------------------
__global__ void convert_all(const float4* __restrict__ h,   uint2* __restrict__ hh,   int n1,
                            const float4* __restrict__ inw, uint2* __restrict__ inwh, int n2,
                            const float4* __restrict__ ow,  uint2* __restrict__ owh,  int n3)
{
    if (blockIdx.x == 0 && threadIdx.x < 16) g_cnts2[threadIdx.x] = 0;
    const int stride = gridDim.x * blockDim.x;
    const int t0 = blockIdx.x * blockDim.x + threadIdx.x;
    for (int i = t0; i < n1; i += stride) {
        float4 v = h[i];
        __half2 lo = __floats2half2_rn(v.x, v.y);
        __half2 hi = __floats2half2_rn(v.z, v.w);
        hh[i] = make_uint2(*(uint32_t*)&lo, *(uint32_t*)&hi);
    }
    for (int i = t0; i < n2; i += stride) {
        float4 v = inw[i];
        __half2 lo = __floats2half2_rn(v.x, v.y);
        __half2 hi = __floats2half2_rn(v.z, v.w);
        inwh[i] = make_uint2(*(uint32_t*)&lo, *(uint32_t*)&hi);
    }
    for (int i = t0; i < n3; i += stride) {
        float4 v = ow[i];
        __half2 lo = __floats2half2_rn(v.x, v.y);
        __half2 hi = __floats2half2_rn(v.z, v.w);
        owh[i] = make_uint2(*(uint32_t*)&lo, *(uint32_t*)&hi);
    }
}

// ---------------------------------------------------------------------------
// Router layer 1, FULL FP32, split-K x2: raw partial sums (no silu here).
// ---------------------------------------------------------------------------
__global__ __launch_bounds__(256) void router_l1(const float* __restrict__ h,
                                                 const float* __restrict__ w1,
                                                 float* __restrict__ rhp)
{
    __shared__ float As[64][33];
    __shared__ float Ws[128][33];

    const int tid = threadIdx.x;
    const int t0 = blockIdx.x * 64;
    const int kbase = blockIdx.y * (Dd / 2);
    float* rh = rhp + (size_t)blockIdx.y * NT * RHID;
    const int ty = tid >> 4;
    const int tx = tid & 15;

    float acc[4][8];
#pragma unroll
    for (int i = 0; i < 4; ++i)
#pragma unroll
        for (int j = 0; j < 8; ++j) acc[i][j] = 0.f;

    const int arow = tid >> 2, acol = (tid & 3) * 8;
    const int wrow = tid >> 1, wcol = (tid & 1) * 16;

    for (int k0 = kbase; k0 < kbase + Dd / 2; k0 += 32) {
        float4 a0 = *(const float4*)&h[(size_t)(t0 + arow) * Dd + k0 + acol];
        float4 a1 = *(const float4*)&h[(size_t)(t0 + arow) * Dd + k0 + acol + 4];
        As[arow][acol + 0] = a0.x; As[arow][acol + 1] = a0.y;
        As[arow][acol + 2] = a0.z; As[arow][acol + 3] = a0.w;
        As[arow][acol + 4] = a1.x; As[arow][acol + 5] = a1.y;
        As[arow][acol + 6] = a1.z; As[arow][acol + 7] = a1.w;
#pragma unroll
        for (int q = 0; q < 4; ++q) {
            float4 w = *(const float4*)&w1[(size_t)wrow * Dd + k0 + wcol + q * 4];
            Ws[wrow][wcol + q * 4 + 0] = w.x; Ws[wrow][wcol + q * 4 + 1] = w.y;
            Ws[wrow][wcol + q * 4 + 2] = w.z; Ws[wrow][wcol + q * 4 + 3] = w.w;
        }
        __syncthreads();

#pragma unroll 8
        for (int k = 0; k < 32; ++k) {
            float a[4], b[8];
#pragma unroll
            for (int i = 0; i < 4; ++i) a[i] = As[ty * 4 + i][k];
#pragma unroll
            for (int j = 0; j < 8; ++j) b[j] = Ws[tx * 8 + j][k];
#pragma unroll
            for (int i = 0; i < 4; ++i)
#pragma unroll
                for (int j = 0; j < 8; ++j) acc[i][j] += a[i] * b[j];
        }
        __syncthreads();
    }

#pragma unroll
    for (int i = 0; i < 4; ++i) {
        int t = t0 + ty * 4 + i;
#pragma unroll
        for (int j = 0; j < 8; ++j)
            rh[(size_t)t * RHID + tx * 8 + j] = acc[i][j];
    }
}

// ---------------------------------------------------------------------------
// Router finish (fp32): rh = silu(p0 + p1), logits, top-2 softmax, lists.
// ---------------------------------------------------------------------------
__global__ void router_finish(const float* __restrict__ rhp,
                              const float* __restrict__ w2)
{
    int t = (blockIdx.x * blockDim.x + threadIdx.x) >> 5;
    int lane = threadIdx.x & 31;
    if (t >= NT) return;

    const float* r0 = rhp + (size_t)t * RHID;
    const float* r1 = rhp + (size_t)NT * RHID + (size_t)t * RHID;
    float v0 = silu_(r0[lane]       + r1[lane]);
    float v1 = silu_(r0[lane + 32]  + r1[lane + 32]);
    float v2 = silu_(r0[lane + 64]  + r1[lane + 64]);
    float v3 = silu_(r0[lane + 96]  + r1[lane + 96]);

    float lg[NE];
#pragma unroll
    for (int e = 0; e < NE; ++e) {
        const float* w = w2 + e * RHID;
        float p = v0 * w[lane] + v1 * w[lane + 32] + v2 * w[lane + 64] + v3 * w[lane + 96];
#pragma unroll
        for (int o = 16; o; o >>= 1) p += __shfl_xor_sync(0xffffffffu, p, o);
        lg[e] = p;
    }

    if (lane == 0) {
        int i1 = 0; float l1 = lg[0];
#pragma unroll
        for (int e = 1; e < NE; ++e) if (lg[e] > l1) { l1 = lg[e]; i1 = e; }
        int i2 = -1; float l2 = -1e30f;
#pragma unroll
        for (int e = 0; e < NE; ++e) { if (e == i1) continue; if (lg[e] > l2) { l2 = lg[e]; i2 = e; } }
        float wtop = 1.f / (1.f + expf(l2 - l1));
        float* cb = &g_comb[(size_t)t * NE];
        int* sf = &g_selflag[(size_t)t * NE];
#pragma unroll
        for (int e = 0; e < NE; ++e) { cb[e] = 0.f; sf[e] = 0; }
        cb[i1] = wtop;       sf[i1] = 1;
        cb[i2] = 1.f - wtop; sf[i2] = 1;
        int q1 = atomicAdd(&g_cnts2[2 * i1], 1); g_lists[(2 * i1) * NT + q1] = t;
        int q2 = atomicAdd(&g_cnts2[2 * i2], 1); g_lists[(2 * i2) * NT + q2] = t;
    }
}

// ---------------------------------------------------------------------------
// Conv-input (dilated) token lists.
// ---------------------------------------------------------------------------
__global__ void build_xlists()
{
    int t = blockIdx.x * blockDim.x + threadIdx.x;
    int e = blockIdx.y;
    if (t >= NT) return;
    int b = t >> 11, s = t & (Ss - 1);
    bool need = false;
#pragma unroll
    for (int j = 0; j < 4; ++j) {
        int sj = s + j;
        if (sj < Ss) need |= (g_selflag[(size_t)(b * Ss + sj) * NE + e] != 0);
    }
    if (need) {
        int p = atomicAdd(&g_cnts2[2 * e + 1], 1);
        g_lists[(2 * e + 1) * NT + p] = t;
        g_posx[e * NT + t] = p;
    }
}

// ---------------------------------------------------------------------------
// FP16 GEMM (TN), batched over blockIdx.z: C[M,N] op= A[M,K] * W[N,K]^T.
// 128x128x64 CTA tile, 128 threads = 4 warps of 64x64 (2m x 2n).
// mma.m16n8k16.f32.f16.f16.f32, fp32 accumulate. 3-stage cp.async ring,
// ping-pong register fragment double-buffering inside each stage.
// mode 0: store fp16 rows. mode 1: atomicAdd fp32 into c_idx rows.
// ---------------------------------------------------------------------------
__global__ __launch_bounds__(128, 2) void gemm_fp16(
    const __half* __restrict__ A, const __half* __restrict__ W,
    void* __restrict__ Cv,
    const int* __restrict__ cnts, int mBase, int mStride,
    int N, int K,
    size_t aStrideZ, size_t wStrideZ, size_t cStrideZ,
    const int* __restrict__ a_idx, size_t aIdxStrideZ,
    const int* __restrict__ c_idx, size_t cIdxStrideZ,
    int mode)
{
    const int z = blockIdx.z;
    const int M = cnts[mBase + z * mStride];
    if ((int)blockIdx.y * BM >= M) return;

    A += (size_t)z * aStrideZ;
    W += (size_t)z * wStrideZ;
    const int* aidx = a_idx ? a_idx + (size_t)z * aIdxStrideZ : nullptr;
    const int* cidx = c_idx ? c_idx + (size_t)z * cIdxStrideZ : nullptr;

    extern __shared__ __half smem[];

    const int tid  = threadIdx.x;
    const int lane = tid & 31;
    const int warp = tid >> 5;
    const int g  = lane >> 2;
    const int tg = lane & 3;
    const int wm = (warp & 1) * 64;      // 0,64
    const int wn = (warp >> 1) * 64;     // 0,64

    // Loader: 16B chunks (8 halfs); row = 64 halfs = 8 chunks.
    const int r0    = tid >> 3;          // 0..15
    const int roffH = (tid & 7) * 8;     // half offset in row

    int arowidx[8];
#pragma unroll
    for (int j = 0; j < 8; ++j) {
        int gr = blockIdx.y * BM + r0 + 16 * j;
        int cr = min(gr, M - 1);
        arowidx[j] = aidx ? aidx[cr] : cr;
    }
    const __half* bbase = W + (size_t)(blockIdx.x * BN + r0) * K + roffH;

    const uint32_t saB = (uint32_t)__cvta_generic_to_shared(&smem[r0 * STRH + roffH]);
    const uint32_t sbB = (uint32_t)__cvta_generic_to_shared(
        &smem[A_STAGE_HALFS + r0 * STRH + roffH]);
    const uint32_t stagestep = (uint32_t)(STAGE_HALFS * sizeof(__half));
    const uint32_t rowskip = (uint32_t)(16 * STRH * sizeof(__half));

    float cc[4][8][4];
#pragma unroll
    for (int i = 0; i < 4; ++i)
#pragma unroll
        for (int j = 0; j < 8; ++j)
#pragma unroll
            for (int r = 0; r < 4; ++r) cc[i][j][r] = 0.f;

    const int nk = K / BKH;

    auto load_stage = [&](int s, int kc) {
        const int k0 = kc * BKH;
        const uint32_t so = s * stagestep;
#pragma unroll
        for (int j = 0; j < 8; ++j) {
            const __half* src = A + (size_t)arowidx[j] * K + roffH + k0;
            asm volatile("cp.async.cg.shared.global [%0], [%1], 16;\n"
                         :: "r"(saB + so + j * rowskip), "l"(src) : "memory");
        }
#pragma unroll
        for (int j = 0; j < 8; ++j)
            asm volatile("cp.async.cg.shared.global [%0], [%1], 16;\n"
                         :: "r"(sbB + so + j * rowskip),
                            "l"(bbase + (size_t)16 * j * K + k0) : "memory");
        asm volatile("cp.async.commit_group;\n" ::: "memory");
    };

    load_stage(0, 0);
    load_stage(1, 1);

    uint32_t af[2][4][4], bf[2][8][2];

    int buf = 0;
    for (int kc = 0; kc < nk; ++kc) {
        asm volatile("cp.async.wait_group 1;\n" ::: "memory");
        __syncthreads();
        if (kc + 2 < nk) {
            int nb = buf + 2; if (nb >= STAGES) nb -= STAGES;
            load_stage(nb, kc + 2);
        } else {
            asm volatile("cp.async.commit_group;\n" ::: "memory");
        }

        const __half* Ash = smem + buf * STAGE_HALFS;
        const __half* Bsh = Ash + A_STAGE_HALFS;

        // load fragments for k16-step 0
#pragma unroll
        for (int mi = 0; mi < 4; ++mi) {
            int r = wm + mi * 16 + g;
            af[0][mi][0] = *(const uint32_t*)&Ash[(r    ) * STRH + 2 * tg    ];
            af[0][mi][1] = *(const uint32_t*)&Ash[(r + 8) * STRH + 2 * tg    ];
            af[0][mi][2] = *(const uint32_t*)&Ash[(r    ) * STRH + 2 * tg + 8];
            af[0][mi][3] = *(const uint32_t*)&Ash[(r + 8) * STRH + 2 * tg + 8];
        }
#pragma unroll
        for (int ni = 0; ni < 8; ++ni) {
            int r = wn + ni * 8 + g;
            bf[0][ni][0] = *(const uint32_t*)&Bsh[r * STRH + 2 * tg    ];
            bf[0][ni][1] = *(const uint32_t*)&Bsh[r * STRH + 2 * tg + 8];
        }

#pragma unroll
        for (int s = 0; s < 4; ++s) {
            const int cur = s & 1, nxt = cur ^ 1;
            if (s < 3) {
                const int kk = (s + 1) * 16;
#pragma unroll
                for (int mi = 0; mi < 4; ++mi) {
                    int r = wm + mi * 16 + g;
                    af[nxt][mi][0] = *(const uint32_t*)&Ash[(r    ) * STRH + kk + 2 * tg    ];
                    af[nxt][mi][1] = *(const uint32_t*)&Ash[(r + 8) * STRH + kk + 2 * tg    ];
                    af[nxt][mi][2] = *(const uint32_t*)&Ash[(r    ) * STRH + kk + 2 * tg + 8];
                    af[nxt][mi][3] = *(const uint32_t*)&Ash[(r + 8) * STRH + kk + 2 * tg + 8];
                }
#pragma unroll
                for (int ni = 0; ni < 8; ++ni) {
                    int r = wn + ni * 8 + g;
                    bf[nxt][ni][0] = *(const uint32_t*)&Bsh[r * STRH + kk + 2 * tg    ];
                    bf[nxt][ni][1] = *(const uint32_t*)&Bsh[r * STRH + kk + 2 * tg + 8];
                }
            }
#pragma unroll
            for (int mi = 0; mi < 4; ++mi)
#pragma unroll
                for (int ni = 0; ni < 8; ++ni)
                    asm volatile(
                        "mma.sync.aligned.m16n8k16.row.col.f32.f16.f16.f32 "
                        "{%0,%1,%2,%3}, {%4,%5,%6,%7}, {%8,%9}, {%0,%1,%2,%3};"
                        : "+f"(cc[mi][ni][0]), "+f"(cc[mi][ni][1]),
                          "+f"(cc[mi][ni][2]), "+f"(cc[mi][ni][3])
                        : "r"(af[cur][mi][0]), "r"(af[cur][mi][1]),
                          "r"(af[cur][mi][2]), "r"(af[cur][mi][3]),
                          "r"(bf[cur][ni][0]), "r"(bf[cur][ni][1]));
        }
        if (++buf == STAGES) buf = 0;
    }

    if (mode == 0) {
        __half* C = (__half*)Cv + (size_t)z * cStrideZ;
#pragma unroll
        for (int mi = 0; mi < 4; ++mi) {
            int m0 = blockIdx.y * BM + wm + mi * 16 + g;
            int m1 = m0 + 8;
#pragma unroll
            for (int ni = 0; ni < 8; ++ni) {
                int n0 = blockIdx.x * BN + wn + ni * 8 + 2 * tg;
                if (m0 < M) {
                    __half2 v = __floats2half2_rn(cc[mi][ni][0], cc[mi][ni][1]);
                    *reinterpret_cast<__half2*>(C + (size_t)m0 * N + n0) = v;
                }
                if (m1 < M) {
                    __half2 v = __floats2half2_rn(cc[mi][ni][2], cc[mi][ni][3]);
                    *reinterpret_cast<__half2*>(C + (size_t)m1 * N + n0) = v;
                }
            }
        }
    } else {
        float* C = (float*)Cv + (size_t)z * cStrideZ;
#pragma unroll
        for (int mi = 0; mi < 4; ++mi) {
            int m0 = blockIdx.y * BM + wm + mi * 16 + g;
            int m1 = m0 + 8;
#pragma unroll
            for (int ni = 0; ni < 8; ++ni) {
                int n0 = blockIdx.x * BN + wn + ni * 8 + 2 * tg;
                if (m0 < M) {
                    float* p = C + (size_t)cidx[m0] * N + n0;
                    atomicAdd(&p[0], cc[mi][ni][0]);
                    atomicAdd(&p[1], cc[mi][ni][1]);
                }
                if (m1 < M) {
                    float* p = C + (size_t)cidx[m1] * N + n0;
                    atomicAdd(&p[0], cc[mi][ni][2]);
                    atomicAdd(&p[1], cc[mi][ni][3]);
                }
            }
        }
    }
}

// ---------------------------------------------------------------------------
// Sparse fused conv + bias + silu(x)*silu(z)*comb (fp16 in -> fp16 out).
// ---------------------------------------------------------------------------
__global__ void conv_act_sparse(const float* __restrict__ cw_all,
                                const float* __restrict__ cb_all)
{
    const int e = blockIdx.y;
    const int cnt = g_cnts2[2 * e];
    const int total = cnt * (DI / 4);
    const int* sel = g_lists + (2 * e) * NT;
    const int* posx = g_posx + e * NT;
    const __half* zb = g_zx + (size_t)(2 * e) * NT * DI;
    const __half* xb = g_zx + (size_t)(2 * e + 1) * NT * DI;
    __half* xact = g_xact + (size_t)e * NT * DI;
    const float4* cwf = reinterpret_cast<const float4*>(cw_all + (size_t)e * DI * 4);
    const float4* cbf = reinterpret_cast<const float4*>(cb_all + (size_t)e * DI);

    for (int idx = blockIdx.x * blockDim.x + threadIdx.x; idx < total;
         idx += gridDim.x * blockDim.x) {
        const int i  = idx >> 9;
        const int c4 = idx & 511;
        const int c  = c4 * 4;
        const int t  = sel[i];
        const float wgt = g_comb[(size_t)t * NE + e];
        const int b = t >> 11, s = t & (Ss - 1);

        float4 w0 = cwf[c4 * 4 + 0];
        float4 w1 = cwf[c4 * 4 + 1];
        float4 w2 = cwf[c4 * 4 + 2];
        float4 w3 = cwf[c4 * 4 + 3];
        float4 acc = cbf[c4];

#pragma unroll
        for (int j = 0; j < 4; ++j) {
            int sj = s - 3 + j;
            if (sj < 0) continue;
            int r = posx[b * Ss + sj];
            const uint2 xr = *reinterpret_cast<const uint2*>(xb + (size_t)r * DI + c);
            float2 xlo = __half22float2(*reinterpret_cast<const __half2*>(&xr.x));
            float2 xhi = __half22float2(*reinterpret_cast<const __half2*>(&xr.y));
            float t0 = (j == 0) ? w0.x : (j == 1) ? w0.y : (j == 2) ? w0.z : w0.w;
            float t1 = (j == 0) ? w1.x : (j == 1) ? w1.y : (j == 2) ? w1.z : w1.w;
            float t2 = (j == 0) ? w2.x : (j == 1) ? w2.y : (j == 2) ? w2.z : w2.w;
            float t3 = (j == 0) ? w3.x : (j == 1) ? w3.y : (j == 2) ? w3.z : w3.w;
            acc.x += t0 * xlo.x; acc.y += t1 * xlo.y;
            acc.z += t2 * xhi.x; acc.w += t3 * xhi.y;
        }

        const uint2 zr = *reinterpret_cast<const uint2*>(zb + (size_t)i * DI + c);
        float2 zlo = __half22float2(*reinterpret_cast<const __half2*>(&zr.x));
        float2 zhi = __half22float2(*reinterpret_cast<const __half2*>(&zr.y));
        __half2 lo = __floats2half2_rn(silu_(acc.x) * silu_(zlo.x) * wgt,
                                       silu_(acc.y) * silu_(zlo.y) * wgt);
        __half2 hi = __floats2half2_rn(silu_(acc.z) * silu_(zhi.x) * wgt,
                                       silu_(acc.w) * silu_(zhi.y) * wgt);
        uint2 o;
        o.x = *reinterpret_cast<uint32_t*>(&lo);
        o.y = *reinterpret_cast<uint32_t*>(&hi);
        *reinterpret_cast<uint2*>(xact + (size_t)i * DI + c) = o;
    }
}

// ---------------------------------------------------------------------------
extern "C" void kernel_launch(void* const* d_in, const int* in_sizes, int n_in,
                              void* d_out, int out_size)
{
    const float* h   = (const float*)d_in[0];
    const float* inw = (const float*)d_in[1];
    const float* cw  = (const float*)d_in[2];
    const float* cb  = (const float*)d_in[3];
    const float* ow  = (const float*)d_in[4];
    const float* rw1 = (const float*)d_in[5];
    const float* rw2 = (const float*)d_in[6];
    float* out = (float*)d_out;

    void *zxp, *xap, *hhp, *iwp, *owp, *rhp, *cntp, *lstp;
    cudaGetSymbolAddress(&zxp, g_zx);
    cudaGetSymbolAddress(&xap, g_xact);
    cudaGetSymbolAddress(&hhp, g_hh);
    cudaGetSymbolAddress(&iwp, g_inwh);
    cudaGetSymbolAddress(&owp, g_owh);
    cudaGetSymbolAddress(&rhp, g_rhp);
    cudaGetSymbolAddress(&cntp, g_cnts2);
    cudaGetSymbolAddress(&lstp, g_lists);
    __half* zx    = (__half*)zxp;
    __half* xact  = (__half*)xap;
    __half* hh    = (__half*)hhp;
    __half* inwh  = (__half*)iwp;
    __half* owh   = (__half*)owp;
    float*  rhpf  = (float*)rhp;
    int*    cnts  = (int*)cntp;
    int*    lists = (int*)lstp;

    cudaFuncSetAttribute(gemm_fp16, cudaFuncAttributeMaxDynamicSharedMemorySize,
                         SMEM_BYTES);

    // 1: fused converts (+cnts zero)
    convert_all<<<2048, 256>>>((const float4*)h,   (uint2*)hh,   NT * Dd / 4,
                               (const float4*)inw, (uint2*)inwh, NE * 2 * DI * Dd / 4,
                               (const float4*)ow,  (uint2*)owh,  NE * Dd * DI / 4);
    // 2: router layer 1 (fp32, split-K x2)
    router_l1<<<dim3(NT / 64, 2), 256>>>(h, rw1, rhpf);
    // 3: router finish (lists for z-jobs ready after this)
    router_finish<<<(NT * 32) / 256, 256>>>(rhpf, rw2);

    // 4: in_proj z-jobs (8) -- this is the kernel ncu profiles
    gemm_fp16<<<dim3(DI / BN, NT / BM, NE), 128, SMEM_BYTES>>>(
        hh, inwh, zx, cnts, 0, 2, DI, Dd,
        (size_t)0, (size_t)2 * DI * Dd, (size_t)2 * NT * DI,
        lists, (size_t)2 * NT, nullptr, (size_t)0, 0);

    // 5: conv-input lists
    build_xlists<<<dim3(NT / 256, NE), 256>>>();

    // 6: in_proj x-jobs (8)
    gemm_fp16<<<dim3(DI / BN, NT / BM, NE), 128, SMEM_BYTES>>>(
        hh, inwh + (size_t)DI * Dd, zx + (size_t)NT * DI, cnts, 1, 2, DI, Dd,
        (size_t)0, (size_t)2 * DI * Dd, (size_t)2 * NT * DI,
        lists + NT, (size_t)2 * NT, nullptr, (size_t)0, 0);

    // out zeroing (needed before out_proj only)
    cudaMemsetAsync(out, 0, (size_t)NT * Dd * sizeof(float));

    // conv + gate
    conv_act_sparse<<<dim3(1024, NE), 256>>>(cw, cb);

    // out_proj per expert: atomic fp32 scatter-accumulate into out
    gemm_fp16<<<dim3(Dd / BN, NT / BM, NE), 128, SMEM_BYTES>>>(
        xact, owh, out, cnts, 0, 2, Dd, DI,
        (size_t)NT * DI, (size_t)Dd * DI, (size_t)0,
        nullptr, (size_t)0, lists, (size_t)2 * NT, 1);
}

// round 14
// speedup vs baseline: 2.1231x; 1.0128x over previous
#include <cuda_runtime.h>
#include <cuda_fp16.h>
#include <cstdint>
#include <cstddef>

// Problem constants
#define BATCH 4
#define Ss 2048
#define Dd 1024
#define DI 2048          // D_INNER
#define NT (BATCH*Ss)    // 8192 tokens
#define NE 8
#define RHID 128

// FP16 GEMM tile config: 128x128x64 CTA tile, 128 threads (4 warps of 64x64)
#define BM 128
#define BN 128
#define BKH 64                          // K elements per stage (halfs)
#define STRH 72                         // padded smem row stride (halfs) = 144B
#define STAGES 3
#define A_STAGE_HALFS (BM * STRH)
#define STAGE_HALFS ((BM + BN) * STRH)
#define SMEM_BYTES (STAGES * STAGE_HALFS * 2)   // 110,592 B -> 2 CTAs/SM

// Scratch (device globals: allocation-free rule)
__device__ __half g_zx[(size_t)16 * NT * DI];     // in_proj outputs (fp16)
__device__ __half g_xact[(size_t)NE * NT * DI];   // gated act (fp16)
__device__ __half g_hh[(size_t)NT * Dd];          // h in fp16
__device__ __half g_inwh[(size_t)NE * 2 * DI * Dd];
__device__ __half g_owh[(size_t)NE * Dd * DI];
__device__ float  g_rhp[(size_t)2 * NT * RHID];   // router hidden partials (fp32)
__device__ float  g_comb[(size_t)NT * NE];
__device__ int    g_selflag[(size_t)NT * NE];
__device__ int    g_lists[16 * NT];
__device__ int    g_posx[NE * NT];
__device__ int    g_cnts2[16];

__device__ __forceinline__ float silu_(float x) { return x / (1.0f + expf(-x)); }

// ---------------------------------------------------------------------------
// Fused fp32 -> fp16 convert for h, in_proj_w, out_proj_w; zeros cnts.
// ---------------------------------------------------------------------------
__global__ void convert_all(const float4* __restrict__ h,   uint2* __restrict__ hh,   int n1,
                            const float4* __restrict__ inw, uint2* __restrict__ inwh, int n2,
                            const float4* __restrict__ ow,  uint2* __restrict__ owh,  int n3)
{
    if (blockIdx.x == 0 && threadIdx.x < 16) g_cnts2[threadIdx.x] = 0;
    const int stride = gridDim.x * blockDim.x;
    const int t0 = blockIdx.x * blockDim.x + threadIdx.x;
    for (int i = t0; i < n1; i += stride) {
        float4 v = h[i];
        __half2 lo = __floats2half2_rn(v.x, v.y);
        __half2 hi = __floats2half2_rn(v.z, v.w);
        hh[i] = make_uint2(*(uint32_t*)&lo, *(uint32_t*)&hi);
    }
    for (int i = t0; i < n2; i += stride) {
        float4 v = inw[i];
        __half2 lo = __floats2half2_rn(v.x, v.y);
        __half2 hi = __floats2half2_rn(v.z, v.w);
        inwh[i] = make_uint2(*(uint32_t*)&lo, *(uint32_t*)&hi);
    }
    for (int i = t0; i < n3; i += stride) {
        float4 v = ow[i];
        __half2 lo = __floats2half2_rn(v.x, v.y);
        __half2 hi = __floats2half2_rn(v.z, v.w);
        owh[i] = make_uint2(*(uint32_t*)&lo, *(uint32_t*)&hi);
    }
}

// ---------------------------------------------------------------------------
// Router layer 1, FULL FP32, split-K x2: raw partial sums (no silu here).
// ---------------------------------------------------------------------------
__global__ __launch_bounds__(256) void router_l1(const float* __restrict__ h,
                                                 const float* __restrict__ w1,
                                                 float* __restrict__ rhp)
{
    __shared__ float As[64][33];
    __shared__ float Ws[128][33];

    const int tid = threadIdx.x;
    const int t0 = blockIdx.x * 64;
    const int kbase = blockIdx.y * (Dd / 2);
    float* rh = rhp + (size_t)blockIdx.y * NT * RHID;
    const int ty = tid >> 4;
    const int tx = tid & 15;

    float acc[4][8];
#pragma unroll
    for (int i = 0; i < 4; ++i)
#pragma unroll
        for (int j = 0; j < 8; ++j) acc[i][j] = 0.f;

    const int arow = tid >> 2, acol = (tid & 3) * 8;
    const int wrow = tid >> 1, wcol = (tid & 1) * 16;

    for (int k0 = kbase; k0 < kbase + Dd / 2; k0 += 32) {
        float4 a0 = *(const float4*)&h[(size_t)(t0 + arow) * Dd + k0 + acol];
        float4 a1 = *(const float4*)&h[(size_t)(t0 + arow) * Dd + k0 + acol + 4];
        As[arow][acol + 0] = a0.x; As[arow][acol + 1] = a0.y;
        As[arow][acol + 2] = a0.z; As[arow][acol + 3] = a0.w;
        As[arow][acol + 4] = a1.x; As[arow][acol + 5] = a1.y;
        As[arow][acol + 6] = a1.z; As[arow][acol + 7] = a1.w;
#pragma unroll
        for (int q = 0; q < 4; ++q) {
            float4 w = *(const float4*)&w1[(size_t)wrow * Dd + k0 + wcol + q * 4];
            Ws[wrow][wcol + q * 4 + 0] = w.x; Ws[wrow][wcol + q * 4 + 1] = w.y;
            Ws[wrow][wcol + q * 4 + 2] = w.z; Ws[wrow][wcol + q * 4 + 3] = w.w;
        }
        __syncthreads();

#pragma unroll 8
        for (int k = 0; k < 32; ++k) {
            float a[4], b[8];
#pragma unroll
            for (int i = 0; i < 4; ++i) a[i] = As[ty * 4 + i][k];
#pragma unroll
            for (int j = 0; j < 8; ++j) b[j] = Ws[tx * 8 + j][k];
#pragma unroll
            for (int i = 0; i < 4; ++i)
#pragma unroll
                for (int j = 0; j < 8; ++j) acc[i][j] += a[i] * b[j];
        }
        __syncthreads();
    }

#pragma unroll
    for (int i = 0; i < 4; ++i) {
        int t = t0 + ty * 4 + i;
#pragma unroll
        for (int j = 0; j < 8; ++j)
            rh[(size_t)t * RHID + tx * 8 + j] = acc[i][j];
    }
}

// ---------------------------------------------------------------------------
// Router finish (fp32): rh = silu(p0 + p1), logits, top-2 softmax, lists.
// ---------------------------------------------------------------------------
__global__ void router_finish(const float* __restrict__ rhp,
                              const float* __restrict__ w2)
{
    int t = (blockIdx.x * blockDim.x + threadIdx.x) >> 5;
    int lane = threadIdx.x & 31;
    if (t >= NT) return;

    const float* r0 = rhp + (size_t)t * RHID;
    const float* r1 = rhp + (size_t)NT * RHID + (size_t)t * RHID;
    float v0 = silu_(r0[lane]       + r1[lane]);
    float v1 = silu_(r0[lane + 32]  + r1[lane + 32]);
    float v2 = silu_(r0[lane + 64]  + r1[lane + 64]);
    float v3 = silu_(r0[lane + 96]  + r1[lane + 96]);

    float lg[NE];
#pragma unroll
    for (int e = 0; e < NE; ++e) {
        const float* w = w2 + e * RHID;
        float p = v0 * w[lane] + v1 * w[lane + 32] + v2 * w[lane + 64] + v3 * w[lane + 96];
#pragma unroll
        for (int o = 16; o; o >>= 1) p += __shfl_xor_sync(0xffffffffu, p, o);
        lg[e] = p;
    }

    if (lane == 0) {
        int i1 = 0; float l1 = lg[0];
#pragma unroll
        for (int e = 1; e < NE; ++e) if (lg[e] > l1) { l1 = lg[e]; i1 = e; }
        int i2 = -1; float l2 = -1e30f;
#pragma unroll
        for (int e = 0; e < NE; ++e) { if (e == i1) continue; if (lg[e] > l2) { l2 = lg[e]; i2 = e; } }
        float wtop = 1.f / (1.f + expf(l2 - l1));
        float* cb = &g_comb[(size_t)t * NE];
        int* sf = &g_selflag[(size_t)t * NE];
#pragma unroll
        for (int e = 0; e < NE; ++e) { cb[e] = 0.f; sf[e] = 0; }
        cb[i1] = wtop;       sf[i1] = 1;
        cb[i2] = 1.f - wtop; sf[i2] = 1;
        int q1 = atomicAdd(&g_cnts2[2 * i1], 1); g_lists[(2 * i1) * NT + q1] = t;
        int q2 = atomicAdd(&g_cnts2[2 * i2], 1); g_lists[(2 * i2) * NT + q2] = t;
    }
}

// ---------------------------------------------------------------------------
// Conv-input (dilated) token lists.
// ---------------------------------------------------------------------------
__global__ void build_xlists()
{
    int t = blockIdx.x * blockDim.x + threadIdx.x;
    int e = blockIdx.y;
    if (t >= NT) return;
    int b = t >> 11, s = t & (Ss - 1);
    bool need = false;
#pragma unroll
    for (int j = 0; j < 4; ++j) {
        int sj = s + j;
        if (sj < Ss) need |= (g_selflag[(size_t)(b * Ss + sj) * NE + e] != 0);
    }
    if (need) {
        int p = atomicAdd(&g_cnts2[2 * e + 1], 1);
        g_lists[(2 * e + 1) * NT + p] = t;
        g_posx[e * NT + t] = p;
    }
}

// ---------------------------------------------------------------------------
// FP16 GEMM (TN), batched over blockIdx.z: C[M,N] op= A[M,K] * W[N,K]^T.
// 128x128x64 CTA tile, 128 threads = 4 warps of 64x64 (2m x 2n).
// ldmatrix.x4 fragment loads (4x fewer shared-load issues vs scalar LDS).
// mma.m16n8k16.f32.f16.f16.f32, fp32 accumulate. 3-stage cp.async ring.
// mode 0: store fp16 rows. mode 1: atomicAdd fp32 into c_idx rows.
// ---------------------------------------------------------------------------
__global__ __launch_bounds__(128, 2) void gemm_fp16(
    const __half* __restrict__ A, const __half* __restrict__ W,
    void* __restrict__ Cv,
    const int* __restrict__ cnts, int mBase, int mStride,
    int N, int K,
    size_t aStrideZ, size_t wStrideZ, size_t cStrideZ,
    const int* __restrict__ a_idx, size_t aIdxStrideZ,
    const int* __restrict__ c_idx, size_t cIdxStrideZ,
    int mode)
{
    const int z = blockIdx.z;
    const int M = cnts[mBase + z * mStride];
    if ((int)blockIdx.y * BM >= M) return;

    A += (size_t)z * aStrideZ;
    W += (size_t)z * wStrideZ;
    const int* aidx = a_idx ? a_idx + (size_t)z * aIdxStrideZ : nullptr;
    const int* cidx = c_idx ? c_idx + (size_t)z * cIdxStrideZ : nullptr;

    extern __shared__ __half smem[];

    const int tid  = threadIdx.x;
    const int lane = tid & 31;
    const int warp = tid >> 5;
    const int g  = lane >> 2;
    const int tg = lane & 3;
    const int wm = (warp & 1) * 64;      // 0,64
    const int wn = (warp >> 1) * 64;     // 0,64

    // Loader: 16B chunks (8 halfs); row = 64 halfs = 8 chunks.
    const int r0    = tid >> 3;          // 0..15
    const int roffH = (tid & 7) * 8;     // half offset in row

    int arowidx[8];
#pragma unroll
    for (int j = 0; j < 8; ++j) {
        int gr = blockIdx.y * BM + r0 + 16 * j;
        int cr = min(gr, M - 1);
        arowidx[j] = aidx ? aidx[cr] : cr;
    }
    const __half* bbase = W + (size_t)(blockIdx.x * BN + r0) * K + roffH;

    const uint32_t saB = (uint32_t)__cvta_generic_to_shared(&smem[r0 * STRH + roffH]);
    const uint32_t sbB = (uint32_t)__cvta_generic_to_shared(
        &smem[A_STAGE_HALFS + r0 * STRH + roffH]);
    const uint32_t stagestep = (uint32_t)(STAGE_HALFS * sizeof(__half));
    const uint32_t rowskip = (uint32_t)(16 * STRH * sizeof(__half));

    // ldmatrix per-thread base addresses.
    // A x4 (m16 x k16): lanes 0-7 -> rows m0-7 @k, 8-15 -> m8-15 @k,
    //                   16-23 -> m0-7 @k+8, 24-31 -> m8-15 @k+8
    const int rowA  = lane & 15;
    const int koffA = (lane >> 4) << 3;
    // B x4 (two n8 x k16 frags): lanes 0-7 -> n0-7 @k, 8-15 -> n0-7 @k+8,
    //                            16-23 -> n8-15 @k, 24-31 -> n8-15 @k+8
    const int rowB  = ((lane >> 4) << 3) + (lane & 7);
    const int koffB = ((lane >> 3) & 1) << 3;

    uint32_t aAddr[4], bAddr[4];
#pragma unroll
    for (int mi = 0; mi < 4; ++mi)
        aAddr[mi] = (uint32_t)__cvta_generic_to_shared(
            &smem[(wm + mi * 16 + rowA) * STRH + koffA]);
#pragma unroll
    for (int nj = 0; nj < 4; ++nj)
        bAddr[nj] = (uint32_t)__cvta_generic_to_shared(
            &smem[A_STAGE_HALFS + (wn + nj * 16 + rowB) * STRH + koffB]);

    float cc[4][8][4];
#pragma unroll
    for (int i = 0; i < 4; ++i)
#pragma unroll
        for (int j = 0; j < 8; ++j)
#pragma unroll
            for (int r = 0; r < 4; ++r) cc[i][j][r] = 0.f;

    const int nk = K / BKH;

    auto load_stage = [&](int s, int kc) {
        const int k0 = kc * BKH;
        const uint32_t so = s * stagestep;
#pragma unroll
        for (int j = 0; j < 8; ++j) {
            const __half* src = A + (size_t)arowidx[j] * K + roffH + k0;
            asm volatile("cp.async.cg.shared.global [%0], [%1], 16;\n"
                         :: "r"(saB + so + j * rowskip), "l"(src) : "memory");
        }
#pragma unroll
        for (int j = 0; j < 8; ++j)
            asm volatile("cp.async.cg.shared.global [%0], [%1], 16;\n"
                         :: "r"(sbB + so + j * rowskip),
                            "l"(bbase + (size_t)16 * j * K + k0) : "memory");
        asm volatile("cp.async.commit_group;\n" ::: "memory");
    };

    load_stage(0, 0);
    load_stage(1, 1);

    int buf = 0;
    for (int kc = 0; kc < nk; ++kc) {
        asm volatile("cp.async.wait_group 1;\n" ::: "memory");
        __syncthreads();
        if (kc + 2 < nk) {
            int nb = buf + 2; if (nb >= STAGES) nb -= STAGES;
            load_stage(nb, kc + 2);
        } else {
            asm volatile("cp.async.commit_group;\n" ::: "memory");
        }

        const uint32_t so = buf * stagestep;

#pragma unroll
        for (int kk = 0; kk < BKH; kk += 16) {
            uint32_t a[4][4], b[4][4];
#pragma unroll
            for (int mi = 0; mi < 4; ++mi)
                asm volatile(
                    "ldmatrix.sync.aligned.m8n8.x4.shared.b16 {%0,%1,%2,%3}, [%4];"
                    : "=r"(a[mi][0]), "=r"(a[mi][1]), "=r"(a[mi][2]), "=r"(a[mi][3])
                    : "r"(aAddr[mi] + so + kk * 2));
#pragma unroll
            for (int nj = 0; nj < 4; ++nj)
                asm volatile(
                    "ldmatrix.sync.aligned.m8n8.x4.shared.b16 {%0,%1,%2,%3}, [%4];"
                    : "=r"(b[nj][0]), "=r"(b[nj][1]), "=r"(b[nj][2]), "=r"(b[nj][3])
                    : "r"(bAddr[nj] + so + kk * 2));
#pragma unroll
            for (int mi = 0; mi < 4; ++mi)
#pragma unroll
                for (int ni = 0; ni < 8; ++ni) {
                    const uint32_t b0 = b[ni >> 1][(ni & 1) ? 2 : 0];
                    const uint32_t b1 = b[ni >> 1][(ni & 1) ? 3 : 1];
                    asm volatile(
                        "mma.sync.aligned.m16n8k16.row.col.f32.f16.f16.f32 "
                        "{%0,%1,%2,%3}, {%4,%5,%6,%7}, {%8,%9}, {%0,%1,%2,%3};"
                        : "+f"(cc[mi][ni][0]), "+f"(cc[mi][ni][1]),
                          "+f"(cc[mi][ni][2]), "+f"(cc[mi][ni][3])
                        : "r"(a[mi][0]), "r"(a[mi][1]), "r"(a[mi][2]), "r"(a[mi][3]),
                          "r"(b0), "r"(b1));
                }
        }
        if (++buf == STAGES) buf = 0;
    }

    if (mode == 0) {
        __half* C = (__half*)Cv + (size_t)z * cStrideZ;
#pragma unroll
        for (int mi = 0; mi < 4; ++mi) {
            int m0 = blockIdx.y * BM + wm + mi * 16 + g;
            int m1 = m0 + 8;
#pragma unroll
            for (int ni = 0; ni < 8; ++ni) {
                int n0 = blockIdx.x * BN + wn + ni * 8 + 2 * tg;
                if (m0 < M) {
                    __half2 v = __floats2half2_rn(cc[mi][ni][0], cc[mi][ni][1]);
                    *reinterpret_cast<__half2*>(C + (size_t)m0 * N + n0) = v;
                }
                if (m1 < M) {
                    __half2 v = __floats2half2_rn(cc[mi][ni][2], cc[mi][ni][3]);
                    *reinterpret_cast<__half2*>(C + (size_t)m1 * N + n0) = v;
                }
            }
        }
    } else {
        float* C = (float*)Cv + (size_t)z * cStrideZ;
#pragma unroll
        for (int mi = 0; mi < 4; ++mi) {
            int m0 = blockIdx.y * BM + wm + mi * 16 + g;
            int m1 = m0 + 8;
#pragma unroll
            for (int ni = 0; ni < 8; ++ni) {
                int n0 = blockIdx.x * BN + wn + ni * 8 + 2 * tg;
                if (m0 < M) {
                    float* p = C + (size_t)cidx[m0] * N + n0;
                    atomicAdd(&p[0], cc[mi][ni][0]);
                    atomicAdd(&p[1], cc[mi][ni][1]);
                }
                if (m1 < M) {
                    float* p = C + (size_t)cidx[m1] * N + n0;
                    atomicAdd(&p[0], cc[mi][ni][2]);
                    atomicAdd(&p[1], cc[mi][ni][3]);
                }
            }
        }
    }
}

// ---------------------------------------------------------------------------
// Sparse fused conv + bias + silu(x)*silu(z)*comb (fp16 in -> fp16 out).
// ---------------------------------------------------------------------------
__global__ void conv_act_sparse(const float* __restrict__ cw_all,
                                const float* __restrict__ cb_all)
{
    const int e = blockIdx.y;
    const int cnt = g_cnts2[2 * e];
    const int total = cnt * (DI / 4);
    const int* sel = g_lists + (2 * e) * NT;
    const int* posx = g_posx + e * NT;
    const __half* zb = g_zx + (size_t)(2 * e) * NT * DI;
    const __half* xb = g_zx + (size_t)(2 * e + 1) * NT * DI;
    __half* xact = g_xact + (size_t)e * NT * DI;
    const float4* cwf = reinterpret_cast<const float4*>(cw_all + (size_t)e * DI * 4);
    const float4* cbf = reinterpret_cast<const float4*>(cb_all + (size_t)e * DI);

    for (int idx = blockIdx.x * blockDim.x + threadIdx.x; idx < total;
         idx += gridDim.x * blockDim.x) {
        const int i  = idx >> 9;
        const int c4 = idx & 511;
        const int c  = c4 * 4;
        const int t  = sel[i];
        const float wgt = g_comb[(size_t)t * NE + e];
        const int b = t >> 11, s = t & (Ss - 1);

        float4 w0 = cwf[c4 * 4 + 0];
        float4 w1 = cwf[c4 * 4 + 1];
        float4 w2 = cwf[c4 * 4 + 2];
        float4 w3 = cwf[c4 * 4 + 3];
        float4 acc = cbf[c4];

#pragma unroll
        for (int j = 0; j < 4; ++j) {
            int sj = s - 3 + j;
            if (sj < 0) continue;
            int r = posx[b * Ss + sj];
            const uint2 xr = *reinterpret_cast<const uint2*>(xb + (size_t)r * DI + c);
            float2 xlo = __half22float2(*reinterpret_cast<const __half2*>(&xr.x));
            float2 xhi = __half22float2(*reinterpret_cast<const __half2*>(&xr.y));
            float t0 = (j == 0) ? w0.x : (j == 1) ? w0.y : (j == 2) ? w0.z : w0.w;
            float t1 = (j == 0) ? w1.x : (j == 1) ? w1.y : (j == 2) ? w1.z : w1.w;
            float t2 = (j == 0) ? w2.x : (j == 1) ? w2.y : (j == 2) ? w2.z : w2.w;
            float t3 = (j == 0) ? w3.x : (j == 1) ? w3.y : (j == 2) ? w3.z : w3.w;
            acc.x += t0 * xlo.x; acc.y += t1 * xlo.y;
            acc.z += t2 * xhi.x; acc.w += t3 * xhi.y;
        }

        const uint2 zr = *reinterpret_cast<const uint2*>(zb + (size_t)i * DI + c);
        float2 zlo = __half22float2(*reinterpret_cast<const __half2*>(&zr.x));
        float2 zhi = __half22float2(*reinterpret_cast<const __half2*>(&zr.y));
        __half2 lo = __floats2half2_rn(silu_(acc.x) * silu_(zlo.x) * wgt,
                                       silu_(acc.y) * silu_(zlo.y) * wgt);
        __half2 hi = __floats2half2_rn(silu_(acc.z) * silu_(zhi.x) * wgt,
                                       silu_(acc.w) * silu_(zhi.y) * wgt);
        uint2 o;
        o.x = *reinterpret_cast<uint32_t*>(&lo);
        o.y = *reinterpret_cast<uint32_t*>(&hi);
        *reinterpret_cast<uint2*>(xact + (size_t)i * DI + c) = o;
    }
}

// ---------------------------------------------------------------------------
extern "C" void kernel_launch(void* const* d_in, const int* in_sizes, int n_in,
                              void* d_out, int out_size)
{
    const float* h   = (const float*)d_in[0];
    const float* inw = (const float*)d_in[1];
    const float* cw  = (const float*)d_in[2];
    const float* cb  = (const float*)d_in[3];
    const float* ow  = (const float*)d_in[4];
    const float* rw1 = (const float*)d_in[5];
    const float* rw2 = (const float*)d_in[6];
    float* out = (float*)d_out;

    void *zxp, *xap, *hhp, *iwp, *owp, *rhp, *cntp, *lstp;
    cudaGetSymbolAddress(&zxp, g_zx);
    cudaGetSymbolAddress(&xap, g_xact);
    cudaGetSymbolAddress(&hhp, g_hh);
    cudaGetSymbolAddress(&iwp, g_inwh);
    cudaGetSymbolAddress(&owp, g_owh);
    cudaGetSymbolAddress(&rhp, g_rhp);
    cudaGetSymbolAddress(&cntp, g_cnts2);
    cudaGetSymbolAddress(&lstp, g_lists);
    __half* zx    = (__half*)zxp;
    __half* xact  = (__half*)xap;
    __half* hh    = (__half*)hhp;
    __half* inwh  = (__half*)iwp;
    __half* owh   = (__half*)owp;
    float*  rhpf  = (float*)rhp;
    int*    cnts  = (int*)cntp;
    int*    lists = (int*)lstp;

    cudaFuncSetAttribute(gemm_fp16, cudaFuncAttributeMaxDynamicSharedMemorySize,
                         SMEM_BYTES);

    // 1: fused converts (+cnts zero)
    convert_all<<<2048, 256>>>((const float4*)h,   (uint2*)hh,   NT * Dd / 4,
                               (const float4*)inw, (uint2*)inwh, NE * 2 * DI * Dd / 4,
                               (const float4*)ow,  (uint2*)owh,  NE * Dd * DI / 4);
    // 2: router layer 1 (fp32, split-K x2)
    router_l1<<<dim3(NT / 64, 2), 256>>>(h, rw1, rhpf);
    // 3: router finish (lists for z-jobs ready after this)
    router_finish<<<(NT * 32) / 256, 256>>>(rhpf, rw2);

    // 4: in_proj z-jobs (8) -- kernel #4 = what ncu profiles
    gemm_fp16<<<dim3(DI / BN, NT / BM, NE), 128, SMEM_BYTES>>>(
        hh, inwh, zx, cnts, 0, 2, DI, Dd,
        (size_t)0, (size_t)2 * DI * Dd, (size_t)2 * NT * DI,
        lists, (size_t)2 * NT, nullptr, (size_t)0, 0);

    // 5: conv-input lists
    build_xlists<<<dim3(NT / 256, NE), 256>>>();

    // 6: in_proj x-jobs (8)
    gemm_fp16<<<dim3(DI / BN, NT / BM, NE), 128, SMEM_BYTES>>>(
        hh, inwh + (size_t)DI * Dd, zx + (size_t)NT * DI, cnts, 1, 2, DI, Dd,
        (size_t)0, (size_t)2 * DI * Dd, (size_t)2 * NT * DI,
        lists + NT, (size_t)2 * NT, nullptr, (size_t)0, 0);

    // out zeroing (needed before out_proj only)
    cudaMemsetAsync(out, 0, (size_t)NT * Dd * sizeof(float));

    // conv + gate
    conv_act_sparse<<<dim3(1024, NE), 256>>>(cw, cb);

    // out_proj per expert: atomic fp32 scatter-accumulate into out
    gemm_fp16<<<dim3(Dd / BN, NT / BM, NE), 128, SMEM_BYTES>>>(
        xact, owh, out, cnts, 0, 2, Dd, DI,
        (size_t)NT * DI, (size_t)Dd * DI, (size_t)0,
        nullptr, (size_t)0, lists, (size_t)2 * NT, 1);
}

// round 15
// speedup vs baseline: 2.1397x; 1.0078x over previous
#include <cuda_runtime.h>
#include <cuda_fp16.h>
#include <cstdint>
#include <cstddef>

// Problem constants
#define BATCH 4
#define Ss 2048
#define Dd 1024
#define DI 2048          // D_INNER
#define NT (BATCH*Ss)    // 8192 tokens
#define NE 8
#define RHID 128
#define RSPLIT 4         // router split-K factor

// FP16 GEMM tile config: 128x128x64 CTA tile, 128 threads (4 warps of 64x64)
#define BM 128
#define BN 128
#define BKH 64                          // K elements per stage (halfs)
#define STRH 72                         // padded smem row stride (halfs) = 144B
#define STAGES 3
#define A_STAGE_HALFS (BM * STRH)
#define STAGE_HALFS ((BM + BN) * STRH)
#define SMEM_BYTES (STAGES * STAGE_HALFS * 2)   // 110,592 B -> 2 CTAs/SM

// Scratch (device globals: allocation-free rule)
__device__ __half g_zx[(size_t)16 * NT * DI];     // in_proj outputs (fp16)
__device__ __half g_xact[(size_t)NE * NT * DI];   // gated act (fp16)
__device__ __half g_hh[(size_t)NT * Dd];          // h in fp16
__device__ __half g_inwh[(size_t)NE * 2 * DI * Dd];
__device__ __half g_owh[(size_t)NE * Dd * DI];
__device__ float  g_rhp[(size_t)RSPLIT * NT * RHID]; // router hidden partials
__device__ float  g_comb[(size_t)NT * NE];
__device__ int    g_selflag[(size_t)NT * NE];
__device__ int    g_lists[16 * NT];
__device__ int    g_posx[NE * NT];
__device__ int    g_cnts2[16];

__device__ __forceinline__ float silu_(float x) { return x / (1.0f + expf(-x)); }

// ---------------------------------------------------------------------------
// Fused fp32 -> fp16 convert for h, in_proj_w, out_proj_w; zeros cnts + out.
// ---------------------------------------------------------------------------
__global__ void convert_all(const float4* __restrict__ h,   uint2* __restrict__ hh,   int n1,
                            const float4* __restrict__ inw, uint2* __restrict__ inwh, int n2,
                            const float4* __restrict__ ow,  uint2* __restrict__ owh,  int n3,
                            float4* __restrict__ outz, int n4)
{
    if (blockIdx.x == 0 && threadIdx.x < 16) g_cnts2[threadIdx.x] = 0;
    const int stride = gridDim.x * blockDim.x;
    const int t0 = blockIdx.x * blockDim.x + threadIdx.x;
    for (int i = t0; i < n1; i += stride) {
        float4 v = h[i];
        __half2 lo = __floats2half2_rn(v.x, v.y);
        __half2 hi = __floats2half2_rn(v.z, v.w);
        hh[i] = make_uint2(*(uint32_t*)&lo, *(uint32_t*)&hi);
    }
    for (int i = t0; i < n2; i += stride) {
        float4 v = inw[i];
        __half2 lo = __floats2half2_rn(v.x, v.y);
        __half2 hi = __floats2half2_rn(v.z, v.w);
        inwh[i] = make_uint2(*(uint32_t*)&lo, *(uint32_t*)&hi);
    }
    for (int i = t0; i < n3; i += stride) {
        float4 v = ow[i];
        __half2 lo = __floats2half2_rn(v.x, v.y);
        __half2 hi = __floats2half2_rn(v.z, v.w);
        owh[i] = make_uint2(*(uint32_t*)&lo, *(uint32_t*)&hi);
    }
    const float4 zero = make_float4(0.f, 0.f, 0.f, 0.f);
    for (int i = t0; i < n4; i += stride) outz[i] = zero;
}

// ---------------------------------------------------------------------------
// Router layer 1, FULL FP32, split-K x RSPLIT: raw partial sums.
// grid (NT/64, RSPLIT). Partials summed in fixed order in router_finish.
// ---------------------------------------------------------------------------
__global__ __launch_bounds__(256) void router_l1(const float* __restrict__ h,
                                                 const float* __restrict__ w1,
                                                 float* __restrict__ rhp)
{
    __shared__ float As[64][33];
    __shared__ float Ws[128][33];

    const int tid = threadIdx.x;
    const int t0 = blockIdx.x * 64;
    const int kbase = blockIdx.y * (Dd / RSPLIT);
    float* rh = rhp + (size_t)blockIdx.y * NT * RHID;
    const int ty = tid >> 4;
    const int tx = tid & 15;

    float acc[4][8];
#pragma unroll
    for (int i = 0; i < 4; ++i)
#pragma unroll
        for (int j = 0; j < 8; ++j) acc[i][j] = 0.f;

    const int arow = tid >> 2, acol = (tid & 3) * 8;
    const int wrow = tid >> 1, wcol = (tid & 1) * 16;

    for (int k0 = kbase; k0 < kbase + Dd / RSPLIT; k0 += 32) {
        float4 a0 = *(const float4*)&h[(size_t)(t0 + arow) * Dd + k0 + acol];
        float4 a1 = *(const float4*)&h[(size_t)(t0 + arow) * Dd + k0 + acol + 4];
        As[arow][acol + 0] = a0.x; As[arow][acol + 1] = a0.y;
        As[arow][acol + 2] = a0.z; As[arow][acol + 3] = a0.w;
        As[arow][acol + 4] = a1.x; As[arow][acol + 5] = a1.y;
        As[arow][acol + 6] = a1.z; As[arow][acol + 7] = a1.w;
#pragma unroll
        for (int q = 0; q < 4; ++q) {
            float4 w = *(const float4*)&w1[(size_t)wrow * Dd + k0 + wcol + q * 4];
            Ws[wrow][wcol + q * 4 + 0] = w.x; Ws[wrow][wcol + q * 4 + 1] = w.y;
            Ws[wrow][wcol + q * 4 + 2] = w.z; Ws[wrow][wcol + q * 4 + 3] = w.w;
        }
        __syncthreads();

#pragma unroll 8
        for (int k = 0; k < 32; ++k) {
            float a[4], b[8];
#pragma unroll
            for (int i = 0; i < 4; ++i) a[i] = As[ty * 4 + i][k];
#pragma unroll
            for (int j = 0; j < 8; ++j) b[j] = Ws[tx * 8 + j][k];
#pragma unroll
            for (int i = 0; i < 4; ++i)
#pragma unroll
                for (int j = 0; j < 8; ++j) acc[i][j] += a[i] * b[j];
        }
        __syncthreads();
    }

#pragma unroll
    for (int i = 0; i < 4; ++i) {
        int t = t0 + ty * 4 + i;
#pragma unroll
        for (int j = 0; j < 8; ++j)
            rh[(size_t)t * RHID + tx * 8 + j] = acc[i][j];
    }
}

// ---------------------------------------------------------------------------
// Router finish (fp32): rh = silu(sum of partials, fixed order), logits,
// top-2 softmax, lists.
// ---------------------------------------------------------------------------
__global__ void router_finish(const float* __restrict__ rhp,
                              const float* __restrict__ w2)
{
    int t = (blockIdx.x * blockDim.x + threadIdx.x) >> 5;
    int lane = threadIdx.x & 31;
    if (t >= NT) return;

    float s[4];
#pragma unroll
    for (int q = 0; q < 4; ++q) {
        float v = 0.f;
#pragma unroll
        for (int p = 0; p < RSPLIT; ++p)
            v += rhp[(size_t)p * NT * RHID + (size_t)t * RHID + lane + 32 * q];
        s[q] = silu_(v);
    }

    float lg[NE];
#pragma unroll
    for (int e = 0; e < NE; ++e) {
        const float* w = w2 + e * RHID;
        float p = s[0] * w[lane] + s[1] * w[lane + 32] + s[2] * w[lane + 64]
                + s[3] * w[lane + 96];
#pragma unroll
        for (int o = 16; o; o >>= 1) p += __shfl_xor_sync(0xffffffffu, p, o);
        lg[e] = p;
    }

    if (lane == 0) {
        int i1 = 0; float l1 = lg[0];
#pragma unroll
        for (int e = 1; e < NE; ++e) if (lg[e] > l1) { l1 = lg[e]; i1 = e; }
        int i2 = -1; float l2 = -1e30f;
#pragma unroll
        for (int e = 0; e < NE; ++e) { if (e == i1) continue; if (lg[e] > l2) { l2 = lg[e]; i2 = e; } }
        float wtop = 1.f / (1.f + expf(l2 - l1));
        float* cb = &g_comb[(size_t)t * NE];
        int* sf = &g_selflag[(size_t)t * NE];
#pragma unroll
        for (int e = 0; e < NE; ++e) { cb[e] = 0.f; sf[e] = 0; }
        cb[i1] = wtop;       sf[i1] = 1;
        cb[i2] = 1.f - wtop; sf[i2] = 1;
        int q1 = atomicAdd(&g_cnts2[2 * i1], 1); g_lists[(2 * i1) * NT + q1] = t;
        int q2 = atomicAdd(&g_cnts2[2 * i2], 1); g_lists[(2 * i2) * NT + q2] = t;
    }
}

// ---------------------------------------------------------------------------
// Conv-input (dilated) token lists.
// ---------------------------------------------------------------------------
__global__ void build_xlists()
{
    int t = blockIdx.x * blockDim.x + threadIdx.x;
    int e = blockIdx.y;
    if (t >= NT) return;
    int b = t >> 11, s = t & (Ss - 1);
    bool need = false;
#pragma unroll
    for (int j = 0; j < 4; ++j) {
        int sj = s + j;
        if (sj < Ss) need |= (g_selflag[(size_t)(b * Ss + sj) * NE + e] != 0);
    }
    if (need) {
        int p = atomicAdd(&g_cnts2[2 * e + 1], 1);
        g_lists[(2 * e + 1) * NT + p] = t;
        g_posx[e * NT + t] = p;
    }
}

// ---------------------------------------------------------------------------
// FP16 GEMM (TN), batched over blockIdx.z: C[M,N] op= A[M,K] * W[N,K]^T.
// 128x128x64 CTA tile, 128 threads = 4 warps of 64x64 (2m x 2n).
// ldmatrix.x4 fragment loads. mma.m16n8k16.f32.f16.f16.f32, fp32 accumulate.
// 3-stage cp.async ring. mode 0: store fp16 rows. mode 1: atomicAdd fp32.
// ---------------------------------------------------------------------------
__global__ __launch_bounds__(128, 2) void gemm_fp16(
    const __half* __restrict__ A, const __half* __restrict__ W,
    void* __restrict__ Cv,
    const int* __restrict__ cnts, int mBase, int mStride,
    int N, int K,
    size_t aStrideZ, size_t wStrideZ, size_t cStrideZ,
    const int* __restrict__ a_idx, size_t aIdxStrideZ,
    const int* __restrict__ c_idx, size_t cIdxStrideZ,
    int mode)
{
    const int z = blockIdx.z;
    const int M = cnts[mBase + z * mStride];
    if ((int)blockIdx.y * BM >= M) return;

    A += (size_t)z * aStrideZ;
    W += (size_t)z * wStrideZ;
    const int* aidx = a_idx ? a_idx + (size_t)z * aIdxStrideZ : nullptr;
    const int* cidx = c_idx ? c_idx + (size_t)z * cIdxStrideZ : nullptr;

    extern __shared__ __half smem[];

    const int tid  = threadIdx.x;
    const int lane = tid & 31;
    const int warp = tid >> 5;
    const int g  = lane >> 2;
    const int tg = lane & 3;
    const int wm = (warp & 1) * 64;      // 0,64
    const int wn = (warp >> 1) * 64;     // 0,64

    const int r0    = tid >> 3;          // 0..15
    const int roffH = (tid & 7) * 8;     // half offset in row

    int arowidx[8];
#pragma unroll
    for (int j = 0; j < 8; ++j) {
        int gr = blockIdx.y * BM + r0 + 16 * j;
        int cr = min(gr, M - 1);
        arowidx[j] = aidx ? aidx[cr] : cr;
    }
    const __half* bbase = W + (size_t)(blockIdx.x * BN + r0) * K + roffH;

    const uint32_t saB = (uint32_t)__cvta_generic_to_shared(&smem[r0 * STRH + roffH]);
    const uint32_t sbB = (uint32_t)__cvta_generic_to_shared(
        &smem[A_STAGE_HALFS + r0 * STRH + roffH]);
    const uint32_t stagestep = (uint32_t)(STAGE_HALFS * sizeof(__half));
    const uint32_t rowskip = (uint32_t)(16 * STRH * sizeof(__half));

    // ldmatrix per-thread base addresses.
    const int rowA  = lane & 15;
    const int koffA = (lane >> 4) << 3;
    const int rowB  = ((lane >> 4) << 3) + (lane & 7);
    const int koffB = ((lane >> 3) & 1) << 3;

    uint32_t aAddr[4], bAddr[4];
#pragma unroll
    for (int mi = 0; mi < 4; ++mi)
        aAddr[mi] = (uint32_t)__cvta_generic_to_shared(
            &smem[(wm + mi * 16 + rowA) * STRH + koffA]);
#pragma unroll
    for (int nj = 0; nj < 4; ++nj)
        bAddr[nj] = (uint32_t)__cvta_generic_to_shared(
            &smem[A_STAGE_HALFS + (wn + nj * 16 + rowB) * STRH + koffB]);

    float cc[4][8][4];
#pragma unroll
    for (int i = 0; i < 4; ++i)
#pragma unroll
        for (int j = 0; j < 8; ++j)
#pragma unroll
            for (int r = 0; r < 4; ++r) cc[i][j][r] = 0.f;

    const int nk = K / BKH;

    auto load_stage = [&](int s, int kc) {
        const int k0 = kc * BKH;
        const uint32_t so = s * stagestep;
#pragma unroll
        for (int j = 0; j < 8; ++j) {
            const __half* src = A + (size_t)arowidx[j] * K + roffH + k0;
            asm volatile("cp.async.cg.shared.global [%0], [%1], 16;\n"
                         :: "r"(saB + so + j * rowskip), "l"(src) : "memory");
        }
#pragma unroll
        for (int j = 0; j < 8; ++j)
            asm volatile("cp.async.cg.shared.global [%0], [%1], 16;\n"
                         :: "r"(sbB + so + j * rowskip),
                            "l"(bbase + (size_t)16 * j * K + k0) : "memory");
        asm volatile("cp.async.commit_group;\n" ::: "memory");
    };

    load_stage(0, 0);
    load_stage(1, 1);

    int buf = 0;
    for (int kc = 0; kc < nk; ++kc) {
        asm volatile("cp.async.wait_group 1;\n" ::: "memory");
        __syncthreads();
        if (kc + 2 < nk) {
            int nb = buf + 2; if (nb >= STAGES) nb -= STAGES;
            load_stage(nb, kc + 2);
        } else {
            asm volatile("cp.async.commit_group;\n" ::: "memory");
        }

        const uint32_t so = buf * stagestep;

#pragma unroll
        for (int kk = 0; kk < BKH; kk += 16) {
            uint32_t a[4][4], b[4][4];
#pragma unroll
            for (int mi = 0; mi < 4; ++mi)
                asm volatile(
                    "ldmatrix.sync.aligned.m8n8.x4.shared.b16 {%0,%1,%2,%3}, [%4];"
                    : "=r"(a[mi][0]), "=r"(a[mi][1]), "=r"(a[mi][2]), "=r"(a[mi][3])
                    : "r"(aAddr[mi] + so + kk * 2));
#pragma unroll
            for (int nj = 0; nj < 4; ++nj)
                asm volatile(
                    "ldmatrix.sync.aligned.m8n8.x4.shared.b16 {%0,%1,%2,%3}, [%4];"
                    : "=r"(b[nj][0]), "=r"(b[nj][1]), "=r"(b[nj][2]), "=r"(b[nj][3])
                    : "r"(bAddr[nj] + so + kk * 2));
#pragma unroll
            for (int mi = 0; mi < 4; ++mi)
#pragma unroll
                for (int ni = 0; ni < 8; ++ni) {
                    const uint32_t b0 = b[ni >> 1][(ni & 1) ? 2 : 0];
                    const uint32_t b1 = b[ni >> 1][(ni & 1) ? 3 : 1];
                    asm volatile(
                        "mma.sync.aligned.m16n8k16.row.col.f32.f16.f16.f32 "
                        "{%0,%1,%2,%3}, {%4,%5,%6,%7}, {%8,%9}, {%0,%1,%2,%3};"
                        : "+f"(cc[mi][ni][0]), "+f"(cc[mi][ni][1]),
                          "+f"(cc[mi][ni][2]), "+f"(cc[mi][ni][3])
                        : "r"(a[mi][0]), "r"(a[mi][1]), "r"(a[mi][2]), "r"(a[mi][3]),
                          "r"(b0), "r"(b1));
                }
        }
        if (++buf == STAGES) buf = 0;
    }

    if (mode == 0) {
        __half* C = (__half*)Cv + (size_t)z * cStrideZ;
#pragma unroll
        for (int mi = 0; mi < 4; ++mi) {
            int m0 = blockIdx.y * BM + wm + mi * 16 + g;
            int m1 = m0 + 8;
#pragma unroll
            for (int ni = 0; ni < 8; ++ni) {
                int n0 = blockIdx.x * BN + wn + ni * 8 + 2 * tg;
                if (m0 < M) {
                    __half2 v = __floats2half2_rn(cc[mi][ni][0], cc[mi][ni][1]);
                    *reinterpret_cast<__half2*>(C + (size_t)m0 * N + n0) = v;
                }
                if (m1 < M) {
                    __half2 v = __floats2half2_rn(cc[mi][ni][2], cc[mi][ni][3]);
                    *reinterpret_cast<__half2*>(C + (size_t)m1 * N + n0) = v;
                }
            }
        }
    } else {
        float* C = (float*)Cv + (size_t)z * cStrideZ;
#pragma unroll
        for (int mi = 0; mi < 4; ++mi) {
            int m0 = blockIdx.y * BM + wm + mi * 16 + g;
            int m1 = m0 + 8;
#pragma unroll
            for (int ni = 0; ni < 8; ++ni) {
                int n0 = blockIdx.x * BN + wn + ni * 8 + 2 * tg;
                if (m0 < M) {
                    float* p = C + (size_t)cidx[m0] * N + n0;
                    atomicAdd(&p[0], cc[mi][ni][0]);
                    atomicAdd(&p[1], cc[mi][ni][1]);
                }
                if (m1 < M) {
                    float* p = C + (size_t)cidx[m1] * N + n0;
                    atomicAdd(&p[0], cc[mi][ni][2]);
                    atomicAdd(&p[1], cc[mi][ni][3]);
                }
            }
        }
    }
}

// ---------------------------------------------------------------------------
// Sparse fused conv + bias + silu(x)*silu(z)*comb (fp16 in -> fp16 out).
// ---------------------------------------------------------------------------
__global__ void conv_act_sparse(const float* __restrict__ cw_all,
                                const float* __restrict__ cb_all)
{
    const int e = blockIdx.y;
    const int cnt = g_cnts2[2 * e];
    const int total = cnt * (DI / 4);
    const int* sel = g_lists + (2 * e) * NT;
    const int* posx = g_posx + e * NT;
    const __half* zb = g_zx + (size_t)(2 * e) * NT * DI;
    const __half* xb = g_zx + (size_t)(2 * e + 1) * NT * DI;
    __half* xact = g_xact + (size_t)e * NT * DI;
    const float4* cwf = reinterpret_cast<const float4*>(cw_all + (size_t)e * DI * 4);
    const float4* cbf = reinterpret_cast<const float4*>(cb_all + (size_t)e * DI);

    for (int idx = blockIdx.x * blockDim.x + threadIdx.x; idx < total;
         idx += gridDim.x * blockDim.x) {
        const int i  = idx >> 9;
        const int c4 = idx & 511;
        const int c  = c4 * 4;
        const int t  = sel[i];
        const float wgt = g_comb[(size_t)t * NE + e];
        const int b = t >> 11, s = t & (Ss - 1);

        float4 w0 = cwf[c4 * 4 + 0];
        float4 w1 = cwf[c4 * 4 + 1];
        float4 w2 = cwf[c4 * 4 + 2];
        float4 w3 = cwf[c4 * 4 + 3];
        float4 acc = cbf[c4];

#pragma unroll
        for (int j = 0; j < 4; ++j) {
            int sj = s - 3 + j;
            if (sj < 0) continue;
            int r = posx[b * Ss + sj];
            const uint2 xr = *reinterpret_cast<const uint2*>(xb + (size_t)r * DI + c);
            float2 xlo = __half22float2(*reinterpret_cast<const __half2*>(&xr.x));
            float2 xhi = __half22float2(*reinterpret_cast<const __half2*>(&xr.y));
            float t0 = (j == 0) ? w0.x : (j == 1) ? w0.y : (j == 2) ? w0.z : w0.w;
            float t1 = (j == 0) ? w1.x : (j == 1) ? w1.y : (j == 2) ? w1.z : w1.w;
            float t2 = (j == 0) ? w2.x : (j == 1) ? w2.y : (j == 2) ? w2.z : w2.w;
            float t3 = (j == 0) ? w3.x : (j == 1) ? w3.y : (j == 2) ? w3.z : w3.w;
            acc.x += t0 * xlo.x; acc.y += t1 * xlo.y;
            acc.z += t2 * xhi.x; acc.w += t3 * xhi.y;
        }

        const uint2 zr = *reinterpret_cast<const uint2*>(zb + (size_t)i * DI + c);
        float2 zlo = __half22float2(*reinterpret_cast<const __half2*>(&zr.x));
        float2 zhi = __half22float2(*reinterpret_cast<const __half2*>(&zr.y));
        __half2 lo = __floats2half2_rn(silu_(acc.x) * silu_(zlo.x) * wgt,
                                       silu_(acc.y) * silu_(zlo.y) * wgt);
        __half2 hi = __floats2half2_rn(silu_(acc.z) * silu_(zhi.x) * wgt,
                                       silu_(acc.w) * silu_(zhi.y) * wgt);
        uint2 o;
        o.x = *reinterpret_cast<uint32_t*>(&lo);
        o.y = *reinterpret_cast<uint32_t*>(&hi);
        *reinterpret_cast<uint2*>(xact + (size_t)i * DI + c) = o;
    }
}

// ---------------------------------------------------------------------------
extern "C" void kernel_launch(void* const* d_in, const int* in_sizes, int n_in,
                              void* d_out, int out_size)
{
    const float* h   = (const float*)d_in[0];
    const float* inw = (const float*)d_in[1];
    const float* cw  = (const float*)d_in[2];
    const float* cb  = (const float*)d_in[3];
    const float* ow  = (const float*)d_in[4];
    const float* rw1 = (const float*)d_in[5];
    const float* rw2 = (const float*)d_in[6];
    float* out = (float*)d_out;

    void *zxp, *xap, *hhp, *iwp, *owp, *rhp, *cntp, *lstp;
    cudaGetSymbolAddress(&zxp, g_zx);
    cudaGetSymbolAddress(&xap, g_xact);
    cudaGetSymbolAddress(&hhp, g_hh);
    cudaGetSymbolAddress(&iwp, g_inwh);
    cudaGetSymbolAddress(&owp, g_owh);
    cudaGetSymbolAddress(&rhp, g_rhp);
    cudaGetSymbolAddress(&cntp, g_cnts2);
    cudaGetSymbolAddress(&lstp, g_lists);
    __half* zx    = (__half*)zxp;
    __half* xact  = (__half*)xap;
    __half* hh    = (__half*)hhp;
    __half* inwh  = (__half*)iwp;
    __half* owh   = (__half*)owp;
    float*  rhpf  = (float*)rhp;
    int*    cnts  = (int*)cntp;
    int*    lists = (int*)lstp;

    cudaFuncSetAttribute(gemm_fp16, cudaFuncAttributeMaxDynamicSharedMemorySize,
                         SMEM_BYTES);

    // 1: fused converts (+cnts zero, +out zero)
    convert_all<<<2048, 256>>>((const float4*)h,   (uint2*)hh,   NT * Dd / 4,
                               (const float4*)inw, (uint2*)inwh, NE * 2 * DI * Dd / 4,
                               (const float4*)ow,  (uint2*)owh,  NE * Dd * DI / 4,
                               (float4*)out, NT * Dd / 4);
    // 2: router layer 1 (fp32, split-K x4)
    router_l1<<<dim3(NT / 64, RSPLIT), 256>>>(h, rw1, rhpf);
    // 3: router finish
    router_finish<<<(NT * 32) / 256, 256>>>(rhpf, rw2);
    // 4: conv-input lists
    build_xlists<<<dim3(NT / 256, NE), 256>>>();

    // 5: in_proj, all 16 jobs in one launch (job 2e = z rows, 2e+1 = x rows)
    gemm_fp16<<<dim3(DI / BN, NT / BM, 16), 128, SMEM_BYTES>>>(
        hh, inwh, zx, cnts, 0, 1, DI, Dd,
        (size_t)0, (size_t)DI * Dd, (size_t)NT * DI,
        lists, (size_t)NT, nullptr, (size_t)0, 0);

    // 6: conv + gate
    conv_act_sparse<<<dim3(1024, NE), 256>>>(cw, cb);

    // 7: out_proj per expert: atomic fp32 scatter-accumulate into out
    gemm_fp16<<<dim3(Dd / BN, NT / BM, NE), 128, SMEM_BYTES>>>(
        xact, owh, out, cnts, 0, 2, Dd, DI,
        (size_t)NT * DI, (size_t)Dd * DI, (size_t)0,
        nullptr, (size_t)0, lists, (size_t)2 * NT, 1);
}

// round 16
// speedup vs baseline: 2.1430x; 1.0015x over previous
#include <cuda_runtime.h>
#include <cuda_fp16.h>
#include <cstdint>
#include <cstddef>

// Problem constants
#define BATCH 4
#define Ss 2048
#define Dd 1024
#define DI 2048          // D_INNER
#define NT (BATCH*Ss)    // 8192 tokens
#define NE 8
#define RHID 128
#define RSPLIT 4         // router split-K factor

// FP16 GEMM tile config: 128x128x64 CTA tile, 128 threads (4 warps of 64x64)
#define BM 128
#define BN 128
#define BKH 64                          // K elements per stage (halfs)
#define STRH 72                         // padded smem row stride (halfs) = 144B
#define STAGES 3
#define A_STAGE_HALFS (BM * STRH)
#define STAGE_HALFS ((BM + BN) * STRH)
#define SMEM_BYTES (STAGES * STAGE_HALFS * 2)   // 110,592 B -> 2 CTAs/SM

// Scratch (device globals: allocation-free rule)
__device__ __half g_zx[(size_t)16 * NT * DI];     // in_proj outputs (fp16)
__device__ __half g_xact[(size_t)NE * NT * DI];   // gated act (fp16)
__device__ __half g_hh[(size_t)NT * Dd];          // h in fp16
__device__ __half g_inwh[(size_t)NE * 2 * DI * Dd];
__device__ __half g_owh[(size_t)NE * Dd * DI];
__device__ float  g_rhp[(size_t)RSPLIT * NT * RHID]; // router hidden partials
__device__ float  g_comb[(size_t)NT * NE];
__device__ int    g_selflag[(size_t)NT * NE];
__device__ int    g_lists[16 * NT];
__device__ int    g_posx[NE * NT];
__device__ int    g_cnts2[16];

__device__ __forceinline__ float silu_(float x) { return x / (1.0f + expf(-x)); }

// ---------------------------------------------------------------------------
// Fused fp32 -> fp16 convert for h, in_proj_w, out_proj_w; zeros out.
// (cnts zeroing moved to stream 2 to avoid a cross-stream race)
// ---------------------------------------------------------------------------
__global__ void convert_all(const float4* __restrict__ h,   uint2* __restrict__ hh,   int n1,
                            const float4* __restrict__ inw, uint2* __restrict__ inwh, int n2,
                            const float4* __restrict__ ow,  uint2* __restrict__ owh,  int n3,
                            float4* __restrict__ outz, int n4)
{
    const int stride = gridDim.x * blockDim.x;
    const int t0 = blockIdx.x * blockDim.x + threadIdx.x;
    for (int i = t0; i < n1; i += stride) {
        float4 v = h[i];
        __half2 lo = __floats2half2_rn(v.x, v.y);
        __half2 hi = __floats2half2_rn(v.z, v.w);
        hh[i] = make_uint2(*(uint32_t*)&lo, *(uint32_t*)&hi);
    }
    for (int i = t0; i < n2; i += stride) {
        float4 v = inw[i];
        __half2 lo = __floats2half2_rn(v.x, v.y);
        __half2 hi = __floats2half2_rn(v.z, v.w);
        inwh[i] = make_uint2(*(uint32_t*)&lo, *(uint32_t*)&hi);
    }
    for (int i = t0; i < n3; i += stride) {
        float4 v = ow[i];
        __half2 lo = __floats2half2_rn(v.x, v.y);
        __half2 hi = __floats2half2_rn(v.z, v.w);
        owh[i] = make_uint2(*(uint32_t*)&lo, *(uint32_t*)&hi);
    }
    const float4 zero = make_float4(0.f, 0.f, 0.f, 0.f);
    for (int i = t0; i < n4; i += stride) outz[i] = zero;
}

// ---------------------------------------------------------------------------
// Router layer 1, FULL FP32, split-K x RSPLIT: raw partial sums.
// ---------------------------------------------------------------------------
__global__ __launch_bounds__(256) void router_l1(const float* __restrict__ h,
                                                 const float* __restrict__ w1,
                                                 float* __restrict__ rhp)
{
    __shared__ float As[64][33];
    __shared__ float Ws[128][33];

    const int tid = threadIdx.x;
    const int t0 = blockIdx.x * 64;
    const int kbase = blockIdx.y * (Dd / RSPLIT);
    float* rh = rhp + (size_t)blockIdx.y * NT * RHID;
    const int ty = tid >> 4;
    const int tx = tid & 15;

    float acc[4][8];
#pragma unroll
    for (int i = 0; i < 4; ++i)
#pragma unroll
        for (int j = 0; j < 8; ++j) acc[i][j] = 0.f;

    const int arow = tid >> 2, acol = (tid & 3) * 8;
    const int wrow = tid >> 1, wcol = (tid & 1) * 16;

    for (int k0 = kbase; k0 < kbase + Dd / RSPLIT; k0 += 32) {
        float4 a0 = *(const float4*)&h[(size_t)(t0 + arow) * Dd + k0 + acol];
        float4 a1 = *(const float4*)&h[(size_t)(t0 + arow) * Dd + k0 + acol + 4];
        As[arow][acol + 0] = a0.x; As[arow][acol + 1] = a0.y;
        As[arow][acol + 2] = a0.z; As[arow][acol + 3] = a0.w;
        As[arow][acol + 4] = a1.x; As[arow][acol + 5] = a1.y;
        As[arow][acol + 6] = a1.z; As[arow][acol + 7] = a1.w;
#pragma unroll
        for (int q = 0; q < 4; ++q) {
            float4 w = *(const float4*)&w1[(size_t)wrow * Dd + k0 + wcol + q * 4];
            Ws[wrow][wcol + q * 4 + 0] = w.x; Ws[wrow][wcol + q * 4 + 1] = w.y;
            Ws[wrow][wcol + q * 4 + 2] = w.z; Ws[wrow][wcol + q * 4 + 3] = w.w;
        }
        __syncthreads();

#pragma unroll 8
        for (int k = 0; k < 32; ++k) {
            float a[4], b[8];
#pragma unroll
            for (int i = 0; i < 4; ++i) a[i] = As[ty * 4 + i][k];
#pragma unroll
            for (int j = 0; j < 8; ++j) b[j] = Ws[tx * 8 + j][k];
#pragma unroll
            for (int i = 0; i < 4; ++i)
#pragma unroll
                for (int j = 0; j < 8; ++j) acc[i][j] += a[i] * b[j];
        }
        __syncthreads();
    }

#pragma unroll
    for (int i = 0; i < 4; ++i) {
        int t = t0 + ty * 4 + i;
#pragma unroll
        for (int j = 0; j < 8; ++j)
            rh[(size_t)t * RHID + tx * 8 + j] = acc[i][j];
    }
}

// ---------------------------------------------------------------------------
// Router finish (fp32): rh = silu(sum of partials, fixed order), logits,
// top-2 softmax, lists.
// ---------------------------------------------------------------------------
__global__ void router_finish(const float* __restrict__ rhp,
                              const float* __restrict__ w2)
{
    int t = (blockIdx.x * blockDim.x + threadIdx.x) >> 5;
    int lane = threadIdx.x & 31;
    if (t >= NT) return;

    float s[4];
#pragma unroll
    for (int q = 0; q < 4; ++q) {
        float v = 0.f;
#pragma unroll
        for (int p = 0; p < RSPLIT; ++p)
            v += rhp[(size_t)p * NT * RHID + (size_t)t * RHID + lane + 32 * q];
        s[q] = silu_(v);
    }

    float lg[NE];
#pragma unroll
    for (int e = 0; e < NE; ++e) {
        const float* w = w2 + e * RHID;
        float p = s[0] * w[lane] + s[1] * w[lane + 32] + s[2] * w[lane + 64]
                + s[3] * w[lane + 96];
#pragma unroll
        for (int o = 16; o; o >>= 1) p += __shfl_xor_sync(0xffffffffu, p, o);
        lg[e] = p;
    }

    if (lane == 0) {
        int i1 = 0; float l1 = lg[0];
#pragma unroll
        for (int e = 1; e < NE; ++e) if (lg[e] > l1) { l1 = lg[e]; i1 = e; }
        int i2 = -1; float l2 = -1e30f;
#pragma unroll
        for (int e = 0; e < NE; ++e) { if (e == i1) continue; if (lg[e] > l2) { l2 = lg[e]; i2 = e; } }
        float wtop = 1.f / (1.f + expf(l2 - l1));
        float* cb = &g_comb[(size_t)t * NE];
        int* sf = &g_selflag[(size_t)t * NE];
#pragma unroll
        for (int e = 0; e < NE; ++e) { cb[e] = 0.f; sf[e] = 0; }
        cb[i1] = wtop;       sf[i1] = 1;
        cb[i2] = 1.f - wtop; sf[i2] = 1;
        int q1 = atomicAdd(&g_cnts2[2 * i1], 1); g_lists[(2 * i1) * NT + q1] = t;
        int q2 = atomicAdd(&g_cnts2[2 * i2], 1); g_lists[(2 * i2) * NT + q2] = t;
    }
}

// ---------------------------------------------------------------------------
// Conv-input (dilated) token lists.
// ---------------------------------------------------------------------------
__global__ void build_xlists()
{
    int t = blockIdx.x * blockDim.x + threadIdx.x;
    int e = blockIdx.y;
    if (t >= NT) return;
    int b = t >> 11, s = t & (Ss - 1);
    bool need = false;
#pragma unroll
    for (int j = 0; j < 4; ++j) {
        int sj = s + j;
        if (sj < Ss) need |= (g_selflag[(size_t)(b * Ss + sj) * NE + e] != 0);
    }
    if (need) {
        int p = atomicAdd(&g_cnts2[2 * e + 1], 1);
        g_lists[(2 * e + 1) * NT + p] = t;
        g_posx[e * NT + t] = p;
    }
}

// ---------------------------------------------------------------------------
// FP16 GEMM (TN), batched over blockIdx.z: C[M,N] op= A[M,K] * W[N,K]^T.
// 128x128x64 CTA tile, 128 threads = 4 warps of 64x64 (2m x 2n).
// ldmatrix.x4 fragment loads. mma.m16n8k16.f32.f16.f16.f32, fp32 accumulate.
// 3-stage cp.async ring. mode 0: store fp16 rows. mode 1: atomicAdd fp32.
// ---------------------------------------------------------------------------
__global__ __launch_bounds__(128, 2) void gemm_fp16(
    const __half* __restrict__ A, const __half* __restrict__ W,
    void* __restrict__ Cv,
    const int* __restrict__ cnts, int mBase, int mStride,
    int N, int K,
    size_t aStrideZ, size_t wStrideZ, size_t cStrideZ,
    const int* __restrict__ a_idx, size_t aIdxStrideZ,
    const int* __restrict__ c_idx, size_t cIdxStrideZ,
    int mode)
{
    const int z = blockIdx.z;
    const int M = cnts[mBase + z * mStride];
    if ((int)blockIdx.y * BM >= M) return;

    A += (size_t)z * aStrideZ;
    W += (size_t)z * wStrideZ;
    const int* aidx = a_idx ? a_idx + (size_t)z * aIdxStrideZ : nullptr;
    const int* cidx = c_idx ? c_idx + (size_t)z * cIdxStrideZ : nullptr;

    extern __shared__ __half smem[];

    const int tid  = threadIdx.x;
    const int lane = tid & 31;
    const int warp = tid >> 5;
    const int g  = lane >> 2;
    const int tg = lane & 3;
    const int wm = (warp & 1) * 64;      // 0,64
    const int wn = (warp >> 1) * 64;     // 0,64

    const int r0    = tid >> 3;          // 0..15
    const int roffH = (tid & 7) * 8;     // half offset in row

    int arowidx[8];
#pragma unroll
    for (int j = 0; j < 8; ++j) {
        int gr = blockIdx.y * BM + r0 + 16 * j;
        int cr = min(gr, M - 1);
        arowidx[j] = aidx ? aidx[cr] : cr;
    }
    const __half* bbase = W + (size_t)(blockIdx.x * BN + r0) * K + roffH;

    const uint32_t saB = (uint32_t)__cvta_generic_to_shared(&smem[r0 * STRH + roffH]);
    const uint32_t sbB = (uint32_t)__cvta_generic_to_shared(
        &smem[A_STAGE_HALFS + r0 * STRH + roffH]);
    const uint32_t stagestep = (uint32_t)(STAGE_HALFS * sizeof(__half));
    const uint32_t rowskip = (uint32_t)(16 * STRH * sizeof(__half));

    // ldmatrix per-thread base addresses.
    const int rowA  = lane & 15;
    const int koffA = (lane >> 4) << 3;
    const int rowB  = ((lane >> 4) << 3) + (lane & 7);
    const int koffB = ((lane >> 3) & 1) << 3;

    uint32_t aAddr[4], bAddr[4];
#pragma unroll
    for (int mi = 0; mi < 4; ++mi)
        aAddr[mi] = (uint32_t)__cvta_generic_to_shared(
            &smem[(wm + mi * 16 + rowA) * STRH + koffA]);
#pragma unroll
    for (int nj = 0; nj < 4; ++nj)
        bAddr[nj] = (uint32_t)__cvta_generic_to_shared(
            &smem[A_STAGE_HALFS + (wn + nj * 16 + rowB) * STRH + koffB]);

    float cc[4][8][4];
#pragma unroll
    for (int i = 0; i < 4; ++i)
#pragma unroll
        for (int j = 0; j < 8; ++j)
#pragma unroll
            for (int r = 0; r < 4; ++r) cc[i][j][r] = 0.f;

    const int nk = K / BKH;

    auto load_stage = [&](int s, int kc) {
        const int k0 = kc * BKH;
        const uint32_t so = s * stagestep;
#pragma unroll
        for (int j = 0; j < 8; ++j) {
            const __half* src = A + (size_t)arowidx[j] * K + roffH + k0;
            asm volatile("cp.async.cg.shared.global [%0], [%1], 16;\n"
                         :: "r"(saB + so + j * rowskip), "l"(src) : "memory");
        }
#pragma unroll
        for (int j = 0; j < 8; ++j)
            asm volatile("cp.async.cg.shared.global [%0], [%1], 16;\n"
                         :: "r"(sbB + so + j * rowskip),
                            "l"(bbase + (size_t)16 * j * K + k0) : "memory");
        asm volatile("cp.async.commit_group;\n" ::: "memory");
    };

    load_stage(0, 0);
    load_stage(1, 1);

    int buf = 0;
    for (int kc = 0; kc < nk; ++kc) {
        asm volatile("cp.async.wait_group 1;\n" ::: "memory");
        __syncthreads();
        if (kc + 2 < nk) {
            int nb = buf + 2; if (nb >= STAGES) nb -= STAGES;
            load_stage(nb, kc + 2);
        } else {
            asm volatile("cp.async.commit_group;\n" ::: "memory");
        }

        const uint32_t so = buf * stagestep;

#pragma unroll
        for (int kk = 0; kk < BKH; kk += 16) {
            uint32_t a[4][4], b[4][4];
#pragma unroll
            for (int mi = 0; mi < 4; ++mi)
                asm volatile(
                    "ldmatrix.sync.aligned.m8n8.x4.shared.b16 {%0,%1,%2,%3}, [%4];"
                    : "=r"(a[mi][0]), "=r"(a[mi][1]), "=r"(a[mi][2]), "=r"(a[mi][3])
                    : "r"(aAddr[mi] + so + kk * 2));
#pragma unroll
            for (int nj = 0; nj < 4; ++nj)
                asm volatile(
                    "ldmatrix.sync.aligned.m8n8.x4.shared.b16 {%0,%1,%2,%3}, [%4];"
                    : "=r"(b[nj][0]), "=r"(b[nj][1]), "=r"(b[nj][2]), "=r"(b[nj][3])
                    : "r"(bAddr[nj] + so + kk * 2));
#pragma unroll
            for (int mi = 0; mi < 4; ++mi)
#pragma unroll
                for (int ni = 0; ni < 8; ++ni) {
                    const uint32_t b0 = b[ni >> 1][(ni & 1) ? 2 : 0];
                    const uint32_t b1 = b[ni >> 1][(ni & 1) ? 3 : 1];
                    asm volatile(
                        "mma.sync.aligned.m16n8k16.row.col.f32.f16.f16.f32 "
                        "{%0,%1,%2,%3}, {%4,%5,%6,%7}, {%8,%9}, {%0,%1,%2,%3};"
                        : "+f"(cc[mi][ni][0]), "+f"(cc[mi][ni][1]),
                          "+f"(cc[mi][ni][2]), "+f"(cc[mi][ni][3])
                        : "r"(a[mi][0]), "r"(a[mi][1]), "r"(a[mi][2]), "r"(a[mi][3]),
                          "r"(b0), "r"(b1));
                }
        }
        if (++buf == STAGES) buf = 0;
    }

    if (mode == 0) {
        __half* C = (__half*)Cv + (size_t)z * cStrideZ;
#pragma unroll
        for (int mi = 0; mi < 4; ++mi) {
            int m0 = blockIdx.y * BM + wm + mi * 16 + g;
            int m1 = m0 + 8;
#pragma unroll
            for (int ni = 0; ni < 8; ++ni) {
                int n0 = blockIdx.x * BN + wn + ni * 8 + 2 * tg;
                if (m0 < M) {
                    __half2 v = __floats2half2_rn(cc[mi][ni][0], cc[mi][ni][1]);
                    *reinterpret_cast<__half2*>(C + (size_t)m0 * N + n0) = v;
                }
                if (m1 < M) {
                    __half2 v = __floats2half2_rn(cc[mi][ni][2], cc[mi][ni][3]);
                    *reinterpret_cast<__half2*>(C + (size_t)m1 * N + n0) = v;
                }
            }
        }
    } else {
        float* C = (float*)Cv + (size_t)z * cStrideZ;
#pragma unroll
        for (int mi = 0; mi < 4; ++mi) {
            int m0 = blockIdx.y * BM + wm + mi * 16 + g;
            int m1 = m0 + 8;
#pragma unroll
            for (int ni = 0; ni < 8; ++ni) {
                int n0 = blockIdx.x * BN + wn + ni * 8 + 2 * tg;
                if (m0 < M) {
                    float* p = C + (size_t)cidx[m0] * N + n0;
                    atomicAdd(&p[0], cc[mi][ni][0]);
                    atomicAdd(&p[1], cc[mi][ni][1]);
                }
                if (m1 < M) {
                    float* p = C + (size_t)cidx[m1] * N + n0;
                    atomicAdd(&p[0], cc[mi][ni][2]);
                    atomicAdd(&p[1], cc[mi][ni][3]);
                }
            }
        }
    }
}

// ---------------------------------------------------------------------------
// Sparse fused conv + bias + silu(x)*silu(z)*comb (fp16 in -> fp16 out).
// ---------------------------------------------------------------------------
__global__ void conv_act_sparse(const float* __restrict__ cw_all,
                                const float* __restrict__ cb_all)
{
    const int e = blockIdx.y;
    const int cnt = g_cnts2[2 * e];
    const int total = cnt * (DI / 4);
    const int* sel = g_lists + (2 * e) * NT;
    const int* posx = g_posx + e * NT;
    const __half* zb = g_zx + (size_t)(2 * e) * NT * DI;
    const __half* xb = g_zx + (size_t)(2 * e + 1) * NT * DI;
    __half* xact = g_xact + (size_t)e * NT * DI;
    const float4* cwf = reinterpret_cast<const float4*>(cw_all + (size_t)e * DI * 4);
    const float4* cbf = reinterpret_cast<const float4*>(cb_all + (size_t)e * DI);

    for (int idx = blockIdx.x * blockDim.x + threadIdx.x; idx < total;
         idx += gridDim.x * blockDim.x) {
        const int i  = idx >> 9;
        const int c4 = idx & 511;
        const int c  = c4 * 4;
        const int t  = sel[i];
        const float wgt = g_comb[(size_t)t * NE + e];
        const int b = t >> 11, s = t & (Ss - 1);

        float4 w0 = cwf[c4 * 4 + 0];
        float4 w1 = cwf[c4 * 4 + 1];
        float4 w2 = cwf[c4 * 4 + 2];
        float4 w3 = cwf[c4 * 4 + 3];
        float4 acc = cbf[c4];

#pragma unroll
        for (int j = 0; j < 4; ++j) {
            int sj = s - 3 + j;
            if (sj < 0) continue;
            int r = posx[b * Ss + sj];
            const uint2 xr = *reinterpret_cast<const uint2*>(xb + (size_t)r * DI + c);
            float2 xlo = __half22float2(*reinterpret_cast<const __half2*>(&xr.x));
            float2 xhi = __half22float2(*reinterpret_cast<const __half2*>(&xr.y));
            float t0 = (j == 0) ? w0.x : (j == 1) ? w0.y : (j == 2) ? w0.z : w0.w;
            float t1 = (j == 0) ? w1.x : (j == 1) ? w1.y : (j == 2) ? w1.z : w1.w;
            float t2 = (j == 0) ? w2.x : (j == 1) ? w2.y : (j == 2) ? w2.z : w2.w;
            float t3 = (j == 0) ? w3.x : (j == 1) ? w3.y : (j == 2) ? w3.z : w3.w;
            acc.x += t0 * xlo.x; acc.y += t1 * xlo.y;
            acc.z += t2 * xhi.x; acc.w += t3 * xhi.y;
        }

        const uint2 zr = *reinterpret_cast<const uint2*>(zb + (size_t)i * DI + c);
        float2 zlo = __half22float2(*reinterpret_cast<const __half2*>(&zr.x));
        float2 zhi = __half22float2(*reinterpret_cast<const __half2*>(&zr.y));
        __half2 lo = __floats2half2_rn(silu_(acc.x) * silu_(zlo.x) * wgt,
                                       silu_(acc.y) * silu_(zlo.y) * wgt);
        __half2 hi = __floats2half2_rn(silu_(acc.z) * silu_(zhi.x) * wgt,
                                       silu_(acc.w) * silu_(zhi.y) * wgt);
        uint2 o;
        o.x = *reinterpret_cast<uint32_t*>(&lo);
        o.y = *reinterpret_cast<uint32_t*>(&hi);
        *reinterpret_cast<uint2*>(xact + (size_t)i * DI + c) = o;
    }
}

// ---------------------------------------------------------------------------
extern "C" void kernel_launch(void* const* d_in, const int* in_sizes, int n_in,
                              void* d_out, int out_size)
{
    const float* h   = (const float*)d_in[0];
    const float* inw = (const float*)d_in[1];
    const float* cw  = (const float*)d_in[2];
    const float* cb  = (const float*)d_in[3];
    const float* ow  = (const float*)d_in[4];
    const float* rw1 = (const float*)d_in[5];
    const float* rw2 = (const float*)d_in[6];
    float* out = (float*)d_out;

    void *zxp, *xap, *hhp, *iwp, *owp, *rhp, *cntp, *lstp;
    cudaGetSymbolAddress(&zxp, g_zx);
    cudaGetSymbolAddress(&xap, g_xact);
    cudaGetSymbolAddress(&hhp, g_hh);
    cudaGetSymbolAddress(&iwp, g_inwh);
    cudaGetSymbolAddress(&owp, g_owh);
    cudaGetSymbolAddress(&rhp, g_rhp);
    cudaGetSymbolAddress(&cntp, g_cnts2);
    cudaGetSymbolAddress(&lstp, g_lists);
    __half* zx    = (__half*)zxp;
    __half* xact  = (__half*)xap;
    __half* hh    = (__half*)hhp;
    __half* inwh  = (__half*)iwp;
    __half* owh   = (__half*)owp;
    float*  rhpf  = (float*)rhp;
    int*    cnts  = (int*)cntp;
    int*    lists = (int*)lstp;

    // One-time host-side handles (no device memory involved).
    static cudaStream_t s2 = nullptr;
    static cudaEvent_t evFork = nullptr, evJoin = nullptr;
    if (!s2) {
        cudaStreamCreateWithFlags(&s2, cudaStreamNonBlocking);
        cudaEventCreateWithFlags(&evFork, cudaEventDisableTiming);
        cudaEventCreateWithFlags(&evJoin, cudaEventDisableTiming);
        cudaFuncSetAttribute(gemm_fp16, cudaFuncAttributeMaxDynamicSharedMemorySize,
                             SMEM_BYTES);
    }

    // Fork: stream 2 runs the router chain while default runs the converts.
    cudaEventRecord(evFork, 0);
    cudaStreamWaitEvent(s2, evFork, 0);

    // default stream: fused converts (+out zero) -- DRAM-bound
    convert_all<<<2048, 256>>>((const float4*)h,   (uint2*)hh,   NT * Dd / 4,
                               (const float4*)inw, (uint2*)inwh, NE * 2 * DI * Dd / 4,
                               (const float4*)ow,  (uint2*)owh,  NE * Dd * DI / 4,
                               (float4*)out, NT * Dd / 4);

    // stream 2: router chain -- FMA-bound (overlaps with converts)
    cudaMemsetAsync(cnts, 0, 16 * sizeof(int), s2);
    router_l1<<<dim3(NT / 64, RSPLIT), 256, 0, s2>>>(h, rw1, rhpf);
    router_finish<<<(NT * 32) / 256, 256, 0, s2>>>(rhpf, rw2);
    build_xlists<<<dim3(NT / 256, NE), 256, 0, s2>>>();

    // Join: in_proj needs converts (default) AND lists (s2).
    cudaEventRecord(evJoin, s2);
    cudaStreamWaitEvent(0, evJoin, 0);

    // in_proj, all 16 jobs (job 2e = z rows, 2e+1 = x rows)
    gemm_fp16<<<dim3(DI / BN, NT / BM, 16), 128, SMEM_BYTES>>>(
        hh, inwh, zx, cnts, 0, 1, DI, Dd,
        (size_t)0, (size_t)DI * Dd, (size_t)NT * DI,
        lists, (size_t)NT, nullptr, (size_t)0, 0);

    // conv + gate
    conv_act_sparse<<<dim3(1024, NE), 256>>>(cw, cb);

    // out_proj per expert: atomic fp32 scatter-accumulate into out
    gemm_fp16<<<dim3(Dd / BN, NT / BM, NE), 128, SMEM_BYTES>>>(
        xact, owh, out, cnts, 0, 2, Dd, DI,
        (size_t)NT * DI, (size_t)Dd * DI, (size_t)0,
        nullptr, (size_t)0, lists, (size_t)2 * NT, 1);
}

// round 17
// speedup vs baseline: 2.2105x; 1.0315x over previous
#include <cuda_runtime.h>
#include <cuda_fp16.h>
#include <cstdint>
#include <cstddef>

// Problem constants
#define BATCH 4
#define Ss 2048
#define Dd 1024
#define DI 2048          // D_INNER
#define NT (BATCH*Ss)    // 8192 tokens
#define NE 8
#define RHID 128
#define RSPLIT 4         // router split-K factor

// FP16 GEMM tile config: 128x128x64 CTA tile, 128 threads (4 warps of 64x64)
#define BM 128
#define BN 128
#define BKH 64                          // K elements per stage (halfs)
#define STRH 72                         // padded smem row stride (halfs) = 144B
#define STAGES 3
#define A_STAGE_HALFS (BM * STRH)
#define STAGE_HALFS ((BM + BN) * STRH)
#define SMEM_BYTES (STAGES * STAGE_HALFS * 2)   // 110,592 B -> 2 CTAs/SM

// Scratch (device globals: allocation-free rule)
__device__ __half g_zx[(size_t)16 * NT * DI];     // in_proj outputs (fp16)
__device__ __half g_xact[(size_t)NE * NT * DI];   // gated act (fp16)
__device__ __half g_hh[(size_t)NT * Dd];          // h in fp16
__device__ __half g_inwh[(size_t)NE * 2 * DI * Dd];
__device__ __half g_owh[(size_t)NE * Dd * DI];
__device__ float  g_rhp[(size_t)RSPLIT * NT * RHID]; // router hidden partials
__device__ float  g_comb[(size_t)NT * NE];
__device__ int    g_selflag[(size_t)NT * NE];
__device__ int    g_lists[16 * NT];
__device__ int    g_posx[NE * NT];
__device__ int    g_cnts2[16];

__device__ __forceinline__ float silu_(float x) { return x / (1.0f + expf(-x)); }

// ---------------------------------------------------------------------------
// fp32 -> fp16 convert: h + in_proj weights (needed before in_proj GEMM).
// ---------------------------------------------------------------------------
__global__ void convert_h_inw(const float4* __restrict__ h,   uint2* __restrict__ hh,   int n1,
                              const float4* __restrict__ inw, uint2* __restrict__ inwh, int n2)
{
    const int stride = gridDim.x * blockDim.x;
    const int t0 = blockIdx.x * blockDim.x + threadIdx.x;
    for (int i = t0; i < n1; i += stride) {
        float4 v = h[i];
        __half2 lo = __floats2half2_rn(v.x, v.y);
        __half2 hi = __floats2half2_rn(v.z, v.w);
        hh[i] = make_uint2(*(uint32_t*)&lo, *(uint32_t*)&hi);
    }
    for (int i = t0; i < n2; i += stride) {
        float4 v = inw[i];
        __half2 lo = __floats2half2_rn(v.x, v.y);
        __half2 hi = __floats2half2_rn(v.z, v.w);
        inwh[i] = make_uint2(*(uint32_t*)&lo, *(uint32_t*)&hi);
    }
}

// ---------------------------------------------------------------------------
// fp32 -> fp16 convert: out_proj weights + zero out (needed before out_proj;
// hides under the in_proj GEMM on a low-priority stream).
// ---------------------------------------------------------------------------
__global__ void convert_ow(const float4* __restrict__ ow, uint2* __restrict__ owh, int n3,
                           float4* __restrict__ outz, int n4)
{
    const int stride = gridDim.x * blockDim.x;
    const int t0 = blockIdx.x * blockDim.x + threadIdx.x;
    for (int i = t0; i < n3; i += stride) {
        float4 v = ow[i];
        __half2 lo = __floats2half2_rn(v.x, v.y);
        __half2 hi = __floats2half2_rn(v.z, v.w);
        owh[i] = make_uint2(*(uint32_t*)&lo, *(uint32_t*)&hi);
    }
    const float4 zero = make_float4(0.f, 0.f, 0.f, 0.f);
    for (int i = t0; i < n4; i += stride) outz[i] = zero;
}

// ---------------------------------------------------------------------------
// Router layer 1, FULL FP32, split-K x RSPLIT: raw partial sums.
// ---------------------------------------------------------------------------
__global__ __launch_bounds__(256) void router_l1(const float* __restrict__ h,
                                                 const float* __restrict__ w1,
                                                 float* __restrict__ rhp)
{
    __shared__ float As[64][33];
    __shared__ float Ws[128][33];

    const int tid = threadIdx.x;
    const int t0 = blockIdx.x * 64;
    const int kbase = blockIdx.y * (Dd / RSPLIT);
    float* rh = rhp + (size_t)blockIdx.y * NT * RHID;
    const int ty = tid >> 4;
    const int tx = tid & 15;

    float acc[4][8];
#pragma unroll
    for (int i = 0; i < 4; ++i)
#pragma unroll
        for (int j = 0; j < 8; ++j) acc[i][j] = 0.f;

    const int arow = tid >> 2, acol = (tid & 3) * 8;
    const int wrow = tid >> 1, wcol = (tid & 1) * 16;

    for (int k0 = kbase; k0 < kbase + Dd / RSPLIT; k0 += 32) {
        float4 a0 = *(const float4*)&h[(size_t)(t0 + arow) * Dd + k0 + acol];
        float4 a1 = *(const float4*)&h[(size_t)(t0 + arow) * Dd + k0 + acol + 4];
        As[arow][acol + 0] = a0.x; As[arow][acol + 1] = a0.y;
        As[arow][acol + 2] = a0.z; As[arow][acol + 3] = a0.w;
        As[arow][acol + 4] = a1.x; As[arow][acol + 5] = a1.y;
        As[arow][acol + 6] = a1.z; As[arow][acol + 7] = a1.w;
#pragma unroll
        for (int q = 0; q < 4; ++q) {
            float4 w = *(const float4*)&w1[(size_t)wrow * Dd + k0 + wcol + q * 4];
            Ws[wrow][wcol + q * 4 + 0] = w.x; Ws[wrow][wcol + q * 4 + 1] = w.y;
            Ws[wrow][wcol + q * 4 + 2] = w.z; Ws[wrow][wcol + q * 4 + 3] = w.w;
        }
        __syncthreads();

#pragma unroll 8
        for (int k = 0; k < 32; ++k) {
            float a[4], b[8];
#pragma unroll
            for (int i = 0; i < 4; ++i) a[i] = As[ty * 4 + i][k];
#pragma unroll
            for (int j = 0; j < 8; ++j) b[j] = Ws[tx * 8 + j][k];
#pragma unroll
            for (int i = 0; i < 4; ++i)
#pragma unroll
                for (int j = 0; j < 8; ++j) acc[i][j] += a[i] * b[j];
        }
        __syncthreads();
    }

#pragma unroll
    for (int i = 0; i < 4; ++i) {
        int t = t0 + ty * 4 + i;
#pragma unroll
        for (int j = 0; j < 8; ++j)
            rh[(size_t)t * RHID + tx * 8 + j] = acc[i][j];
    }
}

// ---------------------------------------------------------------------------
// Router finish (fp32): rh = silu(sum of partials, fixed order), logits,
// top-2 softmax, lists.
// ---------------------------------------------------------------------------
__global__ void router_finish(const float* __restrict__ rhp,
                              const float* __restrict__ w2)
{
    int t = (blockIdx.x * blockDim.x + threadIdx.x) >> 5;
    int lane = threadIdx.x & 31;
    if (t >= NT) return;

    float s[4];
#pragma unroll
    for (int q = 0; q < 4; ++q) {
        float v = 0.f;
#pragma unroll
        for (int p = 0; p < RSPLIT; ++p)
            v += rhp[(size_t)p * NT * RHID + (size_t)t * RHID + lane + 32 * q];
        s[q] = silu_(v);
    }

    float lg[NE];
#pragma unroll
    for (int e = 0; e < NE; ++e) {
        const float* w = w2 + e * RHID;
        float p = s[0] * w[lane] + s[1] * w[lane + 32] + s[2] * w[lane + 64]
                + s[3] * w[lane + 96];
#pragma unroll
        for (int o = 16; o; o >>= 1) p += __shfl_xor_sync(0xffffffffu, p, o);
        lg[e] = p;
    }

    if (lane == 0) {
        int i1 = 0; float l1 = lg[0];
#pragma unroll
        for (int e = 1; e < NE; ++e) if (lg[e] > l1) { l1 = lg[e]; i1 = e; }
        int i2 = -1; float l2 = -1e30f;
#pragma unroll
        for (int e = 0; e < NE; ++e) { if (e == i1) continue; if (lg[e] > l2) { l2 = lg[e]; i2 = e; } }
        float wtop = 1.f / (1.f + expf(l2 - l1));
        float* cb = &g_comb[(size_t)t * NE];
        int* sf = &g_selflag[(size_t)t * NE];
#pragma unroll
        for (int e = 0; e < NE; ++e) { cb[e] = 0.f; sf[e] = 0; }
        cb[i1] = wtop;       sf[i1] = 1;
        cb[i2] = 1.f - wtop; sf[i2] = 1;
        int q1 = atomicAdd(&g_cnts2[2 * i1], 1); g_lists[(2 * i1) * NT + q1] = t;
        int q2 = atomicAdd(&g_cnts2[2 * i2], 1); g_lists[(2 * i2) * NT + q2] = t;
    }
}

// ---------------------------------------------------------------------------
// Conv-input (dilated) token lists.
// ---------------------------------------------------------------------------
__global__ void build_xlists()
{
    int t = blockIdx.x * blockDim.x + threadIdx.x;
    int e = blockIdx.y;
    if (t >= NT) return;
    int b = t >> 11, s = t & (Ss - 1);
    bool need = false;
#pragma unroll
    for (int j = 0; j < 4; ++j) {
        int sj = s + j;
        if (sj < Ss) need |= (g_selflag[(size_t)(b * Ss + sj) * NE + e] != 0);
    }
    if (need) {
        int p = atomicAdd(&g_cnts2[2 * e + 1], 1);
        g_lists[(2 * e + 1) * NT + p] = t;
        g_posx[e * NT + t] = p;
    }
}

// ---------------------------------------------------------------------------
// FP16 GEMM (TN), batched over blockIdx.z: C[M,N] op= A[M,K] * W[N,K]^T.
// 128x128x64 CTA tile, 128 threads = 4 warps of 64x64 (2m x 2n).
// ldmatrix.x4 fragment loads. mma.m16n8k16.f32.f16.f16.f32, fp32 accumulate.
// 3-stage cp.async ring. mode 0: store fp16 rows. mode 1: atomicAdd fp32.
// ---------------------------------------------------------------------------
__global__ __launch_bounds__(128, 2) void gemm_fp16(
    const __half* __restrict__ A, const __half* __restrict__ W,
    void* __restrict__ Cv,
    const int* __restrict__ cnts, int mBase, int mStride,
    int N, int K,
    size_t aStrideZ, size_t wStrideZ, size_t cStrideZ,
    const int* __restrict__ a_idx, size_t aIdxStrideZ,
    const int* __restrict__ c_idx, size_t cIdxStrideZ,
    int mode)
{
    const int z = blockIdx.z;
    const int M = cnts[mBase + z * mStride];
    if ((int)blockIdx.y * BM >= M) return;

    A += (size_t)z * aStrideZ;
    W += (size_t)z * wStrideZ;
    const int* aidx = a_idx ? a_idx + (size_t)z * aIdxStrideZ : nullptr;
    const int* cidx = c_idx ? c_idx + (size_t)z * cIdxStrideZ : nullptr;

    extern __shared__ __half smem[];

    const int tid  = threadIdx.x;
    const int lane = tid & 31;
    const int warp = tid >> 5;
    const int g  = lane >> 2;
    const int tg = lane & 3;
    const int wm = (warp & 1) * 64;      // 0,64
    const int wn = (warp >> 1) * 64;     // 0,64

    const int r0    = tid >> 3;          // 0..15
    const int roffH = (tid & 7) * 8;     // half offset in row

    int arowidx[8];
#pragma unroll
    for (int j = 0; j < 8; ++j) {
        int gr = blockIdx.y * BM + r0 + 16 * j;
        int cr = min(gr, M - 1);
        arowidx[j] = aidx ? aidx[cr] : cr;
    }
    const __half* bbase = W + (size_t)(blockIdx.x * BN + r0) * K + roffH;

    const uint32_t saB = (uint32_t)__cvta_generic_to_shared(&smem[r0 * STRH + roffH]);
    const uint32_t sbB = (uint32_t)__cvta_generic_to_shared(
        &smem[A_STAGE_HALFS + r0 * STRH + roffH]);
    const uint32_t stagestep = (uint32_t)(STAGE_HALFS * sizeof(__half));
    const uint32_t rowskip = (uint32_t)(16 * STRH * sizeof(__half));

    // ldmatrix per-thread base addresses.
    const int rowA  = lane & 15;
    const int koffA = (lane >> 4) << 3;
    const int rowB  = ((lane >> 4) << 3) + (lane & 7);
    const int koffB = ((lane >> 3) & 1) << 3;

    uint32_t aAddr[4], bAddr[4];
#pragma unroll
    for (int mi = 0; mi < 4; ++mi)
        aAddr[mi] = (uint32_t)__cvta_generic_to_shared(
            &smem[(wm + mi * 16 + rowA) * STRH + koffA]);
#pragma unroll
    for (int nj = 0; nj < 4; ++nj)
        bAddr[nj] = (uint32_t)__cvta_generic_to_shared(
            &smem[A_STAGE_HALFS + (wn + nj * 16 + rowB) * STRH + koffB]);

    float cc[4][8][4];
#pragma unroll
    for (int i = 0; i < 4; ++i)
#pragma unroll
        for (int j = 0; j < 8; ++j)
#pragma unroll
            for (int r = 0; r < 4; ++r) cc[i][j][r] = 0.f;

    const int nk = K / BKH;

    auto load_stage = [&](int s, int kc) {
        const int k0 = kc * BKH;
        const uint32_t so = s * stagestep;
#pragma unroll
        for (int j = 0; j < 8; ++j) {
            const __half* src = A + (size_t)arowidx[j] * K + roffH + k0;
            asm volatile("cp.async.cg.shared.global [%0], [%1], 16;\n"
                         :: "r"(saB + so + j * rowskip), "l"(src) : "memory");
        }
#pragma unroll
        for (int j = 0; j < 8; ++j)
            asm volatile("cp.async.cg.shared.global [%0], [%1], 16;\n"
                         :: "r"(sbB + so + j * rowskip),
                            "l"(bbase + (size_t)16 * j * K + k0) : "memory");
        asm volatile("cp.async.commit_group;\n" ::: "memory");
    };

    load_stage(0, 0);
    load_stage(1, 1);

    int buf = 0;
    for (int kc = 0; kc < nk; ++kc) {
        asm volatile("cp.async.wait_group 1;\n" ::: "memory");
        __syncthreads();
        if (kc + 2 < nk) {
            int nb = buf + 2; if (nb >= STAGES) nb -= STAGES;
            load_stage(nb, kc + 2);
        } else {
            asm volatile("cp.async.commit_group;\n" ::: "memory");
        }

        const uint32_t so = buf * stagestep;

#pragma unroll
        for (int kk = 0; kk < BKH; kk += 16) {
            uint32_t a[4][4], b[4][4];
#pragma unroll
            for (int mi = 0; mi < 4; ++mi)
                asm volatile(
                    "ldmatrix.sync.aligned.m8n8.x4.shared.b16 {%0,%1,%2,%3}, [%4];"
                    : "=r"(a[mi][0]), "=r"(a[mi][1]), "=r"(a[mi][2]), "=r"(a[mi][3])
                    : "r"(aAddr[mi] + so + kk * 2));
#pragma unroll
            for (int nj = 0; nj < 4; ++nj)
                asm volatile(
                    "ldmatrix.sync.aligned.m8n8.x4.shared.b16 {%0,%1,%2,%3}, [%4];"
                    : "=r"(b[nj][0]), "=r"(b[nj][1]), "=r"(b[nj][2]), "=r"(b[nj][3])
                    : "r"(bAddr[nj] + so + kk * 2));
#pragma unroll
            for (int mi = 0; mi < 4; ++mi)
#pragma unroll
                for (int ni = 0; ni < 8; ++ni) {
                    const uint32_t b0 = b[ni >> 1][(ni & 1) ? 2 : 0];
                    const uint32_t b1 = b[ni >> 1][(ni & 1) ? 3 : 1];
                    asm volatile(
                        "mma.sync.aligned.m16n8k16.row.col.f32.f16.f16.f32 "
                        "{%0,%1,%2,%3}, {%4,%5,%6,%7}, {%8,%9}, {%0,%1,%2,%3};"
                        : "+f"(cc[mi][ni][0]), "+f"(cc[mi][ni][1]),
                          "+f"(cc[mi][ni][2]), "+f"(cc[mi][ni][3])
                        : "r"(a[mi][0]), "r"(a[mi][1]), "r"(a[mi][2]), "r"(a[mi][3]),
                          "r"(b0), "r"(b1));
                }
        }
        if (++buf == STAGES) buf = 0;
    }

    if (mode == 0) {
        __half* C = (__half*)Cv + (size_t)z * cStrideZ;
#pragma unroll
        for (int mi = 0; mi < 4; ++mi) {
            int m0 = blockIdx.y * BM + wm + mi * 16 + g;
            int m1 = m0 + 8;
#pragma unroll
            for (int ni = 0; ni < 8; ++ni) {
                int n0 = blockIdx.x * BN + wn + ni * 8 + 2 * tg;
                if (m0 < M) {
                    __half2 v = __floats2half2_rn(cc[mi][ni][0], cc[mi][ni][1]);
                    *reinterpret_cast<__half2*>(C + (size_t)m0 * N + n0) = v;
                }
                if (m1 < M) {
                    __half2 v = __floats2half2_rn(cc[mi][ni][2], cc[mi][ni][3]);
                    *reinterpret_cast<__half2*>(C + (size_t)m1 * N + n0) = v;
                }
            }
        }
    } else {
        float* C = (float*)Cv + (size_t)z * cStrideZ;
#pragma unroll
        for (int mi = 0; mi < 4; ++mi) {
            int m0 = blockIdx.y * BM + wm + mi * 16 + g;
            int m1 = m0 + 8;
#pragma unroll
            for (int ni = 0; ni < 8; ++ni) {
                int n0 = blockIdx.x * BN + wn + ni * 8 + 2 * tg;
                if (m0 < M) {
                    float* p = C + (size_t)cidx[m0] * N + n0;
                    atomicAdd(&p[0], cc[mi][ni][0]);
                    atomicAdd(&p[1], cc[mi][ni][1]);
                }
                if (m1 < M) {
                    float* p = C + (size_t)cidx[m1] * N + n0;
                    atomicAdd(&p[0], cc[mi][ni][2]);
                    atomicAdd(&p[1], cc[mi][ni][3]);
                }
            }
        }
    }
}

// ---------------------------------------------------------------------------
// Sparse fused conv + bias + silu(x)*silu(z)*comb (fp16 in -> fp16 out).
// ---------------------------------------------------------------------------
__global__ void conv_act_sparse(const float* __restrict__ cw_all,
                                const float* __restrict__ cb_all)
{
    const int e = blockIdx.y;
    const int cnt = g_cnts2[2 * e];
    const int total = cnt * (DI / 4);
    const int* sel = g_lists + (2 * e) * NT;
    const int* posx = g_posx + e * NT;
    const __half* zb = g_zx + (size_t)(2 * e) * NT * DI;
    const __half* xb = g_zx + (size_t)(2 * e + 1) * NT * DI;
    __half* xact = g_xact + (size_t)e * NT * DI;
    const float4* cwf = reinterpret_cast<const float4*>(cw_all + (size_t)e * DI * 4);
    const float4* cbf = reinterpret_cast<const float4*>(cb_all + (size_t)e * DI);

    for (int idx = blockIdx.x * blockDim.x + threadIdx.x; idx < total;
         idx += gridDim.x * blockDim.x) {
        const int i  = idx >> 9;
        const int c4 = idx & 511;
        const int c  = c4 * 4;
        const int t  = sel[i];
        const float wgt = g_comb[(size_t)t * NE + e];
        const int b = t >> 11, s = t & (Ss - 1);

        float4 w0 = cwf[c4 * 4 + 0];
        float4 w1 = cwf[c4 * 4 + 1];
        float4 w2 = cwf[c4 * 4 + 2];
        float4 w3 = cwf[c4 * 4 + 3];
        float4 acc = cbf[c4];

#pragma unroll
        for (int j = 0; j < 4; ++j) {
            int sj = s - 3 + j;
            if (sj < 0) continue;
            int r = posx[b * Ss + sj];
            const uint2 xr = *reinterpret_cast<const uint2*>(xb + (size_t)r * DI + c);
            float2 xlo = __half22float2(*reinterpret_cast<const __half2*>(&xr.x));
            float2 xhi = __half22float2(*reinterpret_cast<const __half2*>(&xr.y));
            float t0 = (j == 0) ? w0.x : (j == 1) ? w0.y : (j == 2) ? w0.z : w0.w;
            float t1 = (j == 0) ? w1.x : (j == 1) ? w1.y : (j == 2) ? w1.z : w1.w;
            float t2 = (j == 0) ? w2.x : (j == 1) ? w2.y : (j == 2) ? w2.z : w2.w;
            float t3 = (j == 0) ? w3.x : (j == 1) ? w3.y : (j == 2) ? w3.z : w3.w;
            acc.x += t0 * xlo.x; acc.y += t1 * xlo.y;
            acc.z += t2 * xhi.x; acc.w += t3 * xhi.y;
        }

        const uint2 zr = *reinterpret_cast<const uint2*>(zb + (size_t)i * DI + c);
        float2 zlo = __half22float2(*reinterpret_cast<const __half2*>(&zr.x));
        float2 zhi = __half22float2(*reinterpret_cast<const __half2*>(&zr.y));
        __half2 lo = __floats2half2_rn(silu_(acc.x) * silu_(zlo.x) * wgt,
                                       silu_(acc.y) * silu_(zlo.y) * wgt);
        __half2 hi = __floats2half2_rn(silu_(acc.z) * silu_(zhi.x) * wgt,
                                       silu_(acc.w) * silu_(zhi.y) * wgt);
        uint2 o;
        o.x = *reinterpret_cast<uint32_t*>(&lo);
        o.y = *reinterpret_cast<uint32_t*>(&hi);
        *reinterpret_cast<uint2*>(xact + (size_t)i * DI + c) = o;
    }
}

// ---------------------------------------------------------------------------
extern "C" void kernel_launch(void* const* d_in, const int* in_sizes, int n_in,
                              void* d_out, int out_size)
{
    const float* h   = (const float*)d_in[0];
    const float* inw = (const float*)d_in[1];
    const float* cw  = (const float*)d_in[2];
    const float* cb  = (const float*)d_in[3];
    const float* ow  = (const float*)d_in[4];
    const float* rw1 = (const float*)d_in[5];
    const float* rw2 = (const float*)d_in[6];
    float* out = (float*)d_out;

    void *zxp, *xap, *hhp, *iwp, *owp, *rhp, *cntp, *lstp;
    cudaGetSymbolAddress(&zxp, g_zx);
    cudaGetSymbolAddress(&xap, g_xact);
    cudaGetSymbolAddress(&hhp, g_hh);
    cudaGetSymbolAddress(&iwp, g_inwh);
    cudaGetSymbolAddress(&owp, g_owh);
    cudaGetSymbolAddress(&rhp, g_rhp);
    cudaGetSymbolAddress(&cntp, g_cnts2);
    cudaGetSymbolAddress(&lstp, g_lists);
    __half* zx    = (__half*)zxp;
    __half* xact  = (__half*)xap;
    __half* hh    = (__half*)hhp;
    __half* inwh  = (__half*)iwp;
    __half* owh   = (__half*)owp;
    float*  rhpf  = (float*)rhp;
    int*    cnts  = (int*)cntp;
    int*    lists = (int*)lstp;

    // One-time host-side handles (no device memory involved).
    static cudaStream_t sHi = nullptr, sLo = nullptr;
    static cudaEvent_t evFork = nullptr, evRouter = nullptr, evOw = nullptr;
    if (!sHi) {
        int prLow, prHigh;
        cudaDeviceGetStreamPriorityRange(&prLow, &prHigh);
        cudaStreamCreateWithPriority(&sHi, cudaStreamNonBlocking, prHigh);
        cudaStreamCreateWithPriority(&sLo, cudaStreamNonBlocking, prLow);
        cudaEventCreateWithFlags(&evFork, cudaEventDisableTiming);
        cudaEventCreateWithFlags(&evRouter, cudaEventDisableTiming);
        cudaEventCreateWithFlags(&evOw, cudaEventDisableTiming);
        cudaFuncSetAttribute(gemm_fp16, cudaFuncAttributeMaxDynamicSharedMemorySize,
                             SMEM_BYTES);
    }

    // Fork.
    cudaEventRecord(evFork, 0);
    cudaStreamWaitEvent(sHi, evFork, 0);
    cudaStreamWaitEvent(sLo, evFork, 0);

    // sHi (high priority): router chain -- FMA-bound, co-runs with converts.
    cudaMemsetAsync(cnts, 0, 16 * sizeof(int), sHi);
    router_l1<<<dim3(NT / 64, RSPLIT), 256, 0, sHi>>>(h, rw1, rhpf);
    router_finish<<<(NT * 32) / 256, 256, 0, sHi>>>(rhpf, rw2);
    build_xlists<<<dim3(NT / 256, NE), 256, 0, sHi>>>();
    cudaEventRecord(evRouter, sHi);

    // default: convert h + in_proj weights (needed first).
    convert_h_inw<<<1184, 256>>>((const float4*)h,   (uint2*)hh,   NT * Dd / 4,
                                 (const float4*)inw, (uint2*)inwh, NE * 2 * DI * Dd / 4);

    // sLo (low priority): out_proj weight convert + out zero -- hides under
    // the in_proj GEMM; only needed before out_proj.
    convert_ow<<<1184, 256, 0, sLo>>>((const float4*)ow, (uint2*)owh, NE * Dd * DI / 4,
                                      (float4*)out, NT * Dd / 4);
    cudaEventRecord(evOw, sLo);

    // Join router before in_proj.
    cudaStreamWaitEvent(0, evRouter, 0);

    // in_proj, all 16 jobs (job 2e = z rows, 2e+1 = x rows)
    gemm_fp16<<<dim3(DI / BN, NT / BM, 16), 128, SMEM_BYTES>>>(
        hh, inwh, zx, cnts, 0, 1, DI, Dd,
        (size_t)0, (size_t)DI * Dd, (size_t)NT * DI,
        lists, (size_t)NT, nullptr, (size_t)0, 0);

    // conv + gate
    conv_act_sparse<<<dim3(1024, NE), 256>>>(cw, cb);

    // Join ow-convert before out_proj.
    cudaStreamWaitEvent(0, evOw, 0);

    // out_proj per expert: atomic fp32 scatter-accumulate into out
    gemm_fp16<<<dim3(Dd / BN, NT / BM, NE), 128, SMEM_BYTES>>>(
        xact, owh, out, cnts, 0, 2, Dd, DI,
        (size_t)NT * DI, (size_t)Dd * DI, (size_t)0,
        nullptr, (size_t)0, lists, (size_t)2 * NT, 1);
}